// round 2
// baseline (speedup 1.0000x reference)
#include <cuda_runtime.h>
#include <cuda_bf16.h>
#include <math.h>

// ---------------------------------------------------------------------------
// Problem constants
// ---------------------------------------------------------------------------
#define BB    2
#define TT    64
#define PP    256
#define DD    512
#define HH    8
#define DH    64
#define INNER 512          // HH*DH
#define QKV3  1536         // 3*INNER
#define NTOK  32768        // BB*TT*PP
#define DEPTH 4
#define LN_EPS 1e-5f

// ---------------------------------------------------------------------------
// Static device scratch (no runtime allocation allowed)
// g_ctx doubles as the LN-output buffer: LN out is consumed by the QKV GEMM
// before attention writes ctx, so the lifetimes never overlap.
// ---------------------------------------------------------------------------
__device__ float g_qkv[(size_t)NTOK * QKV3];
__device__ float g_ctx[(size_t)NTOK * INNER];
__device__ float g_xs [(size_t)NTOK * DD];
__device__ float g_xt [(size_t)NTOK * DD];
__device__ float g_cos[256 * 32];
__device__ float g_sin[256 * 32];

// ---------------------------------------------------------------------------
// RoPE table: pos in [0,256), pair j in [0,32). theta = pos * 10000^(-2j/64)
// ---------------------------------------------------------------------------
__global__ void rope_table_kernel() {
    int i = blockIdx.x * blockDim.x + threadIdx.x;
    if (i >= 256 * 32) return;
    int pos = i >> 5;
    int j   = i & 31;
    float freq  = powf(10000.0f, -(float)(2 * j) / 64.0f);
    float theta = (float)pos * freq;
    float s, c;
    sincosf(theta, &s, &c);
    g_cos[i] = c;
    g_sin[i] = s;
}

// ---------------------------------------------------------------------------
// Warp-per-row LayerNorm over D=512.
// ---------------------------------------------------------------------------
__device__ __forceinline__ void warp_ln_core(
    const float4 v[4], int lane,
    const float* __restrict__ g, const float* __restrict__ b,
    float4 o[4])
{
    float s = 0.f, s2 = 0.f;
#pragma unroll
    for (int i = 0; i < 4; i++) {
        s  += v[i].x + v[i].y + v[i].z + v[i].w;
        s2 += v[i].x * v[i].x + v[i].y * v[i].y + v[i].z * v[i].z + v[i].w * v[i].w;
    }
#pragma unroll
    for (int o_ = 16; o_ > 0; o_ >>= 1) {
        s  += __shfl_xor_sync(0xffffffffu, s,  o_);
        s2 += __shfl_xor_sync(0xffffffffu, s2, o_);
    }
    float mu   = s * (1.0f / 512.0f);
    float var  = s2 * (1.0f / 512.0f) - mu * mu;
    float rstd = rsqrtf(var + LN_EPS);
#pragma unroll
    for (int i = 0; i < 4; i++) {
        int c = (lane + 32 * i) * 4;
        float4 gg = *(const float4*)(g + c);
        float4 bb = *(const float4*)(b + c);
        o[i].x = (v[i].x - mu) * rstd * gg.x + bb.x;
        o[i].y = (v[i].y - mu) * rstd * gg.y + bb.y;
        o[i].z = (v[i].z - mu) * rstd * gg.z + bb.z;
        o[i].w = (v[i].w - mu) * rstd * gg.w + bb.w;
    }
}

// out[row] = LN(x[row])  — row order preserved
__global__ void ln_kernel(const float* __restrict__ x,
                          const float* __restrict__ g, const float* __restrict__ b,
                          float* __restrict__ out)
{
    int row  = blockIdx.x * 8 + (threadIdx.x >> 5);
    int lane = threadIdx.x & 31;
    const float* xr = x + (size_t)row * DD;
    float4 v[4];
#pragma unroll
    for (int i = 0; i < 4; i++) v[i] = *(const float4*)(xr + (lane + 32 * i) * 4);
    float4 o[4];
    warp_ln_core(v, lane, g, b, o);
    float* orow = out + (size_t)row * DD;
#pragma unroll
    for (int i = 0; i < 4; i++) *(float4*)(orow + (lane + 32 * i) * 4) = o[i];
}

// Temporal pre-LN: out row r in (b,p,t) order = LN(x[src] + xs[src]) where
// src is the (b,t,p) row.
__global__ void ln_add_transpose_kernel(const float* __restrict__ x,
                                        const float* __restrict__ xs,
                                        const float* __restrict__ g, const float* __restrict__ b,
                                        float* __restrict__ out)
{
    int row  = blockIdx.x * 8 + (threadIdx.x >> 5);
    int lane = threadIdx.x & 31;
    int t_ = row & 63;
    int p_ = (row >> 6) & 255;
    int b_ = row >> 14;
    int src = (b_ * TT + t_) * PP + p_;
    const float* xr  = x  + (size_t)src * DD;
    const float* xsr = xs + (size_t)src * DD;
    float4 v[4];
#pragma unroll
    for (int i = 0; i < 4; i++) {
        float4 a = *(const float4*)(xr  + (lane + 32 * i) * 4);
        float4 c = *(const float4*)(xsr + (lane + 32 * i) * 4);
        v[i].x = a.x + c.x; v[i].y = a.y + c.y; v[i].z = a.z + c.z; v[i].w = a.w + c.w;
    }
    float4 o[4];
    warp_ln_core(v, lane, g, b, o);
    float* orow = out + (size_t)row * DD;
#pragma unroll
    for (int i = 0; i < 4; i++) *(float4*)(orow + (lane + 32 * i) * 4) = o[i];
}

// Layer finish: x[r] = LN(xs[r] + xt[perm(r)]) + x[r], r in (b,t,p) order,
// xt stored in (b,p,t) order.
__global__ void ln_final_kernel(const float* __restrict__ xs,
                                const float* __restrict__ xt,
                                const float* __restrict__ g, const float* __restrict__ b,
                                float* __restrict__ x)
{
    int row  = blockIdx.x * 8 + (threadIdx.x >> 5);
    int lane = threadIdx.x & 31;
    int p_ = row & 255;
    int t_ = (row >> 8) & 63;
    int b_ = row >> 14;
    int xtr = (b_ * PP + p_) * TT + t_;
    const float* xsr = xs + (size_t)row * DD;
    const float* xtr_p = xt + (size_t)xtr * DD;
    float* xr = x + (size_t)row * DD;
    float4 v[4], xv[4];
#pragma unroll
    for (int i = 0; i < 4; i++) {
        float4 a = *(const float4*)(xsr + (lane + 32 * i) * 4);
        float4 c = *(const float4*)(xtr_p + (lane + 32 * i) * 4);
        v[i].x = a.x + c.x; v[i].y = a.y + c.y; v[i].z = a.z + c.z; v[i].w = a.w + c.w;
        xv[i] = *(const float4*)(xr + (lane + 32 * i) * 4);
    }
    float4 o[4];
    warp_ln_core(v, lane, g, b, o);
#pragma unroll
    for (int i = 0; i < 4; i++) {
        o[i].x += xv[i].x; o[i].y += xv[i].y; o[i].z += xv[i].z; o[i].w += xv[i].w;
        *(float4*)(xr + (lane + 32 * i) * 4) = o[i];
    }
}

// ---------------------------------------------------------------------------
// fp32 SGEMM: C[M,N] = A[M,K] @ W[K,N] (+ bias). 128x128 tile, BK=16,
// 256 threads, 8x8 per-thread microtile. M,N,K all multiples of tile dims here.
// ---------------------------------------------------------------------------
#define GBM 128
#define GBN 128
#define GBK 16

__global__ void __launch_bounds__(256) sgemm_kernel(
    const float* __restrict__ A, const float* __restrict__ W,
    const float* __restrict__ bias, float* __restrict__ C,
    int M, int N, int K)
{
    __shared__ float As[GBK][GBM];
    __shared__ float Bs[GBK][GBN];
    int tid = threadIdx.x;
    int tx = tid & 15, ty = tid >> 4;
    int bm = blockIdx.x, bn = blockIdx.y;

    const float* Aptr = A + (size_t)bm * GBM * K;
    const float* Wptr = W + (size_t)bn * GBN;

    float acc[8][8];
#pragma unroll
    for (int i = 0; i < 8; i++)
#pragma unroll
        for (int j = 0; j < 8; j++) acc[i][j] = 0.f;

    for (int k0 = 0; k0 < K; k0 += GBK) {
        // A tile: 128 rows x 16 cols -> As transposed [k][m]
#pragma unroll
        for (int s = 0; s < 2; s++) {
            int slot = tid + s * 256;           // 0..511 float4 slots
            int row  = slot >> 2;               // 0..127
            int c4   = (slot & 3) * 4;          // 0,4,8,12
            float4 v = *(const float4*)(Aptr + (size_t)row * K + k0 + c4);
            As[c4 + 0][row] = v.x;
            As[c4 + 1][row] = v.y;
            As[c4 + 2][row] = v.z;
            As[c4 + 3][row] = v.w;
        }
        // B tile: 16 rows x 128 cols
#pragma unroll
        for (int s = 0; s < 2; s++) {
            int slot = tid + s * 256;
            int row  = slot >> 5;               // 0..15
            int c4   = (slot & 31) * 4;
            *(float4*)&Bs[row][c4] = *(const float4*)(Wptr + (size_t)(k0 + row) * N + c4);
        }
        __syncthreads();
#pragma unroll
        for (int kk = 0; kk < GBK; kk++) {
            float4 a0 = *(const float4*)&As[kk][ty * 8];
            float4 a1 = *(const float4*)&As[kk][ty * 8 + 4];
            float4 b0 = *(const float4*)&Bs[kk][tx * 8];
            float4 b1 = *(const float4*)&Bs[kk][tx * 8 + 4];
            float a[8] = {a0.x, a0.y, a0.z, a0.w, a1.x, a1.y, a1.z, a1.w};
            float b[8] = {b0.x, b0.y, b0.z, b0.w, b1.x, b1.y, b1.z, b1.w};
#pragma unroll
            for (int i = 0; i < 8; i++)
#pragma unroll
                for (int j = 0; j < 8; j++) acc[i][j] += a[i] * b[j];
        }
        __syncthreads();
    }

    float bv[8];
    if (bias) {
        float4 b0 = *(const float4*)(bias + bn * GBN + tx * 8);
        float4 b1 = *(const float4*)(bias + bn * GBN + tx * 8 + 4);
        bv[0]=b0.x; bv[1]=b0.y; bv[2]=b0.z; bv[3]=b0.w;
        bv[4]=b1.x; bv[5]=b1.y; bv[6]=b1.z; bv[7]=b1.w;
    } else {
#pragma unroll
        for (int j = 0; j < 8; j++) bv[j] = 0.f;
    }
#pragma unroll
    for (int i = 0; i < 8; i++) {
        float* Crow = C + (size_t)(bm * GBM + ty * 8 + i) * N + bn * GBN + tx * 8;
        float4 o0 = {acc[i][0] + bv[0], acc[i][1] + bv[1], acc[i][2] + bv[2], acc[i][3] + bv[3]};
        float4 o1 = {acc[i][4] + bv[4], acc[i][5] + bv[5], acc[i][6] + bv[6], acc[i][7] + bv[7]};
        *(float4*)(Crow)     = o0;
        *(float4*)(Crow + 4) = o1;
    }
}

// ---------------------------------------------------------------------------
// Flash attention, fp32. Block = (q-tile 64, head, sequence). 64-row KV tiles.
// RoPE + 1/sqrt(dh) fused into q/k loads. Per-warp: 8 q-rows; lane owns
// columns (lane, lane+32). Online softmax; P staged via smem for P@V.
// smem: q[64*64] kT[64*65] v[64*64] p[64*64] = 65792 B (dynamic).
// ---------------------------------------------------------------------------
#define ATTN_SMEM_BYTES ((4096 + 64*65 + 4096 + 4096) * 4)

__global__ void __launch_bounds__(256) attn_kernel(
    const float* __restrict__ qkv, float* __restrict__ ctx, int L)
{
    extern __shared__ float sm[];
    float* q_s  = sm;                       // 64*64
    float* kT_s = sm + 4096;                // 64*65 (dh-major, padded)
    float* v_s  = sm + 4096 + 64 * 65;      // 64*64
    float* p_s  = sm + 4096 + 64 * 65 + 4096; // 64*64

    int tid  = threadIdx.x;
    int lane = tid & 31;
    int w    = tid >> 5;
    int qt = blockIdx.x, h = blockIdx.y;
    size_t seq_base = (size_t)blockIdx.z * L;
    int qbase = qt * 64;

    // load q tile with rotary + scale
#pragma unroll
    for (int it = 0; it < 8; it++) {
        int slot = it * 256 + tid;          // 2048 float2 slots
        int row = slot >> 5, pr = slot & 31;
        int pos = qbase + row;
        const float* p = qkv + (seq_base + pos) * QKV3 + h * DH + 2 * pr;
        float2 qv = *(const float2*)p;
        float c = g_cos[pos * 32 + pr], sn = g_sin[pos * 32 + pr];
        q_s[row * 64 + 2 * pr]     = (qv.x * c - qv.y * sn) * 0.125f;
        q_s[row * 64 + 2 * pr + 1] = (qv.y * c + qv.x * sn) * 0.125f;
    }

    float m[8], lsum[8], o0[8], o1[8];
#pragma unroll
    for (int r = 0; r < 8; r++) { m[r] = -1e30f; lsum[r] = 0.f; o0[r] = 0.f; o1[r] = 0.f; }

    int nt = L >> 6;
    for (int kt = 0; kt < nt; kt++) {
        if (kt > 0) __syncthreads();
        // K tile (rotary, transposed store) + V tile
#pragma unroll
        for (int it = 0; it < 8; it++) {
            int slot = it * 256 + tid;
            int row = slot >> 5, pr = slot & 31;
            int pos = kt * 64 + row;
            const float* p = qkv + (seq_base + pos) * QKV3 + INNER + h * DH + 2 * pr;
            float2 kv = *(const float2*)p;
            float c = g_cos[pos * 32 + pr], sn = g_sin[pos * 32 + pr];
            kT_s[(2 * pr) * 65 + row]     = kv.x * c - kv.y * sn;
            kT_s[(2 * pr + 1) * 65 + row] = kv.y * c + kv.x * sn;
        }
#pragma unroll
        for (int it = 0; it < 4; it++) {
            int slot = it * 256 + tid;      // 1024 float4 slots
            int row = slot >> 4, c4 = (slot & 15) * 4;
            const float* p = qkv + (seq_base + kt * 64 + row) * QKV3 + 2 * INNER + h * DH + c4;
            *(float4*)&v_s[row * 64 + c4] = *(const float4*)p;
        }
        __syncthreads();

        // S = q @ kT   (per-lane: 8 rows x 2 cols)
        float acc0[8], acc1[8];
#pragma unroll
        for (int r = 0; r < 8; r++) { acc0[r] = 0.f; acc1[r] = 0.f; }
#pragma unroll
        for (int k4 = 0; k4 < 16; k4++) {
            int kk = k4 * 4;
            float b00 = kT_s[(kk + 0) * 65 + lane];
            float b01 = kT_s[(kk + 1) * 65 + lane];
            float b02 = kT_s[(kk + 2) * 65 + lane];
            float b03 = kT_s[(kk + 3) * 65 + lane];
            float b10 = kT_s[(kk + 0) * 65 + lane + 32];
            float b11 = kT_s[(kk + 1) * 65 + lane + 32];
            float b12 = kT_s[(kk + 2) * 65 + lane + 32];
            float b13 = kT_s[(kk + 3) * 65 + lane + 32];
#pragma unroll
            for (int r = 0; r < 8; r++) {
                float4 a = *(const float4*)&q_s[(w * 8 + r) * 64 + kk];
                acc0[r] += a.x * b00 + a.y * b01 + a.z * b02 + a.w * b03;
                acc1[r] += a.x * b10 + a.y * b11 + a.z * b12 + a.w * b13;
            }
        }

        // online softmax update + stage P
#pragma unroll
        for (int r = 0; r < 8; r++) {
            float mx = fmaxf(acc0[r], acc1[r]);
#pragma unroll
            for (int o = 16; o > 0; o >>= 1)
                mx = fmaxf(mx, __shfl_xor_sync(0xffffffffu, mx, o));
            float newm  = fmaxf(m[r], mx);
            float alpha = __expf(m[r] - newm);
            float p0 = __expf(acc0[r] - newm);
            float p1 = __expf(acc1[r] - newm);
            float ps = p0 + p1;
#pragma unroll
            for (int o = 16; o > 0; o >>= 1)
                ps += __shfl_xor_sync(0xffffffffu, ps, o);
            lsum[r] = lsum[r] * alpha + ps;
            o0[r] *= alpha;
            o1[r] *= alpha;
            m[r] = newm;
            p_s[(w * 8 + r) * 64 + lane]      = p0;
            p_s[(w * 8 + r) * 64 + lane + 32] = p1;
        }
        __syncwarp();

        // O += P @ V
#pragma unroll
        for (int j4 = 0; j4 < 16; j4++) {
            int j = j4 * 4;
            float v00 = v_s[(j + 0) * 64 + lane];
            float v01 = v_s[(j + 1) * 64 + lane];
            float v02 = v_s[(j + 2) * 64 + lane];
            float v03 = v_s[(j + 3) * 64 + lane];
            float v10 = v_s[(j + 0) * 64 + lane + 32];
            float v11 = v_s[(j + 1) * 64 + lane + 32];
            float v12 = v_s[(j + 2) * 64 + lane + 32];
            float v13 = v_s[(j + 3) * 64 + lane + 32];
#pragma unroll
            for (int r = 0; r < 8; r++) {
                float4 p = *(const float4*)&p_s[(w * 8 + r) * 64 + j];
                o0[r] += p.x * v00 + p.y * v01 + p.z * v02 + p.w * v03;
                o1[r] += p.x * v10 + p.y * v11 + p.z * v12 + p.w * v13;
            }
        }
    }

    // epilogue
#pragma unroll
    for (int r = 0; r < 8; r++) {
        float inv = 1.0f / lsum[r];
        size_t tok = seq_base + qbase + w * 8 + r;
        ctx[tok * INNER + h * DH + lane]      = o0[r] * inv;
        ctx[tok * INNER + h * DH + lane + 32] = o1[r] * inv;
    }
}

// ---------------------------------------------------------------------------
// Host launch
// ---------------------------------------------------------------------------
extern "C" void kernel_launch(void* const* d_in, const int* in_sizes, int n_in,
                              void* d_out, int out_size)
{
    const float* x_in    = (const float*)d_in[0];
    const float* ln_s_g  = (const float*)d_in[1];
    const float* ln_s_b  = (const float*)d_in[2];
    const float* w_qkv_s = (const float*)d_in[3];
    const float* w_out_s = (const float*)d_in[4];
    const float* b_out_s = (const float*)d_in[5];
    const float* ln_t_g  = (const float*)d_in[6];
    const float* ln_t_b  = (const float*)d_in[7];
    const float* w_qkv_t = (const float*)d_in[8];
    const float* w_out_t = (const float*)d_in[9];
    const float* b_out_t = (const float*)d_in[10];
    const float* ln_f_g  = (const float*)d_in[11];
    const float* ln_f_b  = (const float*)d_in[12];
    float* x = (float*)d_out;

    cudaFuncSetAttribute(attn_kernel, cudaFuncAttributeMaxDynamicSharedMemorySize,
                         ATTN_SMEM_BYTES);

    // scratch pointers (device symbols)
    float *qkv_p, *ctx_p, *xs_p, *xt_p;
    cudaGetSymbolAddress((void**)&qkv_p, g_qkv);
    cudaGetSymbolAddress((void**)&ctx_p, g_ctx);
    cudaGetSymbolAddress((void**)&xs_p,  g_xs);
    cudaGetSymbolAddress((void**)&xt_p,  g_xt);
    float* ln_p = ctx_p;   // LN output aliases ctx (lifetimes disjoint)

    // x <- input
    cudaMemcpyAsync(x, x_in, (size_t)NTOK * DD * sizeof(float),
                    cudaMemcpyDeviceToDevice);
    rope_table_kernel<<<(256 * 32 + 255) / 256, 256>>>();

    dim3 ln_grid(NTOK / 8);
    dim3 gemm_qkv_grid(NTOK / GBM, QKV3 / GBN);
    dim3 gemm_out_grid(NTOK / GBM, DD / GBN);
    dim3 attn_s_grid(PP / 64, HH, BB * TT);   // spatial: 128 seqs of len 256
    dim3 attn_t_grid(TT / 64, HH, BB * PP);   // temporal: 512 seqs of len 64

    for (int i = 0; i < DEPTH; i++) {
        const float* wq_s = w_qkv_s + (size_t)i * DD * QKV3;
        const float* wo_s = w_out_s + (size_t)i * INNER * DD;
        const float* wq_t = w_qkv_t + (size_t)i * DD * QKV3;
        const float* wo_t = w_out_t + (size_t)i * INNER * DD;

        // ---- spatial branch (sequences = contiguous runs of P tokens) ----
        ln_kernel<<<ln_grid, 256>>>(x, ln_s_g + i * DD, ln_s_b + i * DD, ln_p);
        sgemm_kernel<<<gemm_qkv_grid, 256>>>(ln_p, wq_s, nullptr, qkv_p,
                                             NTOK, QKV3, DD);
        attn_kernel<<<attn_s_grid, 256, ATTN_SMEM_BYTES>>>(qkv_p, ctx_p, PP);
        sgemm_kernel<<<gemm_out_grid, 256>>>(ctx_p, wo_s, b_out_s + i * DD, xs_p,
                                             NTOK, DD, DD);

        // ---- temporal branch ((b,p,t) order) ----
        ln_add_transpose_kernel<<<ln_grid, 256>>>(x, xs_p, ln_t_g + i * DD,
                                                  ln_t_b + i * DD, ln_p);
        sgemm_kernel<<<gemm_qkv_grid, 256>>>(ln_p, wq_t, nullptr, qkv_p,
                                             NTOK, QKV3, DD);
        attn_kernel<<<attn_t_grid, 256, ATTN_SMEM_BYTES>>>(qkv_p, ctx_p, TT);
        sgemm_kernel<<<gemm_out_grid, 256>>>(ctx_p, wo_t, b_out_t + i * DD, xt_p,
                                             NTOK, DD, DD);

        // ---- finish: x = LN(x_s + x_t) + x ----
        ln_final_kernel<<<ln_grid, 256>>>(xs_p, xt_p, ln_f_g + i * DD,
                                          ln_f_b + i * DD, x);
    }
}

// round 3
// speedup vs baseline: 2.2147x; 2.2147x over previous
#include <cuda_runtime.h>
#include <cuda_bf16.h>
#include <math.h>
#include <stdint.h>

// ---------------------------------------------------------------------------
// Problem constants
// ---------------------------------------------------------------------------
#define BB    2
#define TT    64
#define PP    256
#define DD    512
#define HH    8
#define DH    64
#define INNER 512          // HH*DH
#define QKV3  1536         // 3*INNER
#define NTOK  32768        // BB*TT*PP
#define DEPTH 4
#define LN_EPS 1e-5f

// ---------------------------------------------------------------------------
// Static device scratch (no runtime allocation allowed)
// g_ctx doubles as the LN-output buffer (lifetimes disjoint).
// ---------------------------------------------------------------------------
__device__ float g_qkv[(size_t)NTOK * QKV3];
__device__ float g_ctx[(size_t)NTOK * INNER];
__device__ float g_xs [(size_t)NTOK * DD];
__device__ float g_xt [(size_t)NTOK * DD];
__device__ float g_cos[256 * 32];
__device__ float g_sin[256 * 32];

// ---------------------------------------------------------------------------
// RoPE table
// ---------------------------------------------------------------------------
__global__ void rope_table_kernel() {
    int i = blockIdx.x * blockDim.x + threadIdx.x;
    if (i >= 256 * 32) return;
    int pos = i >> 5;
    int j   = i & 31;
    float freq  = powf(10000.0f, -(float)(2 * j) / 64.0f);
    float theta = (float)pos * freq;
    float s, c;
    sincosf(theta, &s, &c);
    g_cos[i] = c;
    g_sin[i] = s;
}

// ---------------------------------------------------------------------------
// Warp-per-row LayerNorm over D=512
// ---------------------------------------------------------------------------
__device__ __forceinline__ void warp_ln_core(
    const float4 v[4], int lane,
    const float* __restrict__ g, const float* __restrict__ b,
    float4 o[4])
{
    float s = 0.f, s2 = 0.f;
#pragma unroll
    for (int i = 0; i < 4; i++) {
        s  += v[i].x + v[i].y + v[i].z + v[i].w;
        s2 += v[i].x * v[i].x + v[i].y * v[i].y + v[i].z * v[i].z + v[i].w * v[i].w;
    }
#pragma unroll
    for (int o_ = 16; o_ > 0; o_ >>= 1) {
        s  += __shfl_xor_sync(0xffffffffu, s,  o_);
        s2 += __shfl_xor_sync(0xffffffffu, s2, o_);
    }
    float mu   = s * (1.0f / 512.0f);
    float var  = s2 * (1.0f / 512.0f) - mu * mu;
    float rstd = rsqrtf(var + LN_EPS);
#pragma unroll
    for (int i = 0; i < 4; i++) {
        int c = (lane + 32 * i) * 4;
        float4 gg = *(const float4*)(g + c);
        float4 bb = *(const float4*)(b + c);
        o[i].x = (v[i].x - mu) * rstd * gg.x + bb.x;
        o[i].y = (v[i].y - mu) * rstd * gg.y + bb.y;
        o[i].z = (v[i].z - mu) * rstd * gg.z + bb.z;
        o[i].w = (v[i].w - mu) * rstd * gg.w + bb.w;
    }
}

__global__ void ln_kernel(const float* __restrict__ x,
                          const float* __restrict__ g, const float* __restrict__ b,
                          float* __restrict__ out)
{
    int row  = blockIdx.x * 8 + (threadIdx.x >> 5);
    int lane = threadIdx.x & 31;
    const float* xr = x + (size_t)row * DD;
    float4 v[4];
#pragma unroll
    for (int i = 0; i < 4; i++) v[i] = *(const float4*)(xr + (lane + 32 * i) * 4);
    float4 o[4];
    warp_ln_core(v, lane, g, b, o);
    float* orow = out + (size_t)row * DD;
#pragma unroll
    for (int i = 0; i < 4; i++) *(float4*)(orow + (lane + 32 * i) * 4) = o[i];
}

__global__ void ln_add_transpose_kernel(const float* __restrict__ x,
                                        const float* __restrict__ xs,
                                        const float* __restrict__ g, const float* __restrict__ b,
                                        float* __restrict__ out)
{
    int row  = blockIdx.x * 8 + (threadIdx.x >> 5);
    int lane = threadIdx.x & 31;
    int t_ = row & 63;
    int p_ = (row >> 6) & 255;
    int b_ = row >> 14;
    int src = (b_ * TT + t_) * PP + p_;
    const float* xr  = x  + (size_t)src * DD;
    const float* xsr = xs + (size_t)src * DD;
    float4 v[4];
#pragma unroll
    for (int i = 0; i < 4; i++) {
        float4 a = *(const float4*)(xr  + (lane + 32 * i) * 4);
        float4 c = *(const float4*)(xsr + (lane + 32 * i) * 4);
        v[i].x = a.x + c.x; v[i].y = a.y + c.y; v[i].z = a.z + c.z; v[i].w = a.w + c.w;
    }
    float4 o[4];
    warp_ln_core(v, lane, g, b, o);
    float* orow = out + (size_t)row * DD;
#pragma unroll
    for (int i = 0; i < 4; i++) *(float4*)(orow + (lane + 32 * i) * 4) = o[i];
}

__global__ void ln_final_kernel(const float* __restrict__ xs,
                                const float* __restrict__ xt,
                                const float* __restrict__ g, const float* __restrict__ b,
                                float* __restrict__ x)
{
    int row  = blockIdx.x * 8 + (threadIdx.x >> 5);
    int lane = threadIdx.x & 31;
    int p_ = row & 255;
    int t_ = (row >> 8) & 63;
    int b_ = row >> 14;
    int xtr = (b_ * PP + p_) * TT + t_;
    const float* xsr = xs + (size_t)row * DD;
    const float* xtr_p = xt + (size_t)xtr * DD;
    float* xr = x + (size_t)row * DD;
    float4 v[4], xv[4];
#pragma unroll
    for (int i = 0; i < 4; i++) {
        float4 a = *(const float4*)(xsr + (lane + 32 * i) * 4);
        float4 c = *(const float4*)(xtr_p + (lane + 32 * i) * 4);
        v[i].x = a.x + c.x; v[i].y = a.y + c.y; v[i].z = a.z + c.z; v[i].w = a.w + c.w;
        xv[i] = *(const float4*)(xr + (lane + 32 * i) * 4);
    }
    float4 o[4];
    warp_ln_core(v, lane, g, b, o);
#pragma unroll
    for (int i = 0; i < 4; i++) {
        o[i].x += xv[i].x; o[i].y += xv[i].y; o[i].z += xv[i].z; o[i].w += xv[i].w;
        *(float4*)(xr + (lane + 32 * i) * 4) = o[i];
    }
}

// ---------------------------------------------------------------------------
// tf32 tensor-core GEMM: C[M,N] = A[M,K] @ W[K,N] (+bias), fp32 accumulate.
// CTA tile 128x128x32, 8 warps (2m x 4n -> 64x32 warp tiles),
// mma.sync.m16n8k8.tf32, cp.async double-buffered smem.
// Smem pads (36 / 136 floats) make all fragment LDS conflict-free.
// ---------------------------------------------------------------------------
#define TBM 128
#define TBN 128
#define TBK 32
#define A_STR 36           // floats per A smem row  (128B-aligned rows: 144B)
#define B_STR 136          // floats per B smem row  (544B, 16B aligned)
#define A_BUF (TBM * A_STR)    // 4608 floats
#define B_BUF (TBK * B_STR)    // 4352 floats
#define TGEMM_SMEM_BYTES ((2 * A_BUF + 2 * B_BUF) * 4)   // 71680 B

__device__ __forceinline__ uint32_t f2tf32(float f) {
    uint32_t u;
    asm volatile("cvt.rna.tf32.f32 %0, %1;" : "=r"(u) : "f"(f));
    return u;
}

__device__ __forceinline__ void mma_tf32(float c[4],
                                         uint32_t a0, uint32_t a1, uint32_t a2, uint32_t a3,
                                         uint32_t b0, uint32_t b1)
{
    asm volatile(
        "mma.sync.aligned.m16n8k8.row.col.f32.tf32.tf32.f32 "
        "{%0,%1,%2,%3}, {%4,%5,%6,%7}, {%8,%9}, {%0,%1,%2,%3};"
        : "+f"(c[0]), "+f"(c[1]), "+f"(c[2]), "+f"(c[3])
        : "r"(a0), "r"(a1), "r"(a2), "r"(a3), "r"(b0), "r"(b1));
}

__device__ __forceinline__ void cp_async16(uint32_t dst, const void* src) {
    asm volatile("cp.async.cg.shared.global [%0], [%1], 16;\n" :: "r"(dst), "l"(src));
}

__global__ void __launch_bounds__(256) tgemm_kernel(
    const float* __restrict__ A, const float* __restrict__ W,
    const float* __restrict__ bias, float* __restrict__ C,
    int M, int N, int K)
{
    extern __shared__ float sm[];
    float* As = sm;                 // 2 buffers of A_BUF
    float* Bs = sm + 2 * A_BUF;     // 2 buffers of B_BUF

    int tid  = threadIdx.x;
    int lane = tid & 31;
    int wid  = tid >> 5;
    int wm   = wid >> 2;            // 0..1  -> m offset wm*64
    int wn   = wid & 3;             // 0..3  -> n offset wn*32
    int grp  = lane >> 2;           // 0..7
    int tig  = lane & 3;            // 0..3
    int bm = blockIdx.x, bn = blockIdx.y;

    const float* Ag = A + (size_t)bm * TBM * K;
    const float* Wg = W + (size_t)bn * TBN;

    uint32_t as_base = (uint32_t)__cvta_generic_to_shared(As);
    uint32_t bs_base = (uint32_t)__cvta_generic_to_shared(Bs);

    float acc[4][4][4];
#pragma unroll
    for (int i = 0; i < 4; i++)
#pragma unroll
        for (int j = 0; j < 4; j++)
#pragma unroll
            for (int c = 0; c < 4; c++) acc[i][j][c] = 0.f;

    const int NK = K / TBK;

    // ---- async tile loader: A 128x32, B 32x128 (4 float4 each per thread) ----
    auto load_tiles = [&](int kt, int buf) {
#pragma unroll
        for (int it = 0; it < 4; it++) {
            int slot = tid + it * 256;                 // 1024 float4 slots
            int row  = slot >> 3;                      // 0..127
            int c4   = (slot & 7) * 4;                 // 0..28
            uint32_t dst = as_base + (buf * A_BUF + row * A_STR + c4) * 4;
            cp_async16(dst, Ag + (size_t)row * K + kt * TBK + c4);
        }
#pragma unroll
        for (int it = 0; it < 4; it++) {
            int slot = tid + it * 256;
            int row  = slot >> 5;                      // 0..31
            int c4   = (slot & 31) * 4;                // 0..124
            uint32_t dst = bs_base + (buf * B_BUF + row * B_STR + c4) * 4;
            cp_async16(dst, Wg + (size_t)(kt * TBK + row) * N + c4);
        }
        asm volatile("cp.async.commit_group;\n");
    };

    load_tiles(0, 0);

    for (int kt = 0; kt < NK; kt++) {
        int buf = kt & 1;
        if (kt + 1 < NK) {
            load_tiles(kt + 1, buf ^ 1);
            asm volatile("cp.async.wait_group 1;\n");
        } else {
            asm volatile("cp.async.wait_group 0;\n");
        }
        __syncthreads();

        const float* as = As + buf * A_BUF;
        const float* bs = Bs + buf * B_BUF;

#pragma unroll
        for (int ks = 0; ks < 4; ks++) {
            int k = ks * 8;
            uint32_t af[4][4];
#pragma unroll
            for (int mt = 0; mt < 4; mt++) {
                int m = wm * 64 + mt * 16;
                af[mt][0] = f2tf32(as[(m + grp    ) * A_STR + k + tig    ]);
                af[mt][1] = f2tf32(as[(m + grp + 8) * A_STR + k + tig    ]);
                af[mt][2] = f2tf32(as[(m + grp    ) * A_STR + k + tig + 4]);
                af[mt][3] = f2tf32(as[(m + grp + 8) * A_STR + k + tig + 4]);
            }
            uint32_t bf[4][2];
#pragma unroll
            for (int nt = 0; nt < 4; nt++) {
                int n = wn * 32 + nt * 8;
                bf[nt][0] = f2tf32(bs[(k + tig    ) * B_STR + n + grp]);
                bf[nt][1] = f2tf32(bs[(k + tig + 4) * B_STR + n + grp]);
            }
#pragma unroll
            for (int mt = 0; mt < 4; mt++)
#pragma unroll
                for (int nt = 0; nt < 4; nt++)
                    mma_tf32(acc[mt][nt], af[mt][0], af[mt][1], af[mt][2], af[mt][3],
                             bf[nt][0], bf[nt][1]);
        }
        __syncthreads();
    }

    // ---- epilogue: + bias, fp32 stores (float2 per c-pair) ----
#pragma unroll
    for (int nt = 0; nt < 4; nt++) {
        int colg = bn * TBN + wn * 32 + nt * 8 + 2 * tig;
        float2 bv = {0.f, 0.f};
        if (bias) bv = *(const float2*)(bias + colg);
#pragma unroll
        for (int mt = 0; mt < 4; mt++) {
            int row0 = bm * TBM + wm * 64 + mt * 16 + grp;
            float2 lo = {acc[mt][nt][0] + bv.x, acc[mt][nt][1] + bv.y};
            float2 hi = {acc[mt][nt][2] + bv.x, acc[mt][nt][3] + bv.y};
            *(float2*)(C + (size_t)row0 * N + colg)       = lo;
            *(float2*)(C + (size_t)(row0 + 8) * N + colg) = hi;
        }
    }
}

// ---------------------------------------------------------------------------
// Flash attention, fp32 (unchanged from passing round)
// ---------------------------------------------------------------------------
#define ATTN_SMEM_BYTES ((4096 + 64*65 + 4096 + 4096) * 4)

__global__ void __launch_bounds__(256) attn_kernel(
    const float* __restrict__ qkv, float* __restrict__ ctx, int L)
{
    extern __shared__ float sm[];
    float* q_s  = sm;
    float* kT_s = sm + 4096;
    float* v_s  = sm + 4096 + 64 * 65;
    float* p_s  = sm + 4096 + 64 * 65 + 4096;

    int tid  = threadIdx.x;
    int lane = tid & 31;
    int w    = tid >> 5;
    int qt = blockIdx.x, h = blockIdx.y;
    size_t seq_base = (size_t)blockIdx.z * L;
    int qbase = qt * 64;

#pragma unroll
    for (int it = 0; it < 8; it++) {
        int slot = it * 256 + tid;
        int row = slot >> 5, pr = slot & 31;
        int pos = qbase + row;
        const float* p = qkv + (seq_base + pos) * QKV3 + h * DH + 2 * pr;
        float2 qv = *(const float2*)p;
        float c = g_cos[pos * 32 + pr], sn = g_sin[pos * 32 + pr];
        q_s[row * 64 + 2 * pr]     = (qv.x * c - qv.y * sn) * 0.125f;
        q_s[row * 64 + 2 * pr + 1] = (qv.y * c + qv.x * sn) * 0.125f;
    }

    float m[8], lsum[8], o0[8], o1[8];
#pragma unroll
    for (int r = 0; r < 8; r++) { m[r] = -1e30f; lsum[r] = 0.f; o0[r] = 0.f; o1[r] = 0.f; }

    int nt = L >> 6;
    for (int kt = 0; kt < nt; kt++) {
        if (kt > 0) __syncthreads();
#pragma unroll
        for (int it = 0; it < 8; it++) {
            int slot = it * 256 + tid;
            int row = slot >> 5, pr = slot & 31;
            int pos = kt * 64 + row;
            const float* p = qkv + (seq_base + pos) * QKV3 + INNER + h * DH + 2 * pr;
            float2 kv = *(const float2*)p;
            float c = g_cos[pos * 32 + pr], sn = g_sin[pos * 32 + pr];
            kT_s[(2 * pr) * 65 + row]     = kv.x * c - kv.y * sn;
            kT_s[(2 * pr + 1) * 65 + row] = kv.y * c + kv.x * sn;
        }
#pragma unroll
        for (int it = 0; it < 4; it++) {
            int slot = it * 256 + tid;
            int row = slot >> 4, c4 = (slot & 15) * 4;
            const float* p = qkv + (seq_base + kt * 64 + row) * QKV3 + 2 * INNER + h * DH + c4;
            *(float4*)&v_s[row * 64 + c4] = *(const float4*)p;
        }
        __syncthreads();

        float acc0[8], acc1[8];
#pragma unroll
        for (int r = 0; r < 8; r++) { acc0[r] = 0.f; acc1[r] = 0.f; }
#pragma unroll
        for (int k4 = 0; k4 < 16; k4++) {
            int kk = k4 * 4;
            float b00 = kT_s[(kk + 0) * 65 + lane];
            float b01 = kT_s[(kk + 1) * 65 + lane];
            float b02 = kT_s[(kk + 2) * 65 + lane];
            float b03 = kT_s[(kk + 3) * 65 + lane];
            float b10 = kT_s[(kk + 0) * 65 + lane + 32];
            float b11 = kT_s[(kk + 1) * 65 + lane + 32];
            float b12 = kT_s[(kk + 2) * 65 + lane + 32];
            float b13 = kT_s[(kk + 3) * 65 + lane + 32];
#pragma unroll
            for (int r = 0; r < 8; r++) {
                float4 a = *(const float4*)&q_s[(w * 8 + r) * 64 + kk];
                acc0[r] += a.x * b00 + a.y * b01 + a.z * b02 + a.w * b03;
                acc1[r] += a.x * b10 + a.y * b11 + a.z * b12 + a.w * b13;
            }
        }

#pragma unroll
        for (int r = 0; r < 8; r++) {
            float mx = fmaxf(acc0[r], acc1[r]);
#pragma unroll
            for (int o = 16; o > 0; o >>= 1)
                mx = fmaxf(mx, __shfl_xor_sync(0xffffffffu, mx, o));
            float newm  = fmaxf(m[r], mx);
            float alpha = __expf(m[r] - newm);
            float p0 = __expf(acc0[r] - newm);
            float p1 = __expf(acc1[r] - newm);
            float ps = p0 + p1;
#pragma unroll
            for (int o = 16; o > 0; o >>= 1)
                ps += __shfl_xor_sync(0xffffffffu, ps, o);
            lsum[r] = lsum[r] * alpha + ps;
            o0[r] *= alpha;
            o1[r] *= alpha;
            m[r] = newm;
            p_s[(w * 8 + r) * 64 + lane]      = p0;
            p_s[(w * 8 + r) * 64 + lane + 32] = p1;
        }
        __syncwarp();

#pragma unroll
        for (int j4 = 0; j4 < 16; j4++) {
            int j = j4 * 4;
            float v00 = v_s[(j + 0) * 64 + lane];
            float v01 = v_s[(j + 1) * 64 + lane];
            float v02 = v_s[(j + 2) * 64 + lane];
            float v03 = v_s[(j + 3) * 64 + lane];
            float v10 = v_s[(j + 0) * 64 + lane + 32];
            float v11 = v_s[(j + 1) * 64 + lane + 32];
            float v12 = v_s[(j + 2) * 64 + lane + 32];
            float v13 = v_s[(j + 3) * 64 + lane + 32];
#pragma unroll
            for (int r = 0; r < 8; r++) {
                float4 p = *(const float4*)&p_s[(w * 8 + r) * 64 + j];
                o0[r] += p.x * v00 + p.y * v01 + p.z * v02 + p.w * v03;
                o1[r] += p.x * v10 + p.y * v11 + p.z * v12 + p.w * v13;
            }
        }
    }

#pragma unroll
    for (int r = 0; r < 8; r++) {
        float inv = 1.0f / lsum[r];
        size_t tok = seq_base + qbase + w * 8 + r;
        ctx[tok * INNER + h * DH + lane]      = o0[r] * inv;
        ctx[tok * INNER + h * DH + lane + 32] = o1[r] * inv;
    }
}

// ---------------------------------------------------------------------------
// Host launch
// ---------------------------------------------------------------------------
extern "C" void kernel_launch(void* const* d_in, const int* in_sizes, int n_in,
                              void* d_out, int out_size)
{
    const float* x_in    = (const float*)d_in[0];
    const float* ln_s_g  = (const float*)d_in[1];
    const float* ln_s_b  = (const float*)d_in[2];
    const float* w_qkv_s = (const float*)d_in[3];
    const float* w_out_s = (const float*)d_in[4];
    const float* b_out_s = (const float*)d_in[5];
    const float* ln_t_g  = (const float*)d_in[6];
    const float* ln_t_b  = (const float*)d_in[7];
    const float* w_qkv_t = (const float*)d_in[8];
    const float* w_out_t = (const float*)d_in[9];
    const float* b_out_t = (const float*)d_in[10];
    const float* ln_f_g  = (const float*)d_in[11];
    const float* ln_f_b  = (const float*)d_in[12];
    float* x = (float*)d_out;

    cudaFuncSetAttribute(attn_kernel, cudaFuncAttributeMaxDynamicSharedMemorySize,
                         ATTN_SMEM_BYTES);
    cudaFuncSetAttribute(tgemm_kernel, cudaFuncAttributeMaxDynamicSharedMemorySize,
                         TGEMM_SMEM_BYTES);

    float *qkv_p, *ctx_p, *xs_p, *xt_p;
    cudaGetSymbolAddress((void**)&qkv_p, g_qkv);
    cudaGetSymbolAddress((void**)&ctx_p, g_ctx);
    cudaGetSymbolAddress((void**)&xs_p,  g_xs);
    cudaGetSymbolAddress((void**)&xt_p,  g_xt);
    float* ln_p = ctx_p;   // LN output aliases ctx (lifetimes disjoint)

    cudaMemcpyAsync(x, x_in, (size_t)NTOK * DD * sizeof(float),
                    cudaMemcpyDeviceToDevice);
    rope_table_kernel<<<(256 * 32 + 255) / 256, 256>>>();

    dim3 ln_grid(NTOK / 8);
    dim3 gemm_qkv_grid(NTOK / TBM, QKV3 / TBN);
    dim3 gemm_out_grid(NTOK / TBM, DD / TBN);
    dim3 attn_s_grid(PP / 64, HH, BB * TT);
    dim3 attn_t_grid(TT / 64, HH, BB * PP);

    for (int i = 0; i < DEPTH; i++) {
        const float* wq_s = w_qkv_s + (size_t)i * DD * QKV3;
        const float* wo_s = w_out_s + (size_t)i * INNER * DD;
        const float* wq_t = w_qkv_t + (size_t)i * DD * QKV3;
        const float* wo_t = w_out_t + (size_t)i * INNER * DD;

        // ---- spatial branch ----
        ln_kernel<<<ln_grid, 256>>>(x, ln_s_g + i * DD, ln_s_b + i * DD, ln_p);
        tgemm_kernel<<<gemm_qkv_grid, 256, TGEMM_SMEM_BYTES>>>(
            ln_p, wq_s, nullptr, qkv_p, NTOK, QKV3, DD);
        attn_kernel<<<attn_s_grid, 256, ATTN_SMEM_BYTES>>>(qkv_p, ctx_p, PP);
        tgemm_kernel<<<gemm_out_grid, 256, TGEMM_SMEM_BYTES>>>(
            ctx_p, wo_s, b_out_s + i * DD, xs_p, NTOK, DD, DD);

        // ---- temporal branch ----
        ln_add_transpose_kernel<<<ln_grid, 256>>>(x, xs_p, ln_t_g + i * DD,
                                                  ln_t_b + i * DD, ln_p);
        tgemm_kernel<<<gemm_qkv_grid, 256, TGEMM_SMEM_BYTES>>>(
            ln_p, wq_t, nullptr, qkv_p, NTOK, QKV3, DD);
        attn_kernel<<<attn_t_grid, 256, ATTN_SMEM_BYTES>>>(qkv_p, ctx_p, TT);
        tgemm_kernel<<<gemm_out_grid, 256, TGEMM_SMEM_BYTES>>>(
            ctx_p, wo_t, b_out_t + i * DD, xt_p, NTOK, DD, DD);

        // ---- finish ----
        ln_final_kernel<<<ln_grid, 256>>>(xs_p, xt_p, ln_f_g + i * DD,
                                          ln_f_b + i * DD, x);
    }
}

// round 5
// speedup vs baseline: 2.9468x; 1.3306x over previous
#include <cuda_runtime.h>
#include <cuda_bf16.h>
#include <math.h>
#include <stdint.h>

// ---------------------------------------------------------------------------
// Problem constants
// ---------------------------------------------------------------------------
#define BB    2
#define TT    64
#define PP    256
#define DD    512
#define HH    8
#define DH    64
#define INNER 512          // HH*DH
#define QKV3  1536         // 3*INNER
#define NTOK  32768        // BB*TT*PP
#define DEPTH 4
#define LN_EPS 1e-5f

// ---------------------------------------------------------------------------
// Static device scratch
// ---------------------------------------------------------------------------
__device__ float g_qkv[(size_t)NTOK * QKV3];
__device__ float g_ctx[(size_t)NTOK * INNER];
__device__ float g_xs [(size_t)NTOK * DD];
__device__ float g_xt [(size_t)NTOK * DD];
__device__ float g_cos[256 * 32];
__device__ float g_sin[256 * 32];

// ---------------------------------------------------------------------------
// RoPE table
// ---------------------------------------------------------------------------
__global__ void rope_table_kernel() {
    int i = blockIdx.x * blockDim.x + threadIdx.x;
    if (i >= 256 * 32) return;
    int pos = i >> 5;
    int j   = i & 31;
    float freq  = powf(10000.0f, -(float)(2 * j) / 64.0f);
    float theta = (float)pos * freq;
    float s, c;
    sincosf(theta, &s, &c);
    g_cos[i] = c;
    g_sin[i] = s;
}

// ---------------------------------------------------------------------------
// Fast exp on the FMA pipe (no MUFU). |rel err| ~1e-7 for x in [-80, 0].
// ---------------------------------------------------------------------------
__device__ __forceinline__ float fexp(float x) {
    x = fmaxf(x, -80.0f);
    float y = x * 1.44269504088896340736f;     // x * log2(e)
    float t = y + 12582912.0f;                 // capture round-to-nearest int
    int   n = __float_as_int(t) - 0x4B400000;
    float f = y - (t - 12582912.0f);           // f in [-0.5, 0.5]
    float p =             1.54035303933e-4f;
    p = fmaf(p, f, 1.33335581464e-3f);
    p = fmaf(p, f, 9.61812910763e-3f);
    p = fmaf(p, f, 5.55041086648e-2f);
    p = fmaf(p, f, 2.40226506959e-1f);
    p = fmaf(p, f, 6.93147180560e-1f);
    p = fmaf(p, f, 1.0f);
    return p * __int_as_float((n + 127) << 23);
}

// tf32 round-to-nearest (result bits valid as raw mma operand)
__device__ __forceinline__ float tf32r(float f) {
    uint32_t u;
    asm volatile("cvt.rna.tf32.f32 %0, %1;" : "=r"(u) : "f"(f));
    return __uint_as_float(u);
}

__device__ __forceinline__ void mma_tf32(float c[4],
                                         uint32_t a0, uint32_t a1, uint32_t a2, uint32_t a3,
                                         uint32_t b0, uint32_t b1)
{
    asm volatile(
        "mma.sync.aligned.m16n8k8.row.col.f32.tf32.tf32.f32 "
        "{%0,%1,%2,%3}, {%4,%5,%6,%7}, {%8,%9}, {%0,%1,%2,%3};"
        : "+f"(c[0]), "+f"(c[1]), "+f"(c[2]), "+f"(c[3])
        : "r"(a0), "r"(a1), "r"(a2), "r"(a3), "r"(b0), "r"(b1));
}

// ---------------------------------------------------------------------------
// Warp-per-row LayerNorm over D=512
// ---------------------------------------------------------------------------
__device__ __forceinline__ void warp_ln_core(
    const float4 v[4], int lane,
    const float* __restrict__ g, const float* __restrict__ b,
    float4 o[4])
{
    float s = 0.f, s2 = 0.f;
#pragma unroll
    for (int i = 0; i < 4; i++) {
        s  += v[i].x + v[i].y + v[i].z + v[i].w;
        s2 += v[i].x * v[i].x + v[i].y * v[i].y + v[i].z * v[i].z + v[i].w * v[i].w;
    }
#pragma unroll
    for (int o_ = 16; o_ > 0; o_ >>= 1) {
        s  += __shfl_xor_sync(0xffffffffu, s,  o_);
        s2 += __shfl_xor_sync(0xffffffffu, s2, o_);
    }
    float mu   = s * (1.0f / 512.0f);
    float var  = s2 * (1.0f / 512.0f) - mu * mu;
    float rstd = rsqrtf(var + LN_EPS);
#pragma unroll
    for (int i = 0; i < 4; i++) {
        int c = (lane + 32 * i) * 4;
        float4 gg = *(const float4*)(g + c);
        float4 bb = *(const float4*)(b + c);
        o[i].x = (v[i].x - mu) * rstd * gg.x + bb.x;
        o[i].y = (v[i].y - mu) * rstd * gg.y + bb.y;
        o[i].z = (v[i].z - mu) * rstd * gg.z + bb.z;
        o[i].w = (v[i].w - mu) * rstd * gg.w + bb.w;
    }
}

__global__ void ln_kernel(const float* __restrict__ x,
                          const float* __restrict__ g, const float* __restrict__ b,
                          float* __restrict__ out)
{
    int row  = blockIdx.x * 8 + (threadIdx.x >> 5);
    int lane = threadIdx.x & 31;
    const float* xr = x + (size_t)row * DD;
    float4 v[4];
#pragma unroll
    for (int i = 0; i < 4; i++) v[i] = *(const float4*)(xr + (lane + 32 * i) * 4);
    float4 o[4];
    warp_ln_core(v, lane, g, b, o);
    float* orow = out + (size_t)row * DD;
#pragma unroll
    for (int i = 0; i < 4; i++) *(float4*)(orow + (lane + 32 * i) * 4) = o[i];
}

__global__ void ln_add_transpose_kernel(const float* __restrict__ x,
                                        const float* __restrict__ xs,
                                        const float* __restrict__ g, const float* __restrict__ b,
                                        float* __restrict__ out)
{
    int row  = blockIdx.x * 8 + (threadIdx.x >> 5);
    int lane = threadIdx.x & 31;
    int t_ = row & 63;
    int p_ = (row >> 6) & 255;
    int b_ = row >> 14;
    int src = (b_ * TT + t_) * PP + p_;
    const float* xr  = x  + (size_t)src * DD;
    const float* xsr = xs + (size_t)src * DD;
    float4 v[4];
#pragma unroll
    for (int i = 0; i < 4; i++) {
        float4 a = *(const float4*)(xr  + (lane + 32 * i) * 4);
        float4 c = *(const float4*)(xsr + (lane + 32 * i) * 4);
        v[i].x = a.x + c.x; v[i].y = a.y + c.y; v[i].z = a.z + c.z; v[i].w = a.w + c.w;
    }
    float4 o[4];
    warp_ln_core(v, lane, g, b, o);
    float* orow = out + (size_t)row * DD;
#pragma unroll
    for (int i = 0; i < 4; i++) *(float4*)(orow + (lane + 32 * i) * 4) = o[i];
}

__global__ void ln_final_kernel(const float* __restrict__ xs,
                                const float* __restrict__ xt,
                                const float* __restrict__ g, const float* __restrict__ b,
                                float* __restrict__ x)
{
    int row  = blockIdx.x * 8 + (threadIdx.x >> 5);
    int lane = threadIdx.x & 31;
    int p_ = row & 255;
    int t_ = (row >> 8) & 63;
    int b_ = row >> 14;
    int xtr = (b_ * PP + p_) * TT + t_;
    const float* xsr = xs + (size_t)row * DD;
    const float* xtr_p = xt + (size_t)xtr * DD;
    float* xr = x + (size_t)row * DD;
    float4 v[4], xv[4];
#pragma unroll
    for (int i = 0; i < 4; i++) {
        float4 a = *(const float4*)(xsr + (lane + 32 * i) * 4);
        float4 c = *(const float4*)(xtr_p + (lane + 32 * i) * 4);
        v[i].x = a.x + c.x; v[i].y = a.y + c.y; v[i].z = a.z + c.z; v[i].w = a.w + c.w;
        xv[i] = *(const float4*)(xr + (lane + 32 * i) * 4);
    }
    float4 o[4];
    warp_ln_core(v, lane, g, b, o);
#pragma unroll
    for (int i = 0; i < 4; i++) {
        o[i].x += xv[i].x; o[i].y += xv[i].y; o[i].z += xv[i].z; o[i].w += xv[i].w;
        *(float4*)(xr + (lane + 32 * i) * 4) = o[i];
    }
}

// ---------------------------------------------------------------------------
// tf32 tensor-core GEMM (unchanged from passing round)
// ---------------------------------------------------------------------------
#define TBM 128
#define TBN 128
#define TBK 32
#define A_STR 36
#define B_STR 136
#define A_BUF (TBM * A_STR)
#define B_BUF (TBK * B_STR)
#define TGEMM_SMEM_BYTES ((2 * A_BUF + 2 * B_BUF) * 4)

__device__ __forceinline__ uint32_t f2tf32(float f) {
    uint32_t u;
    asm volatile("cvt.rna.tf32.f32 %0, %1;" : "=r"(u) : "f"(f));
    return u;
}

__device__ __forceinline__ void cp_async16(uint32_t dst, const void* src) {
    asm volatile("cp.async.cg.shared.global [%0], [%1], 16;\n" :: "r"(dst), "l"(src));
}

__global__ void __launch_bounds__(256) tgemm_kernel(
    const float* __restrict__ A, const float* __restrict__ W,
    const float* __restrict__ bias, float* __restrict__ C,
    int M, int N, int K)
{
    extern __shared__ float sm[];
    float* As = sm;
    float* Bs = sm + 2 * A_BUF;

    int tid  = threadIdx.x;
    int lane = tid & 31;
    int wid  = tid >> 5;
    int wm   = wid >> 2;
    int wn   = wid & 3;
    int grp  = lane >> 2;
    int tig  = lane & 3;
    int bm = blockIdx.x, bn = blockIdx.y;

    const float* Ag = A + (size_t)bm * TBM * K;
    const float* Wg = W + (size_t)bn * TBN;

    uint32_t as_base = (uint32_t)__cvta_generic_to_shared(As);
    uint32_t bs_base = (uint32_t)__cvta_generic_to_shared(Bs);

    float acc[4][4][4];
#pragma unroll
    for (int i = 0; i < 4; i++)
#pragma unroll
        for (int j = 0; j < 4; j++)
#pragma unroll
            for (int c = 0; c < 4; c++) acc[i][j][c] = 0.f;

    const int NK = K / TBK;

    auto load_tiles = [&](int kt, int buf) {
#pragma unroll
        for (int it = 0; it < 4; it++) {
            int slot = tid + it * 256;
            int row  = slot >> 3;
            int c4   = (slot & 7) * 4;
            uint32_t dst = as_base + (buf * A_BUF + row * A_STR + c4) * 4;
            cp_async16(dst, Ag + (size_t)row * K + kt * TBK + c4);
        }
#pragma unroll
        for (int it = 0; it < 4; it++) {
            int slot = tid + it * 256;
            int row  = slot >> 5;
            int c4   = (slot & 31) * 4;
            uint32_t dst = bs_base + (buf * B_BUF + row * B_STR + c4) * 4;
            cp_async16(dst, Wg + (size_t)(kt * TBK + row) * N + c4);
        }
        asm volatile("cp.async.commit_group;\n");
    };

    load_tiles(0, 0);

    for (int kt = 0; kt < NK; kt++) {
        int buf = kt & 1;
        if (kt + 1 < NK) {
            load_tiles(kt + 1, buf ^ 1);
            asm volatile("cp.async.wait_group 1;\n");
        } else {
            asm volatile("cp.async.wait_group 0;\n");
        }
        __syncthreads();

        const float* as = As + buf * A_BUF;
        const float* bs = Bs + buf * B_BUF;

#pragma unroll
        for (int ks = 0; ks < 4; ks++) {
            int k = ks * 8;
            uint32_t af[4][4];
#pragma unroll
            for (int mt = 0; mt < 4; mt++) {
                int m = wm * 64 + mt * 16;
                af[mt][0] = f2tf32(as[(m + grp    ) * A_STR + k + tig    ]);
                af[mt][1] = f2tf32(as[(m + grp + 8) * A_STR + k + tig    ]);
                af[mt][2] = f2tf32(as[(m + grp    ) * A_STR + k + tig + 4]);
                af[mt][3] = f2tf32(as[(m + grp + 8) * A_STR + k + tig + 4]);
            }
            uint32_t bf[4][2];
#pragma unroll
            for (int nt = 0; nt < 4; nt++) {
                int n = wn * 32 + nt * 8;
                bf[nt][0] = f2tf32(bs[(k + tig    ) * B_STR + n + grp]);
                bf[nt][1] = f2tf32(bs[(k + tig + 4) * B_STR + n + grp]);
            }
#pragma unroll
            for (int mt = 0; mt < 4; mt++)
#pragma unroll
                for (int nt = 0; nt < 4; nt++)
                    mma_tf32(acc[mt][nt], af[mt][0], af[mt][1], af[mt][2], af[mt][3],
                             bf[nt][0], bf[nt][1]);
        }
        __syncthreads();
    }

#pragma unroll
    for (int nt = 0; nt < 4; nt++) {
        int colg = bn * TBN + wn * 32 + nt * 8 + 2 * tig;
        float2 bv = {0.f, 0.f};
        if (bias) bv = *(const float2*)(bias + colg);
#pragma unroll
        for (int mt = 0; mt < 4; mt++) {
            int row0 = bm * TBM + wm * 64 + mt * 16 + grp;
            float2 lo = {acc[mt][nt][0] + bv.x, acc[mt][nt][1] + bv.y};
            float2 hi = {acc[mt][nt][2] + bv.x, acc[mt][nt][3] + bv.y};
            *(float2*)(C + (size_t)row0 * N + colg)       = lo;
            *(float2*)(C + (size_t)(row0 + 8) * N + colg) = hi;
        }
    }
}

// ---------------------------------------------------------------------------
// Tensor-core flash attention (tf32 mma + FMA-pipe exp).
// Block = 128 threads (4 warps), one (seq, head, 64-row q-tile).
// Warp w owns q-rows [w*16, w*16+16). KV tiles of 64.
// smem tiles stride 76 floats: qs[64] (reused as ps), ks[pos][d], vs[pos][d].
// All smem operands pre-rounded to tf32 -> raw-bit mma (no cvt in hot loop).
// ---------------------------------------------------------------------------
#define AST 76
#define ATTN_TC_SMEM (3 * 64 * AST * 4)   // 58368 B

__global__ void __launch_bounds__(128, 3) attn_tc_kernel(
    const float* __restrict__ qkv, float* __restrict__ ctx, int L)
{
    extern __shared__ float sm[];
    float* qs = sm;                   // 64 x AST ; reused as ps after preload
    float* ks = sm + 64 * AST;
    float* vs = sm + 2 * 64 * AST;
    float* ps = qs;

    int tid  = threadIdx.x;
    int lane = tid & 31;
    int w    = tid >> 5;
    int grp  = lane >> 2;             // 0..7
    int tig  = lane & 3;              // 0..3
    int qt = blockIdx.x, h = blockIdx.y;
    size_t seq_base = (size_t)blockIdx.z * L;
    int qbase = qt * 64;
    int m0 = w * 16;

    // ---- stage Q (rotary + scale + tf32 round) ----
#pragma unroll
    for (int it = 0; it < 16; it++) {
        int slot = it * 128 + tid;            // 2048 rotary pairs
        int row = slot >> 5, pr = slot & 31;
        int pos = qbase + row;
        const float* p = qkv + (seq_base + pos) * QKV3 + h * DH + 2 * pr;
        float2 qv = *(const float2*)p;
        float c = g_cos[pos * 32 + pr], sn = g_sin[pos * 32 + pr];
        float e0 = (qv.x * c - qv.y * sn) * 0.125f;
        float e1 = (qv.y * c + qv.x * sn) * 0.125f;
        *(float2*)&qs[row * AST + 2 * pr] = make_float2(tf32r(e0), tf32r(e1));
    }

    // ---- KV staging helper ----
    auto stage_kv = [&](int kt) {
#pragma unroll
        for (int it = 0; it < 16; it++) {
            int slot = it * 128 + tid;
            int row = slot >> 5, pr = slot & 31;
            int pos = kt * 64 + row;
            const float* p = qkv + (seq_base + pos) * QKV3 + INNER + h * DH + 2 * pr;
            float2 kv = *(const float2*)p;
            float c = g_cos[pos * 32 + pr], sn = g_sin[pos * 32 + pr];
            float e0 = kv.x * c - kv.y * sn;
            float e1 = kv.y * c + kv.x * sn;
            *(float2*)&ks[row * AST + 2 * pr] = make_float2(tf32r(e0), tf32r(e1));
        }
#pragma unroll
        for (int it = 0; it < 8; it++) {
            int slot = it * 128 + tid;            // 1024 float4 slots
            int row = slot >> 4, c4 = (slot & 15) * 4;
            const float* p = qkv + (seq_base + kt * 64 + row) * QKV3 + 2 * INNER + h * DH + c4;
            float4 vv = *(const float4*)p;
            vv.x = tf32r(vv.x); vv.y = tf32r(vv.y);
            vv.z = tf32r(vv.z); vv.w = tf32r(vv.w);
            *(float4*)&vs[row * AST + c4] = vv;
        }
    };

    stage_kv(0);
    __syncthreads();

    // ---- preload Q fragments (own warp's 16 rows) ----
    uint32_t qa[8][4];
#pragma unroll
    for (int kk = 0; kk < 8; kk++) {
        int k = kk * 8;
        qa[kk][0] = __float_as_uint(qs[(m0 + grp    ) * AST + k + tig    ]);
        qa[kk][1] = __float_as_uint(qs[(m0 + grp + 8) * AST + k + tig    ]);
        qa[kk][2] = __float_as_uint(qs[(m0 + grp    ) * AST + k + tig + 4]);
        qa[kk][3] = __float_as_uint(qs[(m0 + grp + 8) * AST + k + tig + 4]);
    }

    float mrow[2] = {-1e30f, -1e30f};
    float lrow[2] = {0.f, 0.f};
    float oc[8][4];
#pragma unroll
    for (int nt = 0; nt < 8; nt++)
#pragma unroll
        for (int c = 0; c < 4; c++) oc[nt][c] = 0.f;

    int ntl = L >> 6;
    for (int kt = 0; kt < ntl; kt++) {
        if (kt > 0) {
            __syncthreads();          // all warps done with previous ks/vs
            stage_kv(kt);
            __syncthreads();
        }

        // ---- S = Q @ K^T ----
        float sacc[8][4];
#pragma unroll
        for (int nt = 0; nt < 8; nt++)
#pragma unroll
            for (int c = 0; c < 4; c++) sacc[nt][c] = 0.f;
#pragma unroll
        for (int kk = 0; kk < 8; kk++) {
            int k = kk * 8;
#pragma unroll
            for (int nt = 0; nt < 8; nt++) {
                uint32_t b0 = __float_as_uint(ks[(nt * 8 + grp) * AST + k + tig    ]);
                uint32_t b1 = __float_as_uint(ks[(nt * 8 + grp) * AST + k + tig + 4]);
                mma_tf32(sacc[nt], qa[kk][0], qa[kk][1], qa[kk][2], qa[kk][3], b0, b1);
            }
        }

        // ---- online softmax (rows m0+grp and m0+grp+8) ----
        float mx0 = -1e30f, mx1 = -1e30f;
#pragma unroll
        for (int nt = 0; nt < 8; nt++) {
            mx0 = fmaxf(mx0, fmaxf(sacc[nt][0], sacc[nt][1]));
            mx1 = fmaxf(mx1, fmaxf(sacc[nt][2], sacc[nt][3]));
        }
        mx0 = fmaxf(mx0, __shfl_xor_sync(0xffffffffu, mx0, 1));
        mx0 = fmaxf(mx0, __shfl_xor_sync(0xffffffffu, mx0, 2));
        mx1 = fmaxf(mx1, __shfl_xor_sync(0xffffffffu, mx1, 1));
        mx1 = fmaxf(mx1, __shfl_xor_sync(0xffffffffu, mx1, 2));
        float nm0 = fmaxf(mrow[0], mx0), nm1 = fmaxf(mrow[1], mx1);
        float al0 = fexp(mrow[0] - nm0),  al1 = fexp(mrow[1] - nm1);
        float s0 = 0.f, s1 = 0.f;
#pragma unroll
        for (int nt = 0; nt < 8; nt++) {
            float p0 = fexp(sacc[nt][0] - nm0);
            float p1 = fexp(sacc[nt][1] - nm0);
            float p2 = fexp(sacc[nt][2] - nm1);
            float p3 = fexp(sacc[nt][3] - nm1);
            s0 += p0 + p1;
            s1 += p2 + p3;
            *(float2*)&ps[(m0 + grp    ) * AST + nt * 8 + 2 * tig] =
                make_float2(tf32r(p0), tf32r(p1));
            *(float2*)&ps[(m0 + grp + 8) * AST + nt * 8 + 2 * tig] =
                make_float2(tf32r(p2), tf32r(p3));
        }
        s0 += __shfl_xor_sync(0xffffffffu, s0, 1);
        s0 += __shfl_xor_sync(0xffffffffu, s0, 2);
        s1 += __shfl_xor_sync(0xffffffffu, s1, 1);
        s1 += __shfl_xor_sync(0xffffffffu, s1, 2);
        lrow[0] = lrow[0] * al0 + s0;
        lrow[1] = lrow[1] * al1 + s1;
        mrow[0] = nm0; mrow[1] = nm1;
#pragma unroll
        for (int nt = 0; nt < 8; nt++) {
            oc[nt][0] *= al0; oc[nt][1] *= al0;
            oc[nt][2] *= al1; oc[nt][3] *= al1;
        }
        __syncwarp();

        // ---- O += P @ V ----
#pragma unroll
        for (int kk = 0; kk < 8; kk++) {
            int k = kk * 8;
            uint32_t pa0 = __float_as_uint(ps[(m0 + grp    ) * AST + k + tig    ]);
            uint32_t pa1 = __float_as_uint(ps[(m0 + grp + 8) * AST + k + tig    ]);
            uint32_t pa2 = __float_as_uint(ps[(m0 + grp    ) * AST + k + tig + 4]);
            uint32_t pa3 = __float_as_uint(ps[(m0 + grp + 8) * AST + k + tig + 4]);
#pragma unroll
            for (int nt = 0; nt < 8; nt++) {
                uint32_t vb0 = __float_as_uint(vs[(k + tig    ) * AST + nt * 8 + grp]);
                uint32_t vb1 = __float_as_uint(vs[(k + tig + 4) * AST + nt * 8 + grp]);
                mma_tf32(oc[nt], pa0, pa1, pa2, pa3, vb0, vb1);
            }
        }
        __syncwarp();   // ps reads done before next tile's softmax overwrites
    }

    // ---- epilogue ----
    float i0 = 1.0f / lrow[0], i1 = 1.0f / lrow[1];
    size_t tok0 = seq_base + qbase + m0 + grp;
#pragma unroll
    for (int nt = 0; nt < 8; nt++) {
        int col = h * DH + nt * 8 + 2 * tig;
        *(float2*)&ctx[tok0 * INNER + col] =
            make_float2(oc[nt][0] * i0, oc[nt][1] * i0);
        *(float2*)&ctx[(tok0 + 8) * INNER + col] =
            make_float2(oc[nt][2] * i1, oc[nt][3] * i1);
    }
}

// ---------------------------------------------------------------------------
// Host launch
// ---------------------------------------------------------------------------
extern "C" void kernel_launch(void* const* d_in, const int* in_sizes, int n_in,
                              void* d_out, int out_size)
{
    const float* x_in    = (const float*)d_in[0];
    const float* ln_s_g  = (const float*)d_in[1];
    const float* ln_s_b  = (const float*)d_in[2];
    const float* w_qkv_s = (const float*)d_in[3];
    const float* w_out_s = (const float*)d_in[4];
    const float* b_out_s = (const float*)d_in[5];
    const float* ln_t_g  = (const float*)d_in[6];
    const float* ln_t_b  = (const float*)d_in[7];
    const float* w_qkv_t = (const float*)d_in[8];
    const float* w_out_t = (const float*)d_in[9];
    const float* b_out_t = (const float*)d_in[10];
    const float* ln_f_g  = (const float*)d_in[11];
    const float* ln_f_b  = (const float*)d_in[12];
    float* x = (float*)d_out;

    cudaFuncSetAttribute(attn_tc_kernel, cudaFuncAttributeMaxDynamicSharedMemorySize,
                         ATTN_TC_SMEM);
    cudaFuncSetAttribute(tgemm_kernel, cudaFuncAttributeMaxDynamicSharedMemorySize,
                         TGEMM_SMEM_BYTES);

    float *qkv_p, *ctx_p, *xs_p, *xt_p;
    cudaGetSymbolAddress((void**)&qkv_p, g_qkv);
    cudaGetSymbolAddress((void**)&ctx_p, g_ctx);
    cudaGetSymbolAddress((void**)&xs_p,  g_xs);
    cudaGetSymbolAddress((void**)&xt_p,  g_xt);
    float* ln_p = ctx_p;   // LN output aliases ctx (lifetimes disjoint)

    cudaMemcpyAsync(x, x_in, (size_t)NTOK * DD * sizeof(float),
                    cudaMemcpyDeviceToDevice);
    rope_table_kernel<<<(256 * 32 + 255) / 256, 256>>>();

    dim3 ln_grid(NTOK / 8);
    dim3 gemm_qkv_grid(NTOK / TBM, QKV3 / TBN);
    dim3 gemm_out_grid(NTOK / TBM, DD / TBN);
    dim3 attn_s_grid(PP / 64, HH, BB * TT);
    dim3 attn_t_grid(TT / 64, HH, BB * PP);

    for (int i = 0; i < DEPTH; i++) {
        const float* wq_s = w_qkv_s + (size_t)i * DD * QKV3;
        const float* wo_s = w_out_s + (size_t)i * INNER * DD;
        const float* wq_t = w_qkv_t + (size_t)i * DD * QKV3;
        const float* wo_t = w_out_t + (size_t)i * INNER * DD;

        // ---- spatial branch ----
        ln_kernel<<<ln_grid, 256>>>(x, ln_s_g + i * DD, ln_s_b + i * DD, ln_p);
        tgemm_kernel<<<gemm_qkv_grid, 256, TGEMM_SMEM_BYTES>>>(
            ln_p, wq_s, nullptr, qkv_p, NTOK, QKV3, DD);
        attn_tc_kernel<<<attn_s_grid, 128, ATTN_TC_SMEM>>>(qkv_p, ctx_p, PP);
        tgemm_kernel<<<gemm_out_grid, 256, TGEMM_SMEM_BYTES>>>(
            ctx_p, wo_s, b_out_s + i * DD, xs_p, NTOK, DD, DD);

        // ---- temporal branch ----
        ln_add_transpose_kernel<<<ln_grid, 256>>>(x, xs_p, ln_t_g + i * DD,
                                                  ln_t_b + i * DD, ln_p);
        tgemm_kernel<<<gemm_qkv_grid, 256, TGEMM_SMEM_BYTES>>>(
            ln_p, wq_t, nullptr, qkv_p, NTOK, QKV3, DD);
        attn_tc_kernel<<<attn_t_grid, 128, ATTN_TC_SMEM>>>(qkv_p, ctx_p, TT);
        tgemm_kernel<<<gemm_out_grid, 256, TGEMM_SMEM_BYTES>>>(
            ctx_p, wo_t, b_out_t + i * DD, xt_p, NTOK, DD, DD);

        // ---- finish ----
        ln_final_kernel<<<ln_grid, 256>>>(xs_p, xt_p, ln_f_g + i * DD,
                                          ln_f_b + i * DD, x);
    }
}

// round 6
// speedup vs baseline: 3.1130x; 1.0564x over previous
#include <cuda_runtime.h>
#include <cuda_bf16.h>
#include <math.h>
#include <stdint.h>

// ---------------------------------------------------------------------------
// Problem constants
// ---------------------------------------------------------------------------
#define BB    2
#define TT    64
#define PP    256
#define DD    512
#define HH    8
#define DH    64
#define INNER 512          // HH*DH
#define QKV3  1536         // 3*INNER
#define NTOK  32768        // BB*TT*PP
#define DEPTH 4
#define LN_EPS 1e-5f

#define WQKV_SZ (DEPTH * DD * QKV3)    // 3,145,728
#define WOUT_SZ (DEPTH * INNER * DD)   // 1,048,576

// ---------------------------------------------------------------------------
// Static device scratch
// ---------------------------------------------------------------------------
__device__ float g_qkv[(size_t)NTOK * QKV3];
__device__ float g_ctx[(size_t)NTOK * INNER];
__device__ float g_xs [(size_t)NTOK * DD];
__device__ float g_xt [(size_t)NTOK * DD];
__device__ float g_wr [2 * (WQKV_SZ + WOUT_SZ)];   // pre-rounded weights
__device__ float g_cos[256 * 32];
__device__ float g_sin[256 * 32];

// ---------------------------------------------------------------------------
// RoPE table
// ---------------------------------------------------------------------------
__global__ void rope_table_kernel() {
    int i = blockIdx.x * blockDim.x + threadIdx.x;
    if (i >= 256 * 32) return;
    int pos = i >> 5;
    int j   = i & 31;
    float freq  = powf(10000.0f, -(float)(2 * j) / 64.0f);
    float theta = (float)pos * freq;
    float s, c;
    sincosf(theta, &s, &c);
    g_cos[i] = c;
    g_sin[i] = s;
}

// ---------------------------------------------------------------------------
// Fast exp on the FMA pipe (no MUFU). |rel err| ~1e-7 for x in [-80, 0].
// ---------------------------------------------------------------------------
__device__ __forceinline__ float fexp(float x) {
    x = fmaxf(x, -80.0f);
    float y = x * 1.44269504088896340736f;
    float t = y + 12582912.0f;
    int   n = __float_as_int(t) - 0x4B400000;
    float f = y - (t - 12582912.0f);
    float p =             1.54035303933e-4f;
    p = fmaf(p, f, 1.33335581464e-3f);
    p = fmaf(p, f, 9.61812910763e-3f);
    p = fmaf(p, f, 5.55041086648e-2f);
    p = fmaf(p, f, 2.40226506959e-1f);
    p = fmaf(p, f, 6.93147180560e-1f);
    p = fmaf(p, f, 1.0f);
    return p * __int_as_float((n + 127) << 23);
}

// tf32 round-to-nearest (bits are valid raw mma operands)
__device__ __forceinline__ float tf32r(float f) {
    uint32_t u;
    asm volatile("cvt.rna.tf32.f32 %0, %1;" : "=r"(u) : "f"(f));
    return __uint_as_float(u);
}

__device__ __forceinline__ void mma_tf32(float c[4],
                                         uint32_t a0, uint32_t a1, uint32_t a2, uint32_t a3,
                                         uint32_t b0, uint32_t b1)
{
    asm volatile(
        "mma.sync.aligned.m16n8k8.row.col.f32.tf32.tf32.f32 "
        "{%0,%1,%2,%3}, {%4,%5,%6,%7}, {%8,%9}, {%0,%1,%2,%3};"
        : "+f"(c[0]), "+f"(c[1]), "+f"(c[2]), "+f"(c[3])
        : "r"(a0), "r"(a1), "r"(a2), "r"(a3), "r"(b0), "r"(b1));
}

// ---------------------------------------------------------------------------
// Weight pre-rounding: dst[i] = tf32r(src[i])
// ---------------------------------------------------------------------------
__global__ void round_tf32_kernel(const float* __restrict__ src,
                                  float* __restrict__ dst, int n4)
{
    int i = blockIdx.x * blockDim.x + threadIdx.x;
    if (i >= n4) return;
    float4 v = *(const float4*)(src + 4 * (size_t)i);
    v.x = tf32r(v.x); v.y = tf32r(v.y); v.z = tf32r(v.z); v.w = tf32r(v.w);
    *(float4*)(dst + 4 * (size_t)i) = v;
}

// ---------------------------------------------------------------------------
// Warp-per-row LayerNorm over D=512
// ---------------------------------------------------------------------------
__device__ __forceinline__ void warp_ln_core(
    const float4 v[4], int lane,
    const float* __restrict__ g, const float* __restrict__ b,
    float4 o[4])
{
    float s = 0.f, s2 = 0.f;
#pragma unroll
    for (int i = 0; i < 4; i++) {
        s  += v[i].x + v[i].y + v[i].z + v[i].w;
        s2 += v[i].x * v[i].x + v[i].y * v[i].y + v[i].z * v[i].z + v[i].w * v[i].w;
    }
#pragma unroll
    for (int o_ = 16; o_ > 0; o_ >>= 1) {
        s  += __shfl_xor_sync(0xffffffffu, s,  o_);
        s2 += __shfl_xor_sync(0xffffffffu, s2, o_);
    }
    float mu   = s * (1.0f / 512.0f);
    float var  = s2 * (1.0f / 512.0f) - mu * mu;
    float rstd = rsqrtf(var + LN_EPS);
#pragma unroll
    for (int i = 0; i < 4; i++) {
        int c = (lane + 32 * i) * 4;
        float4 gg = *(const float4*)(g + c);
        float4 bb = *(const float4*)(b + c);
        o[i].x = (v[i].x - mu) * rstd * gg.x + bb.x;
        o[i].y = (v[i].y - mu) * rstd * gg.y + bb.y;
        o[i].z = (v[i].z - mu) * rstd * gg.z + bb.z;
        o[i].w = (v[i].w - mu) * rstd * gg.w + bb.w;
    }
}

// out = tf32r(LN(x))  — feeds QKV GEMM only
__global__ void ln_kernel(const float* __restrict__ x,
                          const float* __restrict__ g, const float* __restrict__ b,
                          float* __restrict__ out)
{
    int row  = blockIdx.x * 8 + (threadIdx.x >> 5);
    int lane = threadIdx.x & 31;
    const float* xr = x + (size_t)row * DD;
    float4 v[4];
#pragma unroll
    for (int i = 0; i < 4; i++) v[i] = *(const float4*)(xr + (lane + 32 * i) * 4);
    float4 o[4];
    warp_ln_core(v, lane, g, b, o);
    float* orow = out + (size_t)row * DD;
#pragma unroll
    for (int i = 0; i < 4; i++) {
        o[i].x = tf32r(o[i].x); o[i].y = tf32r(o[i].y);
        o[i].z = tf32r(o[i].z); o[i].w = tf32r(o[i].w);
        *(float4*)(orow + (lane + 32 * i) * 4) = o[i];
    }
}

// out = tf32r(LN(x[src] + xs[src])) in (b,p,t) order — feeds QKV GEMM only
__global__ void ln_add_transpose_kernel(const float* __restrict__ x,
                                        const float* __restrict__ xs,
                                        const float* __restrict__ g, const float* __restrict__ b,
                                        float* __restrict__ out)
{
    int row  = blockIdx.x * 8 + (threadIdx.x >> 5);
    int lane = threadIdx.x & 31;
    int t_ = row & 63;
    int p_ = (row >> 6) & 255;
    int b_ = row >> 14;
    int src = (b_ * TT + t_) * PP + p_;
    const float* xr  = x  + (size_t)src * DD;
    const float* xsr = xs + (size_t)src * DD;
    float4 v[4];
#pragma unroll
    for (int i = 0; i < 4; i++) {
        float4 a = *(const float4*)(xr  + (lane + 32 * i) * 4);
        float4 c = *(const float4*)(xsr + (lane + 32 * i) * 4);
        v[i].x = a.x + c.x; v[i].y = a.y + c.y; v[i].z = a.z + c.z; v[i].w = a.w + c.w;
    }
    float4 o[4];
    warp_ln_core(v, lane, g, b, o);
    float* orow = out + (size_t)row * DD;
#pragma unroll
    for (int i = 0; i < 4; i++) {
        o[i].x = tf32r(o[i].x); o[i].y = tf32r(o[i].y);
        o[i].z = tf32r(o[i].z); o[i].w = tf32r(o[i].w);
        *(float4*)(orow + (lane + 32 * i) * 4) = o[i];
    }
}

// x = LN(xs + xt[perm]) + x  (full fp32 — residual/output path)
__global__ void ln_final_kernel(const float* __restrict__ xs,
                                const float* __restrict__ xt,
                                const float* __restrict__ g, const float* __restrict__ b,
                                float* __restrict__ x)
{
    int row  = blockIdx.x * 8 + (threadIdx.x >> 5);
    int lane = threadIdx.x & 31;
    int p_ = row & 255;
    int t_ = (row >> 8) & 63;
    int b_ = row >> 14;
    int xtr = (b_ * PP + p_) * TT + t_;
    const float* xsr = xs + (size_t)row * DD;
    const float* xtr_p = xt + (size_t)xtr * DD;
    float* xr = x + (size_t)row * DD;
    float4 v[4], xv[4];
#pragma unroll
    for (int i = 0; i < 4; i++) {
        float4 a = *(const float4*)(xsr + (lane + 32 * i) * 4);
        float4 c = *(const float4*)(xtr_p + (lane + 32 * i) * 4);
        v[i].x = a.x + c.x; v[i].y = a.y + c.y; v[i].z = a.z + c.z; v[i].w = a.w + c.w;
        xv[i] = *(const float4*)(xr + (lane + 32 * i) * 4);
    }
    float4 o[4];
    warp_ln_core(v, lane, g, b, o);
#pragma unroll
    for (int i = 0; i < 4; i++) {
        o[i].x += xv[i].x; o[i].y += xv[i].y; o[i].z += xv[i].z; o[i].w += xv[i].w;
        *(float4*)(xr + (lane + 32 * i) * 4) = o[i];
    }
}

// ---------------------------------------------------------------------------
// tf32 tensor-core GEMM. Inputs are PRE-ROUNDED to tf32 -> raw-bit mma,
// zero cvt in the hot loop. 128x128x32 tile, 8 warps, double-buffered cp.async.
// ---------------------------------------------------------------------------
#define TBM 128
#define TBN 128
#define TBK 32
#define A_STR 36
#define B_STR 136
#define A_BUF (TBM * A_STR)
#define B_BUF (TBK * B_STR)
#define TGEMM_SMEM_BYTES ((2 * A_BUF + 2 * B_BUF) * 4)

__device__ __forceinline__ void cp_async16(uint32_t dst, const void* src) {
    asm volatile("cp.async.cg.shared.global [%0], [%1], 16;\n" :: "r"(dst), "l"(src));
}

__global__ void __launch_bounds__(256, 2) tgemm_kernel(
    const float* __restrict__ A, const float* __restrict__ W,
    const float* __restrict__ bias, float* __restrict__ C,
    int M, int N, int K)
{
    extern __shared__ float sm[];
    float* As = sm;
    float* Bs = sm + 2 * A_BUF;

    int tid  = threadIdx.x;
    int lane = tid & 31;
    int wid  = tid >> 5;
    int wm   = wid >> 2;
    int wn   = wid & 3;
    int grp  = lane >> 2;
    int tig  = lane & 3;
    int bm = blockIdx.x, bn = blockIdx.y;

    const float* Ag = A + (size_t)bm * TBM * K;
    const float* Wg = W + (size_t)bn * TBN;

    uint32_t as_base = (uint32_t)__cvta_generic_to_shared(As);
    uint32_t bs_base = (uint32_t)__cvta_generic_to_shared(Bs);

    float acc[4][4][4];
#pragma unroll
    for (int i = 0; i < 4; i++)
#pragma unroll
        for (int j = 0; j < 4; j++)
#pragma unroll
            for (int c = 0; c < 4; c++) acc[i][j][c] = 0.f;

    const int NK = K / TBK;

    auto load_tiles = [&](int kt, int buf) {
#pragma unroll
        for (int it = 0; it < 4; it++) {
            int slot = tid + it * 256;
            int row  = slot >> 3;
            int c4   = (slot & 7) * 4;
            uint32_t dst = as_base + (buf * A_BUF + row * A_STR + c4) * 4;
            cp_async16(dst, Ag + (size_t)row * K + kt * TBK + c4);
        }
#pragma unroll
        for (int it = 0; it < 4; it++) {
            int slot = tid + it * 256;
            int row  = slot >> 5;
            int c4   = (slot & 31) * 4;
            uint32_t dst = bs_base + (buf * B_BUF + row * B_STR + c4) * 4;
            cp_async16(dst, Wg + (size_t)(kt * TBK + row) * N + c4);
        }
        asm volatile("cp.async.commit_group;\n");
    };

    load_tiles(0, 0);

    for (int kt = 0; kt < NK; kt++) {
        int buf = kt & 1;
        if (kt + 1 < NK) {
            load_tiles(kt + 1, buf ^ 1);
            asm volatile("cp.async.wait_group 1;\n");
        } else {
            asm volatile("cp.async.wait_group 0;\n");
        }
        __syncthreads();

        const float* as = As + buf * A_BUF;
        const float* bs = Bs + buf * B_BUF;

#pragma unroll
        for (int ks = 0; ks < 4; ks++) {
            int k = ks * 8;
            uint32_t af[4][4];
#pragma unroll
            for (int mt = 0; mt < 4; mt++) {
                int m = wm * 64 + mt * 16;
                af[mt][0] = __float_as_uint(as[(m + grp    ) * A_STR + k + tig    ]);
                af[mt][1] = __float_as_uint(as[(m + grp + 8) * A_STR + k + tig    ]);
                af[mt][2] = __float_as_uint(as[(m + grp    ) * A_STR + k + tig + 4]);
                af[mt][3] = __float_as_uint(as[(m + grp + 8) * A_STR + k + tig + 4]);
            }
            uint32_t bf[4][2];
#pragma unroll
            for (int nt = 0; nt < 4; nt++) {
                int n = wn * 32 + nt * 8;
                bf[nt][0] = __float_as_uint(bs[(k + tig    ) * B_STR + n + grp]);
                bf[nt][1] = __float_as_uint(bs[(k + tig + 4) * B_STR + n + grp]);
            }
#pragma unroll
            for (int mt = 0; mt < 4; mt++)
#pragma unroll
                for (int nt = 0; nt < 4; nt++)
                    mma_tf32(acc[mt][nt], af[mt][0], af[mt][1], af[mt][2], af[mt][3],
                             bf[nt][0], bf[nt][1]);
        }
        __syncthreads();
    }

#pragma unroll
    for (int nt = 0; nt < 4; nt++) {
        int colg = bn * TBN + wn * 32 + nt * 8 + 2 * tig;
        float2 bv = {0.f, 0.f};
        if (bias) bv = *(const float2*)(bias + colg);
#pragma unroll
        for (int mt = 0; mt < 4; mt++) {
            int row0 = bm * TBM + wm * 64 + mt * 16 + grp;
            float2 lo = {acc[mt][nt][0] + bv.x, acc[mt][nt][1] + bv.y};
            float2 hi = {acc[mt][nt][2] + bv.x, acc[mt][nt][3] + bv.y};
            *(float2*)(C + (size_t)row0 * N + colg)       = lo;
            *(float2*)(C + (size_t)(row0 + 8) * N + colg) = hi;
        }
    }
}

// ---------------------------------------------------------------------------
// Tensor-core flash attention (tf32 mma + FMA-pipe exp). Unchanged except
// the ctx epilogue emits tf32-rounded values (feeds out-proj GEMM only).
// ---------------------------------------------------------------------------
#define AST 76
#define ATTN_TC_SMEM (3 * 64 * AST * 4)

__global__ void __launch_bounds__(128, 3) attn_tc_kernel(
    const float* __restrict__ qkv, float* __restrict__ ctx, int L)
{
    extern __shared__ float sm[];
    float* qs = sm;
    float* ks = sm + 64 * AST;
    float* vs = sm + 2 * 64 * AST;
    float* ps = qs;

    int tid  = threadIdx.x;
    int lane = tid & 31;
    int w    = tid >> 5;
    int grp  = lane >> 2;
    int tig  = lane & 3;
    int qt = blockIdx.x, h = blockIdx.y;
    size_t seq_base = (size_t)blockIdx.z * L;
    int qbase = qt * 64;
    int m0 = w * 16;

#pragma unroll
    for (int it = 0; it < 16; it++) {
        int slot = it * 128 + tid;
        int row = slot >> 5, pr = slot & 31;
        int pos = qbase + row;
        const float* p = qkv + (seq_base + pos) * QKV3 + h * DH + 2 * pr;
        float2 qv = *(const float2*)p;
        float c = g_cos[pos * 32 + pr], sn = g_sin[pos * 32 + pr];
        float e0 = (qv.x * c - qv.y * sn) * 0.125f;
        float e1 = (qv.y * c + qv.x * sn) * 0.125f;
        *(float2*)&qs[row * AST + 2 * pr] = make_float2(tf32r(e0), tf32r(e1));
    }

    auto stage_kv = [&](int kt) {
#pragma unroll
        for (int it = 0; it < 16; it++) {
            int slot = it * 128 + tid;
            int row = slot >> 5, pr = slot & 31;
            int pos = kt * 64 + row;
            const float* p = qkv + (seq_base + pos) * QKV3 + INNER + h * DH + 2 * pr;
            float2 kv = *(const float2*)p;
            float c = g_cos[pos * 32 + pr], sn = g_sin[pos * 32 + pr];
            float e0 = kv.x * c - kv.y * sn;
            float e1 = kv.y * c + kv.x * sn;
            *(float2*)&ks[row * AST + 2 * pr] = make_float2(tf32r(e0), tf32r(e1));
        }
#pragma unroll
        for (int it = 0; it < 8; it++) {
            int slot = it * 128 + tid;
            int row = slot >> 4, c4 = (slot & 15) * 4;
            const float* p = qkv + (seq_base + kt * 64 + row) * QKV3 + 2 * INNER + h * DH + c4;
            float4 vv = *(const float4*)p;
            vv.x = tf32r(vv.x); vv.y = tf32r(vv.y);
            vv.z = tf32r(vv.z); vv.w = tf32r(vv.w);
            *(float4*)&vs[row * AST + c4] = vv;
        }
    };

    stage_kv(0);
    __syncthreads();

    uint32_t qa[8][4];
#pragma unroll
    for (int kk = 0; kk < 8; kk++) {
        int k = kk * 8;
        qa[kk][0] = __float_as_uint(qs[(m0 + grp    ) * AST + k + tig    ]);
        qa[kk][1] = __float_as_uint(qs[(m0 + grp + 8) * AST + k + tig    ]);
        qa[kk][2] = __float_as_uint(qs[(m0 + grp    ) * AST + k + tig + 4]);
        qa[kk][3] = __float_as_uint(qs[(m0 + grp + 8) * AST + k + tig + 4]);
    }

    float mrow[2] = {-1e30f, -1e30f};
    float lrow[2] = {0.f, 0.f};
    float oc[8][4];
#pragma unroll
    for (int nt = 0; nt < 8; nt++)
#pragma unroll
        for (int c = 0; c < 4; c++) oc[nt][c] = 0.f;

    int ntl = L >> 6;
    for (int kt = 0; kt < ntl; kt++) {
        if (kt > 0) {
            __syncthreads();
            stage_kv(kt);
            __syncthreads();
        }

        float sacc[8][4];
#pragma unroll
        for (int nt = 0; nt < 8; nt++)
#pragma unroll
            for (int c = 0; c < 4; c++) sacc[nt][c] = 0.f;
#pragma unroll
        for (int kk = 0; kk < 8; kk++) {
            int k = kk * 8;
#pragma unroll
            for (int nt = 0; nt < 8; nt++) {
                uint32_t b0 = __float_as_uint(ks[(nt * 8 + grp) * AST + k + tig    ]);
                uint32_t b1 = __float_as_uint(ks[(nt * 8 + grp) * AST + k + tig + 4]);
                mma_tf32(sacc[nt], qa[kk][0], qa[kk][1], qa[kk][2], qa[kk][3], b0, b1);
            }
        }

        float mx0 = -1e30f, mx1 = -1e30f;
#pragma unroll
        for (int nt = 0; nt < 8; nt++) {
            mx0 = fmaxf(mx0, fmaxf(sacc[nt][0], sacc[nt][1]));
            mx1 = fmaxf(mx1, fmaxf(sacc[nt][2], sacc[nt][3]));
        }
        mx0 = fmaxf(mx0, __shfl_xor_sync(0xffffffffu, mx0, 1));
        mx0 = fmaxf(mx0, __shfl_xor_sync(0xffffffffu, mx0, 2));
        mx1 = fmaxf(mx1, __shfl_xor_sync(0xffffffffu, mx1, 1));
        mx1 = fmaxf(mx1, __shfl_xor_sync(0xffffffffu, mx1, 2));
        float nm0 = fmaxf(mrow[0], mx0), nm1 = fmaxf(mrow[1], mx1);
        float al0 = fexp(mrow[0] - nm0),  al1 = fexp(mrow[1] - nm1);
        float s0 = 0.f, s1 = 0.f;
#pragma unroll
        for (int nt = 0; nt < 8; nt++) {
            float p0 = fexp(sacc[nt][0] - nm0);
            float p1 = fexp(sacc[nt][1] - nm0);
            float p2 = fexp(sacc[nt][2] - nm1);
            float p3 = fexp(sacc[nt][3] - nm1);
            s0 += p0 + p1;
            s1 += p2 + p3;
            *(float2*)&ps[(m0 + grp    ) * AST + nt * 8 + 2 * tig] =
                make_float2(tf32r(p0), tf32r(p1));
            *(float2*)&ps[(m0 + grp + 8) * AST + nt * 8 + 2 * tig] =
                make_float2(tf32r(p2), tf32r(p3));
        }
        s0 += __shfl_xor_sync(0xffffffffu, s0, 1);
        s0 += __shfl_xor_sync(0xffffffffu, s0, 2);
        s1 += __shfl_xor_sync(0xffffffffu, s1, 1);
        s1 += __shfl_xor_sync(0xffffffffu, s1, 2);
        lrow[0] = lrow[0] * al0 + s0;
        lrow[1] = lrow[1] * al1 + s1;
        mrow[0] = nm0; mrow[1] = nm1;
#pragma unroll
        for (int nt = 0; nt < 8; nt++) {
            oc[nt][0] *= al0; oc[nt][1] *= al0;
            oc[nt][2] *= al1; oc[nt][3] *= al1;
        }
        __syncwarp();

#pragma unroll
        for (int kk = 0; kk < 8; kk++) {
            int k = kk * 8;
            uint32_t pa0 = __float_as_uint(ps[(m0 + grp    ) * AST + k + tig    ]);
            uint32_t pa1 = __float_as_uint(ps[(m0 + grp + 8) * AST + k + tig    ]);
            uint32_t pa2 = __float_as_uint(ps[(m0 + grp    ) * AST + k + tig + 4]);
            uint32_t pa3 = __float_as_uint(ps[(m0 + grp + 8) * AST + k + tig + 4]);
#pragma unroll
            for (int nt = 0; nt < 8; nt++) {
                uint32_t vb0 = __float_as_uint(vs[(k + tig    ) * AST + nt * 8 + grp]);
                uint32_t vb1 = __float_as_uint(vs[(k + tig + 4) * AST + nt * 8 + grp]);
                mma_tf32(oc[nt], pa0, pa1, pa2, pa3, vb0, vb1);
            }
        }
        __syncwarp();
    }

    // epilogue: tf32-rounded ctx (feeds the out-proj GEMM only)
    float i0 = 1.0f / lrow[0], i1 = 1.0f / lrow[1];
    size_t tok0 = seq_base + qbase + m0 + grp;
#pragma unroll
    for (int nt = 0; nt < 8; nt++) {
        int col = h * DH + nt * 8 + 2 * tig;
        *(float2*)&ctx[tok0 * INNER + col] =
            make_float2(tf32r(oc[nt][0] * i0), tf32r(oc[nt][1] * i0));
        *(float2*)&ctx[(tok0 + 8) * INNER + col] =
            make_float2(tf32r(oc[nt][2] * i1), tf32r(oc[nt][3] * i1));
    }
}

// ---------------------------------------------------------------------------
// Host launch
// ---------------------------------------------------------------------------
extern "C" void kernel_launch(void* const* d_in, const int* in_sizes, int n_in,
                              void* d_out, int out_size)
{
    const float* x_in    = (const float*)d_in[0];
    const float* ln_s_g  = (const float*)d_in[1];
    const float* ln_s_b  = (const float*)d_in[2];
    const float* w_qkv_s = (const float*)d_in[3];
    const float* w_out_s = (const float*)d_in[4];
    const float* b_out_s = (const float*)d_in[5];
    const float* ln_t_g  = (const float*)d_in[6];
    const float* ln_t_b  = (const float*)d_in[7];
    const float* w_qkv_t = (const float*)d_in[8];
    const float* w_out_t = (const float*)d_in[9];
    const float* b_out_t = (const float*)d_in[10];
    const float* ln_f_g  = (const float*)d_in[11];
    const float* ln_f_b  = (const float*)d_in[12];
    float* x = (float*)d_out;

    cudaFuncSetAttribute(attn_tc_kernel, cudaFuncAttributeMaxDynamicSharedMemorySize,
                         ATTN_TC_SMEM);
    cudaFuncSetAttribute(tgemm_kernel, cudaFuncAttributeMaxDynamicSharedMemorySize,
                         TGEMM_SMEM_BYTES);

    float *qkv_p, *ctx_p, *xs_p, *xt_p, *wr_p;
    cudaGetSymbolAddress((void**)&qkv_p, g_qkv);
    cudaGetSymbolAddress((void**)&ctx_p, g_ctx);
    cudaGetSymbolAddress((void**)&xs_p,  g_xs);
    cudaGetSymbolAddress((void**)&xt_p,  g_xt);
    cudaGetSymbolAddress((void**)&wr_p,  g_wr);
    float* ln_p = ctx_p;   // LN output aliases ctx (lifetimes disjoint)

    float* wr_qkv_s = wr_p;
    float* wr_out_s = wr_p + WQKV_SZ;
    float* wr_qkv_t = wr_p + WQKV_SZ + WOUT_SZ;
    float* wr_out_t = wr_p + 2 * WQKV_SZ + WOUT_SZ;

    cudaMemcpyAsync(x, x_in, (size_t)NTOK * DD * sizeof(float),
                    cudaMemcpyDeviceToDevice);
    rope_table_kernel<<<(256 * 32 + 255) / 256, 256>>>();

    // pre-round all weights to tf32 once per launch
    round_tf32_kernel<<<WQKV_SZ / 4 / 256, 256>>>(w_qkv_s, wr_qkv_s, WQKV_SZ / 4);
    round_tf32_kernel<<<WOUT_SZ / 4 / 256, 256>>>(w_out_s, wr_out_s, WOUT_SZ / 4);
    round_tf32_kernel<<<WQKV_SZ / 4 / 256, 256>>>(w_qkv_t, wr_qkv_t, WQKV_SZ / 4);
    round_tf32_kernel<<<WOUT_SZ / 4 / 256, 256>>>(w_out_t, wr_out_t, WOUT_SZ / 4);

    dim3 ln_grid(NTOK / 8);
    dim3 gemm_qkv_grid(NTOK / TBM, QKV3 / TBN);
    dim3 gemm_out_grid(NTOK / TBM, DD / TBN);
    dim3 attn_s_grid(PP / 64, HH, BB * TT);
    dim3 attn_t_grid(TT / 64, HH, BB * PP);

    for (int i = 0; i < DEPTH; i++) {
        const float* wq_s = wr_qkv_s + (size_t)i * DD * QKV3;
        const float* wo_s = wr_out_s + (size_t)i * INNER * DD;
        const float* wq_t = wr_qkv_t + (size_t)i * DD * QKV3;
        const float* wo_t = wr_out_t + (size_t)i * INNER * DD;

        // ---- spatial branch ----
        ln_kernel<<<ln_grid, 256>>>(x, ln_s_g + i * DD, ln_s_b + i * DD, ln_p);
        tgemm_kernel<<<gemm_qkv_grid, 256, TGEMM_SMEM_BYTES>>>(
            ln_p, wq_s, nullptr, qkv_p, NTOK, QKV3, DD);
        attn_tc_kernel<<<attn_s_grid, 128, ATTN_TC_SMEM>>>(qkv_p, ctx_p, PP);
        tgemm_kernel<<<gemm_out_grid, 256, TGEMM_SMEM_BYTES>>>(
            ctx_p, wo_s, b_out_s + i * DD, xs_p, NTOK, DD, DD);

        // ---- temporal branch ----
        ln_add_transpose_kernel<<<ln_grid, 256>>>(x, xs_p, ln_t_g + i * DD,
                                                  ln_t_b + i * DD, ln_p);
        tgemm_kernel<<<gemm_qkv_grid, 256, TGEMM_SMEM_BYTES>>>(
            ln_p, wq_t, nullptr, qkv_p, NTOK, QKV3, DD);
        attn_tc_kernel<<<attn_t_grid, 128, ATTN_TC_SMEM>>>(qkv_p, ctx_p, TT);
        tgemm_kernel<<<gemm_out_grid, 256, TGEMM_SMEM_BYTES>>>(
            ctx_p, wo_t, b_out_t + i * DD, xt_p, NTOK, DD, DD);

        // ---- finish ----
        ln_final_kernel<<<ln_grid, 256>>>(xs_p, xt_p, ln_f_g + i * DD,
                                          ln_f_b + i * DD, x);
    }
}

// round 10
// speedup vs baseline: 4.1386x; 1.3294x over previous
#include <cuda_runtime.h>
#include <cuda_bf16.h>
#include <cuda_fp16.h>
#include <math.h>
#include <stdint.h>

// ---------------------------------------------------------------------------
// Problem constants
// ---------------------------------------------------------------------------
#define BB    2
#define TT    64
#define PP    256
#define DD    512
#define HH    8
#define DH    64
#define INNER 512          // HH*DH
#define QKV3  1536         // 3*INNER
#define NTOK  32768        // BB*TT*PP
#define DEPTH 4
#define LN_EPS 1e-5f

#define WQKV_SZ (DEPTH * DD * QKV3)
#define WOUT_SZ (DEPTH * INNER * DD)

// ---------------------------------------------------------------------------
// Static device scratch
// g_ctx (fp16) doubles as the LN-output buffer (lifetimes disjoint,
// identical element counts: NTOK*INNER == NTOK*DD).
// ---------------------------------------------------------------------------
__device__ float    g_qkv[(size_t)NTOK * QKV3];
__device__ __half   g_ctx[(size_t)NTOK * INNER];
__device__ float    g_xs [(size_t)NTOK * DD];
__device__ float    g_xt [(size_t)NTOK * DD];
__device__ uint32_t g_wp [WQKV_SZ + WOUT_SZ];   // k-pair-packed fp16 weights
__device__ float    g_cos[256 * 32];
__device__ float    g_sin[256 * 32];

// ---------------------------------------------------------------------------
// RoPE table
// ---------------------------------------------------------------------------
__global__ void rope_table_kernel() {
    int i = blockIdx.x * blockDim.x + threadIdx.x;
    if (i >= 256 * 32) return;
    int pos = i >> 5;
    int j   = i & 31;
    float freq  = powf(10000.0f, -(float)(2 * j) / 64.0f);
    float theta = (float)pos * freq;
    float s, c;
    sincosf(theta, &s, &c);
    g_cos[i] = c;
    g_sin[i] = s;
}

// ---------------------------------------------------------------------------
// Fast exp on the FMA pipe
// ---------------------------------------------------------------------------
__device__ __forceinline__ float fexp(float x) {
    x = fmaxf(x, -80.0f);
    float y = x * 1.44269504088896340736f;
    float t = y + 12582912.0f;
    int   n = __float_as_int(t) - 0x4B400000;
    float f = y - (t - 12582912.0f);
    float p =             1.54035303933e-4f;
    p = fmaf(p, f, 1.33335581464e-3f);
    p = fmaf(p, f, 9.61812910763e-3f);
    p = fmaf(p, f, 5.55041086648e-2f);
    p = fmaf(p, f, 2.40226506959e-1f);
    p = fmaf(p, f, 6.93147180560e-1f);
    p = fmaf(p, f, 1.0f);
    return p * __int_as_float((n + 127) << 23);
}

// tf32 round-to-nearest (attention path)
__device__ __forceinline__ float tf32r(float f) {
    uint32_t u;
    asm volatile("cvt.rna.tf32.f32 %0, %1;" : "=r"(u) : "f"(f));
    return __uint_as_float(u);
}

__device__ __forceinline__ void mma_tf32(float c[4],
                                         uint32_t a0, uint32_t a1, uint32_t a2, uint32_t a3,
                                         uint32_t b0, uint32_t b1)
{
    asm volatile(
        "mma.sync.aligned.m16n8k8.row.col.f32.tf32.tf32.f32 "
        "{%0,%1,%2,%3}, {%4,%5,%6,%7}, {%8,%9}, {%0,%1,%2,%3};"
        : "+f"(c[0]), "+f"(c[1]), "+f"(c[2]), "+f"(c[3])
        : "r"(a0), "r"(a1), "r"(a2), "r"(a3), "r"(b0), "r"(b1));
}

__device__ __forceinline__ void mma_f16(float c[4],
                                        uint32_t a0, uint32_t a1, uint32_t a2, uint32_t a3,
                                        uint32_t b0, uint32_t b1)
{
    asm volatile(
        "mma.sync.aligned.m16n8k16.row.col.f32.f16.f16.f32 "
        "{%0,%1,%2,%3}, {%4,%5,%6,%7}, {%8,%9}, {%0,%1,%2,%3};"
        : "+f"(c[0]), "+f"(c[1]), "+f"(c[2]), "+f"(c[3])
        : "r"(a0), "r"(a1), "r"(a2), "r"(a3), "r"(b0), "r"(b1));
}

__device__ __forceinline__ void cp_async16(uint32_t dst, const void* src) {
    asm volatile("cp.async.cg.shared.global [%0], [%1], 16;\n" :: "r"(dst), "l"(src));
}

// ---------------------------------------------------------------------------
// Weight prep: dst word (k2, n) = half2(W[2k2][n], W[2k2+1][n])   per layer z
// ---------------------------------------------------------------------------
__global__ void pack_half_kernel(const float* __restrict__ src,
                                 uint32_t* __restrict__ dst, int K2, int N)
{
    int i = blockIdx.x * blockDim.x + threadIdx.x;
    if (i >= K2 * N) return;
    int z = blockIdx.y;
    const float* s = src + (size_t)z * 2 * K2 * N;
    int k2 = i / N, n = i - k2 * N;
    __half2 h = __floats2half2_rn(s[(size_t)(2 * k2) * N + n],
                                  s[(size_t)(2 * k2 + 1) * N + n]);
    dst[(size_t)z * K2 * N + i] = *(uint32_t*)&h;
}

// ---------------------------------------------------------------------------
// Warp-per-row LayerNorm over D=512
// ---------------------------------------------------------------------------
__device__ __forceinline__ void warp_ln_core(
    const float4 v[4], int lane,
    const float* __restrict__ g, const float* __restrict__ b,
    float4 o[4])
{
    float s = 0.f, s2 = 0.f;
#pragma unroll
    for (int i = 0; i < 4; i++) {
        s  += v[i].x + v[i].y + v[i].z + v[i].w;
        s2 += v[i].x * v[i].x + v[i].y * v[i].y + v[i].z * v[i].z + v[i].w * v[i].w;
    }
#pragma unroll
    for (int o_ = 16; o_ > 0; o_ >>= 1) {
        s  += __shfl_xor_sync(0xffffffffu, s,  o_);
        s2 += __shfl_xor_sync(0xffffffffu, s2, o_);
    }
    float mu   = s * (1.0f / 512.0f);
    float var  = s2 * (1.0f / 512.0f) - mu * mu;
    float rstd = rsqrtf(var + LN_EPS);
#pragma unroll
    for (int i = 0; i < 4; i++) {
        int c = (lane + 32 * i) * 4;
        float4 gg = *(const float4*)(g + c);
        float4 bb = *(const float4*)(b + c);
        o[i].x = (v[i].x - mu) * rstd * gg.x + bb.x;
        o[i].y = (v[i].y - mu) * rstd * gg.y + bb.y;
        o[i].z = (v[i].z - mu) * rstd * gg.z + bb.z;
        o[i].w = (v[i].w - mu) * rstd * gg.w + bb.w;
    }
}

__device__ __forceinline__ void store_half4(__half* p, float4 o) {
    __half2 ha = __floats2half2_rn(o.x, o.y);
    __half2 hb = __floats2half2_rn(o.z, o.w);
    uint2 pk = make_uint2(*(uint32_t*)&ha, *(uint32_t*)&hb);
    *(uint2*)p = pk;
}

// out = fp16(LN(x)) — feeds QKV GEMM only
__global__ void ln_kernel(const float* __restrict__ x,
                          const float* __restrict__ g, const float* __restrict__ b,
                          __half* __restrict__ out)
{
    int row  = blockIdx.x * 8 + (threadIdx.x >> 5);
    int lane = threadIdx.x & 31;
    const float* xr = x + (size_t)row * DD;
    float4 v[4];
#pragma unroll
    for (int i = 0; i < 4; i++) v[i] = *(const float4*)(xr + (lane + 32 * i) * 4);
    float4 o[4];
    warp_ln_core(v, lane, g, b, o);
    __half* orow = out + (size_t)row * DD;
#pragma unroll
    for (int i = 0; i < 4; i++) store_half4(orow + (lane + 32 * i) * 4, o[i]);
}

// out = fp16(LN(x[src] + xs[src])) in (b,p,t) order — feeds QKV GEMM only
__global__ void ln_add_transpose_kernel(const float* __restrict__ x,
                                        const float* __restrict__ xs,
                                        const float* __restrict__ g, const float* __restrict__ b,
                                        __half* __restrict__ out)
{
    int row  = blockIdx.x * 8 + (threadIdx.x >> 5);
    int lane = threadIdx.x & 31;
    int t_ = row & 63;
    int p_ = (row >> 6) & 255;
    int b_ = row >> 14;
    int src = (b_ * TT + t_) * PP + p_;
    const float* xr  = x  + (size_t)src * DD;
    const float* xsr = xs + (size_t)src * DD;
    float4 v[4];
#pragma unroll
    for (int i = 0; i < 4; i++) {
        float4 a = *(const float4*)(xr  + (lane + 32 * i) * 4);
        float4 c = *(const float4*)(xsr + (lane + 32 * i) * 4);
        v[i].x = a.x + c.x; v[i].y = a.y + c.y; v[i].z = a.z + c.z; v[i].w = a.w + c.w;
    }
    float4 o[4];
    warp_ln_core(v, lane, g, b, o);
    __half* orow = out + (size_t)row * DD;
#pragma unroll
    for (int i = 0; i < 4; i++) store_half4(orow + (lane + 32 * i) * 4, o[i]);
}

// x = LN(xs + xt[perm]) + x  (full fp32 — residual/output path)
__global__ void ln_final_kernel(const float* __restrict__ xs,
                                const float* __restrict__ xt,
                                const float* __restrict__ g, const float* __restrict__ b,
                                float* __restrict__ x)
{
    int row  = blockIdx.x * 8 + (threadIdx.x >> 5);
    int lane = threadIdx.x & 31;
    int p_ = row & 255;
    int t_ = (row >> 8) & 63;
    int b_ = row >> 14;
    int xtr = (b_ * PP + p_) * TT + t_;
    const float* xsr = xs + (size_t)row * DD;
    const float* xtr_p = xt + (size_t)xtr * DD;
    float* xr = x + (size_t)row * DD;
    float4 v[4], xv[4];
#pragma unroll
    for (int i = 0; i < 4; i++) {
        float4 a = *(const float4*)(xsr + (lane + 32 * i) * 4);
        float4 c = *(const float4*)(xtr_p + (lane + 32 * i) * 4);
        v[i].x = a.x + c.x; v[i].y = a.y + c.y; v[i].z = a.z + c.z; v[i].w = a.w + c.w;
        xv[i] = *(const float4*)(xr + (lane + 32 * i) * 4);
    }
    float4 o[4];
    warp_ln_core(v, lane, g, b, o);
#pragma unroll
    for (int i = 0; i < 4; i++) {
        o[i].x += xv[i].x; o[i].y += xv[i].y; o[i].z += xv[i].z; o[i].w += xv[i].w;
        *(float4*)(xr + (lane + 32 * i) * 4) = o[i];
    }
}

// ---------------------------------------------------------------------------
// fp16 tensor-core GEMM: C[M,N] = A[M,K] @ W[K,N] (+bias), fp32 accumulate.
// A: fp16 row-major. Bp: k-pair-packed fp16 words [K/2][N].
// 128x128x32 tile, 8 warps (2m x 4n), mma.m16n8k16, double-buffered cp.async.
// Smem: A 128x40 halves (word stride 20 -> bank permutation),
//       B 16x136 words (136 % 32 == 8 -> conflict-free b-frag).
// ---------------------------------------------------------------------------
#define HA_STR 40              // halves per A smem row
#define HB_STR 136             // words per B smem row
#define HA_BUF (128 * HA_STR)  // 5120 halves = 10240 B
#define HB_BUF (16 * HB_STR)   // 2176 words  =  8704 B

__global__ void __launch_bounds__(256) hgemm_kernel(
    const __half* __restrict__ A, const uint32_t* __restrict__ Bp,
    const float* __restrict__ bias, float* __restrict__ C,
    int M, int N, int K)
{
    __shared__ __half   As[2][HA_BUF];
    __shared__ uint32_t Bs[2][HB_BUF];

    int tid  = threadIdx.x;
    int lane = tid & 31;
    int wid  = tid >> 5;
    int wm   = wid >> 2;
    int wn   = wid & 3;
    int grp  = lane >> 2;
    int tig  = lane & 3;
    int bm = blockIdx.x, bn = blockIdx.y;

    const __half*   Ag = A  + (size_t)bm * 128 * K;
    const uint32_t* Bg = Bp + bn * 128;

    uint32_t as_base = (uint32_t)__cvta_generic_to_shared(&As[0][0]);
    uint32_t bs_base = (uint32_t)__cvta_generic_to_shared(&Bs[0][0]);

    float acc[4][4][4];
#pragma unroll
    for (int i = 0; i < 4; i++)
#pragma unroll
        for (int j = 0; j < 4; j++)
#pragma unroll
            for (int c = 0; c < 4; c++) acc[i][j][c] = 0.f;

    const int NK = K / 32;

    auto load_tiles = [&](int kt, int buf) {
#pragma unroll
        for (int it = 0; it < 2; it++) {           // A: 128 rows x 32 halves
            int slot = tid + it * 256;             // 512 chunks of 16B
            int row  = slot >> 2;
            int seg  = slot & 3;
            uint32_t dst = as_base + buf * (HA_BUF * 2) + row * (HA_STR * 2) + seg * 16;
            cp_async16(dst, Ag + (size_t)row * K + kt * 32 + seg * 8);
        }
#pragma unroll
        for (int it = 0; it < 2; it++) {           // B: 16 k2-rows x 128 words
            int slot = tid + it * 256;
            int row  = slot >> 5;
            int seg  = slot & 31;
            uint32_t dst = bs_base + buf * (HB_BUF * 4) + row * (HB_STR * 4) + seg * 16;
            cp_async16(dst, Bg + (size_t)(kt * 16 + row) * N + seg * 4);
        }
        asm volatile("cp.async.commit_group;\n");
    };

    load_tiles(0, 0);

    for (int kt = 0; kt < NK; kt++) {
        int buf = kt & 1;
        if (kt + 1 < NK) {
            load_tiles(kt + 1, buf ^ 1);
            asm volatile("cp.async.wait_group 1;\n");
        } else {
            asm volatile("cp.async.wait_group 0;\n");
        }
        __syncthreads();

#pragma unroll
        for (int ks = 0; ks < 2; ks++) {           // two m16n8k16 k-steps
            uint32_t af[4][4];
#pragma unroll
            for (int mt = 0; mt < 4; mt++) {
                int m = wm * 64 + mt * 16;
                const __half* ar0 = &As[buf][(m + grp    ) * HA_STR + ks * 16 + 2 * tig];
                const __half* ar1 = &As[buf][(m + grp + 8) * HA_STR + ks * 16 + 2 * tig];
                af[mt][0] = *(const uint32_t*)ar0;
                af[mt][1] = *(const uint32_t*)ar1;
                af[mt][2] = *(const uint32_t*)(ar0 + 8);
                af[mt][3] = *(const uint32_t*)(ar1 + 8);
            }
            uint32_t bf[4][2];
#pragma unroll
            for (int nt = 0; nt < 4; nt++) {
                int n = wn * 32 + nt * 8;
                bf[nt][0] = Bs[buf][(ks * 8 + tig    ) * HB_STR + n + grp];
                bf[nt][1] = Bs[buf][(ks * 8 + tig + 4) * HB_STR + n + grp];
            }
#pragma unroll
            for (int mt = 0; mt < 4; mt++)
#pragma unroll
                for (int nt = 0; nt < 4; nt++)
                    mma_f16(acc[mt][nt], af[mt][0], af[mt][1], af[mt][2], af[mt][3],
                            bf[nt][0], bf[nt][1]);
        }
        __syncthreads();
    }

#pragma unroll
    for (int nt = 0; nt < 4; nt++) {
        int colg = bn * 128 + wn * 32 + nt * 8 + 2 * tig;
        float2 bv = {0.f, 0.f};
        if (bias) bv = *(const float2*)(bias + colg);
#pragma unroll
        for (int mt = 0; mt < 4; mt++) {
            int row0 = bm * 128 + wm * 64 + mt * 16 + grp;
            float2 lo = {acc[mt][nt][0] + bv.x, acc[mt][nt][1] + bv.y};
            float2 hi = {acc[mt][nt][2] + bv.x, acc[mt][nt][3] + bv.y};
            *(float2*)(C + (size_t)row0 * N + colg)       = lo;
            *(float2*)(C + (size_t)(row0 + 8) * N + colg) = hi;
        }
    }
}

// ---------------------------------------------------------------------------
// Tensor-core flash attention (tf32 mma + FMA exp) — unchanged except the
// ctx epilogue emits fp16 (feeds the out-proj fp16 GEMM).
// ---------------------------------------------------------------------------
#define AST 76
#define ATTN_TC_SMEM (3 * 64 * AST * 4)

__global__ void __launch_bounds__(128, 3) attn_tc_kernel(
    const float* __restrict__ qkv, __half* __restrict__ ctx, int L)
{
    extern __shared__ float sm[];
    float* qs = sm;
    float* ks = sm + 64 * AST;
    float* vs = sm + 2 * 64 * AST;
    float* ps = qs;

    int tid  = threadIdx.x;
    int lane = tid & 31;
    int w    = tid >> 5;
    int grp  = lane >> 2;
    int tig  = lane & 3;
    int qt = blockIdx.x, h = blockIdx.y;
    size_t seq_base = (size_t)blockIdx.z * L;
    int qbase = qt * 64;
    int m0 = w * 16;

#pragma unroll
    for (int it = 0; it < 16; it++) {
        int slot = it * 128 + tid;
        int row = slot >> 5, pr = slot & 31;
        int pos = qbase + row;
        const float* p = qkv + (seq_base + pos) * QKV3 + h * DH + 2 * pr;
        float2 qv = *(const float2*)p;
        float c = g_cos[pos * 32 + pr], sn = g_sin[pos * 32 + pr];
        float e0 = (qv.x * c - qv.y * sn) * 0.125f;
        float e1 = (qv.y * c + qv.x * sn) * 0.125f;
        *(float2*)&qs[row * AST + 2 * pr] = make_float2(tf32r(e0), tf32r(e1));
    }

    auto stage_kv = [&](int kt) {
#pragma unroll
        for (int it = 0; it < 16; it++) {
            int slot = it * 128 + tid;
            int row = slot >> 5, pr = slot & 31;
            int pos = kt * 64 + row;
            const float* p = qkv + (seq_base + pos) * QKV3 + INNER + h * DH + 2 * pr;
            float2 kv = *(const float2*)p;
            float c = g_cos[pos * 32 + pr], sn = g_sin[pos * 32 + pr];
            float e0 = kv.x * c - kv.y * sn;
            float e1 = kv.y * c + kv.x * sn;
            *(float2*)&ks[row * AST + 2 * pr] = make_float2(tf32r(e0), tf32r(e1));
        }
#pragma unroll
        for (int it = 0; it < 8; it++) {
            int slot = it * 128 + tid;
            int row = slot >> 4, c4 = (slot & 15) * 4;
            const float* p = qkv + (seq_base + kt * 64 + row) * QKV3 + 2 * INNER + h * DH + c4;
            float4 vv = *(const float4*)p;
            vv.x = tf32r(vv.x); vv.y = tf32r(vv.y);
            vv.z = tf32r(vv.z); vv.w = tf32r(vv.w);
            *(float4*)&vs[row * AST + c4] = vv;
        }
    };

    stage_kv(0);
    __syncthreads();

    uint32_t qa[8][4];
#pragma unroll
    for (int kk = 0; kk < 8; kk++) {
        int k = kk * 8;
        qa[kk][0] = __float_as_uint(qs[(m0 + grp    ) * AST + k + tig    ]);
        qa[kk][1] = __float_as_uint(qs[(m0 + grp + 8) * AST + k + tig    ]);
        qa[kk][2] = __float_as_uint(qs[(m0 + grp    ) * AST + k + tig + 4]);
        qa[kk][3] = __float_as_uint(qs[(m0 + grp + 8) * AST + k + tig + 4]);
    }

    float mrow[2] = {-1e30f, -1e30f};
    float lrow[2] = {0.f, 0.f};
    float oc[8][4];
#pragma unroll
    for (int nt = 0; nt < 8; nt++)
#pragma unroll
        for (int c = 0; c < 4; c++) oc[nt][c] = 0.f;

    int ntl = L >> 6;
    for (int kt = 0; kt < ntl; kt++) {
        if (kt > 0) {
            __syncthreads();
            stage_kv(kt);
            __syncthreads();
        }

        float sacc[8][4];
#pragma unroll
        for (int nt = 0; nt < 8; nt++)
#pragma unroll
            for (int c = 0; c < 4; c++) sacc[nt][c] = 0.f;
#pragma unroll
        for (int kk = 0; kk < 8; kk++) {
            int k = kk * 8;
#pragma unroll
            for (int nt = 0; nt < 8; nt++) {
                uint32_t b0 = __float_as_uint(ks[(nt * 8 + grp) * AST + k + tig    ]);
                uint32_t b1 = __float_as_uint(ks[(nt * 8 + grp) * AST + k + tig + 4]);
                mma_tf32(sacc[nt], qa[kk][0], qa[kk][1], qa[kk][2], qa[kk][3], b0, b1);
            }
        }

        float mx0 = -1e30f, mx1 = -1e30f;
#pragma unroll
        for (int nt = 0; nt < 8; nt++) {
            mx0 = fmaxf(mx0, fmaxf(sacc[nt][0], sacc[nt][1]));
            mx1 = fmaxf(mx1, fmaxf(sacc[nt][2], sacc[nt][3]));
        }
        mx0 = fmaxf(mx0, __shfl_xor_sync(0xffffffffu, mx0, 1));
        mx0 = fmaxf(mx0, __shfl_xor_sync(0xffffffffu, mx0, 2));
        mx1 = fmaxf(mx1, __shfl_xor_sync(0xffffffffu, mx1, 1));
        mx1 = fmaxf(mx1, __shfl_xor_sync(0xffffffffu, mx1, 2));
        float nm0 = fmaxf(mrow[0], mx0), nm1 = fmaxf(mrow[1], mx1);
        float al0 = fexp(mrow[0] - nm0),  al1 = fexp(mrow[1] - nm1);
        float s0 = 0.f, s1 = 0.f;
#pragma unroll
        for (int nt = 0; nt < 8; nt++) {
            float p0 = fexp(sacc[nt][0] - nm0);
            float p1 = fexp(sacc[nt][1] - nm0);
            float p2 = fexp(sacc[nt][2] - nm1);
            float p3 = fexp(sacc[nt][3] - nm1);
            s0 += p0 + p1;
            s1 += p2 + p3;
            *(float2*)&ps[(m0 + grp    ) * AST + nt * 8 + 2 * tig] =
                make_float2(tf32r(p0), tf32r(p1));
            *(float2*)&ps[(m0 + grp + 8) * AST + nt * 8 + 2 * tig] =
                make_float2(tf32r(p2), tf32r(p3));
        }
        s0 += __shfl_xor_sync(0xffffffffu, s0, 1);
        s0 += __shfl_xor_sync(0xffffffffu, s0, 2);
        s1 += __shfl_xor_sync(0xffffffffu, s1, 1);
        s1 += __shfl_xor_sync(0xffffffffu, s1, 2);
        lrow[0] = lrow[0] * al0 + s0;
        lrow[1] = lrow[1] * al1 + s1;
        mrow[0] = nm0; mrow[1] = nm1;
#pragma unroll
        for (int nt = 0; nt < 8; nt++) {
            oc[nt][0] *= al0; oc[nt][1] *= al0;
            oc[nt][2] *= al1; oc[nt][3] *= al1;
        }
        __syncwarp();

#pragma unroll
        for (int kk = 0; kk < 8; kk++) {
            int k = kk * 8;
            uint32_t pa0 = __float_as_uint(ps[(m0 + grp    ) * AST + k + tig    ]);
            uint32_t pa1 = __float_as_uint(ps[(m0 + grp + 8) * AST + k + tig    ]);
            uint32_t pa2 = __float_as_uint(ps[(m0 + grp    ) * AST + k + tig + 4]);
            uint32_t pa3 = __float_as_uint(ps[(m0 + grp + 8) * AST + k + tig + 4]);
#pragma unroll
            for (int nt = 0; nt < 8; nt++) {
                uint32_t vb0 = __float_as_uint(vs[(k + tig    ) * AST + nt * 8 + grp]);
                uint32_t vb1 = __float_as_uint(vs[(k + tig + 4) * AST + nt * 8 + grp]);
                mma_tf32(oc[nt], pa0, pa1, pa2, pa3, vb0, vb1);
            }
        }
        __syncwarp();
    }

    // epilogue: fp16 ctx (A operand of out-proj fp16 GEMM)
    float i0 = 1.0f / lrow[0], i1 = 1.0f / lrow[1];
    size_t tok0 = seq_base + qbase + m0 + grp;
#pragma unroll
    for (int nt = 0; nt < 8; nt++) {
        int col = h * DH + nt * 8 + 2 * tig;
        *(__half2*)&ctx[tok0 * INNER + col] =
            __floats2half2_rn(oc[nt][0] * i0, oc[nt][1] * i0);
        *(__half2*)&ctx[(tok0 + 8) * INNER + col] =
            __floats2half2_rn(oc[nt][2] * i1, oc[nt][3] * i1);
    }
}

// ---------------------------------------------------------------------------
// Host launch
// ---------------------------------------------------------------------------
extern "C" void kernel_launch(void* const* d_in, const int* in_sizes, int n_in,
                              void* d_out, int out_size)
{
    const float* x_in    = (const float*)d_in[0];
    const float* ln_s_g  = (const float*)d_in[1];
    const float* ln_s_b  = (const float*)d_in[2];
    const float* w_qkv_s = (const float*)d_in[3];
    const float* w_out_s = (const float*)d_in[4];
    const float* b_out_s = (const float*)d_in[5];
    const float* ln_t_g  = (const float*)d_in[6];
    const float* ln_t_b  = (const float*)d_in[7];
    const float* w_qkv_t = (const float*)d_in[8];
    const float* w_out_t = (const float*)d_in[9];
    const float* b_out_t = (const float*)d_in[10];
    const float* ln_f_g  = (const float*)d_in[11];
    const float* ln_f_b  = (const float*)d_in[12];
    float* x = (float*)d_out;

    cudaFuncSetAttribute(attn_tc_kernel, cudaFuncAttributeMaxDynamicSharedMemorySize,
                         ATTN_TC_SMEM);

    float *qkv_p, *xs_p, *xt_p;
    __half* ctx_p;
    uint32_t* wp_p;
    cudaGetSymbolAddress((void**)&qkv_p, g_qkv);
    cudaGetSymbolAddress((void**)&ctx_p, g_ctx);
    cudaGetSymbolAddress((void**)&xs_p,  g_xs);
    cudaGetSymbolAddress((void**)&xt_p,  g_xt);
    cudaGetSymbolAddress((void**)&wp_p,  g_wp);
    __half* ln_p = ctx_p;   // LN output aliases ctx (lifetimes disjoint)

    uint32_t* wp_qkv_s = wp_p;
    uint32_t* wp_out_s = wp_p + WQKV_SZ / 2;
    uint32_t* wp_qkv_t = wp_p + (WQKV_SZ + WOUT_SZ) / 2;
    uint32_t* wp_out_t = wp_p + WQKV_SZ + WOUT_SZ / 2;

    cudaMemcpyAsync(x, x_in, (size_t)NTOK * DD * sizeof(float),
                    cudaMemcpyDeviceToDevice);
    rope_table_kernel<<<(256 * 32 + 255) / 256, 256>>>();

    // pack all weights into fp16 k-pair words, once per launch
    {
        int nq = (DD / 2) * QKV3;      // per-layer packed words (QKV)
        int no = (INNER / 2) * DD;     // per-layer packed words (out-proj)
        pack_half_kernel<<<dim3((nq + 255) / 256, DEPTH), 256>>>(w_qkv_s, wp_qkv_s, DD / 2, QKV3);
        pack_half_kernel<<<dim3((no + 255) / 256, DEPTH), 256>>>(w_out_s, wp_out_s, INNER / 2, DD);
        pack_half_kernel<<<dim3((nq + 255) / 256, DEPTH), 256>>>(w_qkv_t, wp_qkv_t, DD / 2, QKV3);
        pack_half_kernel<<<dim3((no + 255) / 256, DEPTH), 256>>>(w_out_t, wp_out_t, INNER / 2, DD);
    }

    dim3 ln_grid(NTOK / 8);
    dim3 gemm_qkv_grid(NTOK / 128, QKV3 / 128);
    dim3 gemm_out_grid(NTOK / 128, DD / 128);
    dim3 attn_s_grid(PP / 64, HH, BB * TT);
    dim3 attn_t_grid(TT / 64, HH, BB * PP);

    for (int i = 0; i < DEPTH; i++) {
        const uint32_t* wq_s = wp_qkv_s + (size_t)i * (DD / 2) * QKV3;
        const uint32_t* wo_s = wp_out_s + (size_t)i * (INNER / 2) * DD;
        const uint32_t* wq_t = wp_qkv_t + (size_t)i * (DD / 2) * QKV3;
        const uint32_t* wo_t = wp_out_t + (size_t)i * (INNER / 2) * DD;

        // ---- spatial branch ----
        ln_kernel<<<ln_grid, 256>>>(x, ln_s_g + i * DD, ln_s_b + i * DD, ln_p);
        hgemm_kernel<<<gemm_qkv_grid, 256>>>(ln_p, wq_s, nullptr, qkv_p,
                                             NTOK, QKV3, DD);
        attn_tc_kernel<<<attn_s_grid, 128, ATTN_TC_SMEM>>>(qkv_p, ctx_p, PP);
        hgemm_kernel<<<gemm_out_grid, 256>>>(ctx_p, wo_s, b_out_s + i * DD, xs_p,
                                             NTOK, DD, INNER);

        // ---- temporal branch ----
        ln_add_transpose_kernel<<<ln_grid, 256>>>(x, xs_p, ln_t_g + i * DD,
                                                  ln_t_b + i * DD, ln_p);
        hgemm_kernel<<<gemm_qkv_grid, 256>>>(ln_p, wq_t, nullptr, qkv_p,
                                             NTOK, QKV3, DD);
        attn_tc_kernel<<<attn_t_grid, 128, ATTN_TC_SMEM>>>(qkv_p, ctx_p, TT);
        hgemm_kernel<<<gemm_out_grid, 256>>>(ctx_p, wo_t, b_out_t + i * DD, xt_p,
                                             NTOK, DD, INNER);

        // ---- finish ----
        ln_final_kernel<<<ln_grid, 256>>>(xs_p, xt_p, ln_f_g + i * DD,
                                          ln_f_b + i * DD, x);
    }
}

// round 11
// speedup vs baseline: 4.5206x; 1.0923x over previous
#include <cuda_runtime.h>
#include <cuda_bf16.h>
#include <cuda_fp16.h>
#include <math.h>
#include <stdint.h>

// ---------------------------------------------------------------------------
// Problem constants
// ---------------------------------------------------------------------------
#define BB    2
#define TT    64
#define PP    256
#define DD    512
#define HH    8
#define DH    64
#define INNER 512          // HH*DH
#define QKV3  1536         // 3*INNER
#define NTOK  32768        // BB*TT*PP
#define DEPTH 4
#define LN_EPS 1e-5f

#define WQKV_SZ (DEPTH * DD * QKV3)
#define WOUT_SZ (DEPTH * INNER * DD)

// ---------------------------------------------------------------------------
// Static device scratch
// g_ctx (fp16) doubles as the LN-output buffer (lifetimes disjoint).
// ---------------------------------------------------------------------------
__device__ float    g_qkv[(size_t)NTOK * QKV3];
__device__ __half   g_ctx[(size_t)NTOK * INNER];
__device__ float    g_xs [(size_t)NTOK * DD];
__device__ float    g_xt [(size_t)NTOK * DD];
__device__ uint32_t g_wp [WQKV_SZ + WOUT_SZ];   // k-pair-packed fp16 weights
__device__ float    g_cos[256 * 32];
__device__ float    g_sin[256 * 32];

// ---------------------------------------------------------------------------
// RoPE table
// ---------------------------------------------------------------------------
__global__ void rope_table_kernel() {
    int i = blockIdx.x * blockDim.x + threadIdx.x;
    if (i >= 256 * 32) return;
    int pos = i >> 5;
    int j   = i & 31;
    float freq  = powf(10000.0f, -(float)(2 * j) / 64.0f);
    float theta = (float)pos * freq;
    float s, c;
    sincosf(theta, &s, &c);
    g_cos[i] = c;
    g_sin[i] = s;
}

// ---------------------------------------------------------------------------
// Fast exp on the FMA pipe
// ---------------------------------------------------------------------------
__device__ __forceinline__ float fexp(float x) {
    x = fmaxf(x, -80.0f);
    float y = x * 1.44269504088896340736f;
    float t = y + 12582912.0f;
    int   n = __float_as_int(t) - 0x4B400000;
    float f = y - (t - 12582912.0f);
    float p =             1.54035303933e-4f;
    p = fmaf(p, f, 1.33335581464e-3f);
    p = fmaf(p, f, 9.61812910763e-3f);
    p = fmaf(p, f, 5.55041086648e-2f);
    p = fmaf(p, f, 2.40226506959e-1f);
    p = fmaf(p, f, 6.93147180560e-1f);
    p = fmaf(p, f, 1.0f);
    return p * __int_as_float((n + 127) << 23);
}

__device__ __forceinline__ void mma_f16(float c[4],
                                        uint32_t a0, uint32_t a1, uint32_t a2, uint32_t a3,
                                        uint32_t b0, uint32_t b1)
{
    asm volatile(
        "mma.sync.aligned.m16n8k16.row.col.f32.f16.f16.f32 "
        "{%0,%1,%2,%3}, {%4,%5,%6,%7}, {%8,%9}, {%0,%1,%2,%3};"
        : "+f"(c[0]), "+f"(c[1]), "+f"(c[2]), "+f"(c[3])
        : "r"(a0), "r"(a1), "r"(a2), "r"(a3), "r"(b0), "r"(b1));
}

__device__ __forceinline__ void cp_async16(uint32_t dst, const void* src) {
    asm volatile("cp.async.cg.shared.global [%0], [%1], 16;\n" :: "r"(dst), "l"(src));
}

// ---------------------------------------------------------------------------
// Weight prep: dst word (k2, n) = half2(W[2k2][n], W[2k2+1][n])   per layer z
// ---------------------------------------------------------------------------
__global__ void pack_half_kernel(const float* __restrict__ src,
                                 uint32_t* __restrict__ dst, int K2, int N)
{
    int i = blockIdx.x * blockDim.x + threadIdx.x;
    if (i >= K2 * N) return;
    int z = blockIdx.y;
    const float* s = src + (size_t)z * 2 * K2 * N;
    int k2 = i / N, n = i - k2 * N;
    __half2 h = __floats2half2_rn(s[(size_t)(2 * k2) * N + n],
                                  s[(size_t)(2 * k2 + 1) * N + n]);
    dst[(size_t)z * K2 * N + i] = *(uint32_t*)&h;
}

// ---------------------------------------------------------------------------
// Warp-per-row LayerNorm over D=512
// ---------------------------------------------------------------------------
__device__ __forceinline__ void warp_ln_core(
    const float4 v[4], int lane,
    const float* __restrict__ g, const float* __restrict__ b,
    float4 o[4])
{
    float s = 0.f, s2 = 0.f;
#pragma unroll
    for (int i = 0; i < 4; i++) {
        s  += v[i].x + v[i].y + v[i].z + v[i].w;
        s2 += v[i].x * v[i].x + v[i].y * v[i].y + v[i].z * v[i].z + v[i].w * v[i].w;
    }
#pragma unroll
    for (int o_ = 16; o_ > 0; o_ >>= 1) {
        s  += __shfl_xor_sync(0xffffffffu, s,  o_);
        s2 += __shfl_xor_sync(0xffffffffu, s2, o_);
    }
    float mu   = s * (1.0f / 512.0f);
    float var  = s2 * (1.0f / 512.0f) - mu * mu;
    float rstd = rsqrtf(var + LN_EPS);
#pragma unroll
    for (int i = 0; i < 4; i++) {
        int c = (lane + 32 * i) * 4;
        float4 gg = *(const float4*)(g + c);
        float4 bb = *(const float4*)(b + c);
        o[i].x = (v[i].x - mu) * rstd * gg.x + bb.x;
        o[i].y = (v[i].y - mu) * rstd * gg.y + bb.y;
        o[i].z = (v[i].z - mu) * rstd * gg.z + bb.z;
        o[i].w = (v[i].w - mu) * rstd * gg.w + bb.w;
    }
}

__device__ __forceinline__ void store_half4(__half* p, float4 o) {
    __half2 ha = __floats2half2_rn(o.x, o.y);
    __half2 hb = __floats2half2_rn(o.z, o.w);
    uint2 pk = make_uint2(*(uint32_t*)&ha, *(uint32_t*)&hb);
    *(uint2*)p = pk;
}

// out = fp16(LN(x)) — feeds QKV GEMM only
__global__ void ln_kernel(const float* __restrict__ x,
                          const float* __restrict__ g, const float* __restrict__ b,
                          __half* __restrict__ out)
{
    int row  = blockIdx.x * 8 + (threadIdx.x >> 5);
    int lane = threadIdx.x & 31;
    const float* xr = x + (size_t)row * DD;
    float4 v[4];
#pragma unroll
    for (int i = 0; i < 4; i++) v[i] = *(const float4*)(xr + (lane + 32 * i) * 4);
    float4 o[4];
    warp_ln_core(v, lane, g, b, o);
    __half* orow = out + (size_t)row * DD;
#pragma unroll
    for (int i = 0; i < 4; i++) store_half4(orow + (lane + 32 * i) * 4, o[i]);
}

// out = fp16(LN(x[src] + xs[src])) in (b,p,t) order — feeds QKV GEMM only
__global__ void ln_add_transpose_kernel(const float* __restrict__ x,
                                        const float* __restrict__ xs,
                                        const float* __restrict__ g, const float* __restrict__ b,
                                        __half* __restrict__ out)
{
    int row  = blockIdx.x * 8 + (threadIdx.x >> 5);
    int lane = threadIdx.x & 31;
    int t_ = row & 63;
    int p_ = (row >> 6) & 255;
    int b_ = row >> 14;
    int src = (b_ * TT + t_) * PP + p_;
    const float* xr  = x  + (size_t)src * DD;
    const float* xsr = xs + (size_t)src * DD;
    float4 v[4];
#pragma unroll
    for (int i = 0; i < 4; i++) {
        float4 a = *(const float4*)(xr  + (lane + 32 * i) * 4);
        float4 c = *(const float4*)(xsr + (lane + 32 * i) * 4);
        v[i].x = a.x + c.x; v[i].y = a.y + c.y; v[i].z = a.z + c.z; v[i].w = a.w + c.w;
    }
    float4 o[4];
    warp_ln_core(v, lane, g, b, o);
    __half* orow = out + (size_t)row * DD;
#pragma unroll
    for (int i = 0; i < 4; i++) store_half4(orow + (lane + 32 * i) * 4, o[i]);
}

// x = LN(xs + xt[perm]) + x  (full fp32 — residual/output path)
__global__ void ln_final_kernel(const float* __restrict__ xs,
                                const float* __restrict__ xt,
                                const float* __restrict__ g, const float* __restrict__ b,
                                float* __restrict__ x)
{
    int row  = blockIdx.x * 8 + (threadIdx.x >> 5);
    int lane = threadIdx.x & 31;
    int p_ = row & 255;
    int t_ = (row >> 8) & 63;
    int b_ = row >> 14;
    int xtr = (b_ * PP + p_) * TT + t_;
    const float* xsr = xs + (size_t)row * DD;
    const float* xtr_p = xt + (size_t)xtr * DD;
    float* xr = x + (size_t)row * DD;
    float4 v[4], xv[4];
#pragma unroll
    for (int i = 0; i < 4; i++) {
        float4 a = *(const float4*)(xsr + (lane + 32 * i) * 4);
        float4 c = *(const float4*)(xtr_p + (lane + 32 * i) * 4);
        v[i].x = a.x + c.x; v[i].y = a.y + c.y; v[i].z = a.z + c.z; v[i].w = a.w + c.w;
        xv[i] = *(const float4*)(xr + (lane + 32 * i) * 4);
    }
    float4 o[4];
    warp_ln_core(v, lane, g, b, o);
#pragma unroll
    for (int i = 0; i < 4; i++) {
        o[i].x += xv[i].x; o[i].y += xv[i].y; o[i].z += xv[i].z; o[i].w += xv[i].w;
        *(float4*)(xr + (lane + 32 * i) * 4) = o[i];
    }
}

// ---------------------------------------------------------------------------
// fp16 tensor-core GEMM (unchanged from passing Round 10)
// ---------------------------------------------------------------------------
#define HA_STR 40
#define HB_STR 136
#define HA_BUF (128 * HA_STR)
#define HB_BUF (16 * HB_STR)

__global__ void __launch_bounds__(256) hgemm_kernel(
    const __half* __restrict__ A, const uint32_t* __restrict__ Bp,
    const float* __restrict__ bias, float* __restrict__ C,
    int M, int N, int K)
{
    __shared__ __half   As[2][HA_BUF];
    __shared__ uint32_t Bs[2][HB_BUF];

    int tid  = threadIdx.x;
    int lane = tid & 31;
    int wid  = tid >> 5;
    int wm   = wid >> 2;
    int wn   = wid & 3;
    int grp  = lane >> 2;
    int tig  = lane & 3;
    int bm = blockIdx.x, bn = blockIdx.y;

    const __half*   Ag = A  + (size_t)bm * 128 * K;
    const uint32_t* Bg = Bp + bn * 128;

    uint32_t as_base = (uint32_t)__cvta_generic_to_shared(&As[0][0]);
    uint32_t bs_base = (uint32_t)__cvta_generic_to_shared(&Bs[0][0]);

    float acc[4][4][4];
#pragma unroll
    for (int i = 0; i < 4; i++)
#pragma unroll
        for (int j = 0; j < 4; j++)
#pragma unroll
            for (int c = 0; c < 4; c++) acc[i][j][c] = 0.f;

    const int NK = K / 32;

    auto load_tiles = [&](int kt, int buf) {
#pragma unroll
        for (int it = 0; it < 2; it++) {
            int slot = tid + it * 256;
            int row  = slot >> 2;
            int seg  = slot & 3;
            uint32_t dst = as_base + buf * (HA_BUF * 2) + row * (HA_STR * 2) + seg * 16;
            cp_async16(dst, Ag + (size_t)row * K + kt * 32 + seg * 8);
        }
#pragma unroll
        for (int it = 0; it < 2; it++) {
            int slot = tid + it * 256;
            int row  = slot >> 5;
            int seg  = slot & 31;
            uint32_t dst = bs_base + buf * (HB_BUF * 4) + row * (HB_STR * 4) + seg * 16;
            cp_async16(dst, Bg + (size_t)(kt * 16 + row) * N + seg * 4);
        }
        asm volatile("cp.async.commit_group;\n");
    };

    load_tiles(0, 0);

    for (int kt = 0; kt < NK; kt++) {
        int buf = kt & 1;
        if (kt + 1 < NK) {
            load_tiles(kt + 1, buf ^ 1);
            asm volatile("cp.async.wait_group 1;\n");
        } else {
            asm volatile("cp.async.wait_group 0;\n");
        }
        __syncthreads();

#pragma unroll
        for (int ks = 0; ks < 2; ks++) {
            uint32_t af[4][4];
#pragma unroll
            for (int mt = 0; mt < 4; mt++) {
                int m = wm * 64 + mt * 16;
                const __half* ar0 = &As[buf][(m + grp    ) * HA_STR + ks * 16 + 2 * tig];
                const __half* ar1 = &As[buf][(m + grp + 8) * HA_STR + ks * 16 + 2 * tig];
                af[mt][0] = *(const uint32_t*)ar0;
                af[mt][1] = *(const uint32_t*)ar1;
                af[mt][2] = *(const uint32_t*)(ar0 + 8);
                af[mt][3] = *(const uint32_t*)(ar1 + 8);
            }
            uint32_t bf[4][2];
#pragma unroll
            for (int nt = 0; nt < 4; nt++) {
                int n = wn * 32 + nt * 8;
                bf[nt][0] = Bs[buf][(ks * 8 + tig    ) * HB_STR + n + grp];
                bf[nt][1] = Bs[buf][(ks * 8 + tig + 4) * HB_STR + n + grp];
            }
#pragma unroll
            for (int mt = 0; mt < 4; mt++)
#pragma unroll
                for (int nt = 0; nt < 4; nt++)
                    mma_f16(acc[mt][nt], af[mt][0], af[mt][1], af[mt][2], af[mt][3],
                            bf[nt][0], bf[nt][1]);
        }
        __syncthreads();
    }

#pragma unroll
    for (int nt = 0; nt < 4; nt++) {
        int colg = bn * 128 + wn * 32 + nt * 8 + 2 * tig;
        float2 bv = {0.f, 0.f};
        if (bias) bv = *(const float2*)(bias + colg);
#pragma unroll
        for (int mt = 0; mt < 4; mt++) {
            int row0 = bm * 128 + wm * 64 + mt * 16 + grp;
            float2 lo = {acc[mt][nt][0] + bv.x, acc[mt][nt][1] + bv.y};
            float2 hi = {acc[mt][nt][2] + bv.x, acc[mt][nt][3] + bv.y};
            *(float2*)(C + (size_t)row0 * N + colg)       = lo;
            *(float2*)(C + (size_t)(row0 + 8) * N + colg) = hi;
        }
    }
}

// ---------------------------------------------------------------------------
// fp16 tensor-core flash attention (mma.m16n8k16 + FMA exp).
// Block = 128 threads (4 warps); warp w owns q-rows [w*16, w*16+16).
// Tiles (stride 72 halves = 36 words; frag bank sets 4*grp+tig are full
// permutations -> conflict-free): qs[q][k] (reused as ps[q][pos]),
// ks[key][k], vsT[d][pos] (V transposed so P@V B-frags get pos-pairs).
// ---------------------------------------------------------------------------
#define ASTH 72                 // halves per tile row
#define ATW  36                 // words per tile row

__global__ void __launch_bounds__(128, 4) attn_tc_kernel(
    const float* __restrict__ qkv, __half* __restrict__ ctx, int L)
{
    __shared__ __half qs [64 * ASTH];
    __shared__ __half ks [64 * ASTH];
    __shared__ __half vsT[64 * ASTH];
    __half* ps = qs;

    int tid  = threadIdx.x;
    int lane = tid & 31;
    int w    = tid >> 5;
    int grp  = lane >> 2;
    int tig  = lane & 3;
    int qt = blockIdx.x, h = blockIdx.y;
    size_t seq_base = (size_t)blockIdx.z * L;
    int qbase = qt * 64;
    int m0 = w * 16;

    // ---- stage Q (rotary + scale -> fp16) ----
#pragma unroll
    for (int it = 0; it < 16; it++) {
        int slot = it * 128 + tid;            // 2048 rotary pairs
        int row = slot >> 5, pr = slot & 31;
        int pos = qbase + row;
        const float* p = qkv + (seq_base + pos) * QKV3 + h * DH + 2 * pr;
        float2 qv = *(const float2*)p;
        float c = g_cos[pos * 32 + pr], sn = g_sin[pos * 32 + pr];
        float e0 = (qv.x * c - qv.y * sn) * 0.125f;
        float e1 = (qv.y * c + qv.x * sn) * 0.125f;
        *(__half2*)&qs[row * ASTH + 2 * pr] = __floats2half2_rn(e0, e1);
    }

    // ---- KV staging: K rotary->fp16, V transposed fp16 ----
    auto stage_kv = [&](int kt) {
#pragma unroll
        for (int it = 0; it < 16; it++) {
            int slot = it * 128 + tid;
            int row = slot >> 5, pr = slot & 31;
            int pos = kt * 64 + row;
            const float* p = qkv + (seq_base + pos) * QKV3 + INNER + h * DH + 2 * pr;
            float2 kv = *(const float2*)p;
            float c = g_cos[pos * 32 + pr], sn = g_sin[pos * 32 + pr];
            float e0 = kv.x * c - kv.y * sn;
            float e1 = kv.y * c + kv.x * sn;
            *(__half2*)&ks[row * ASTH + 2 * pr] = __floats2half2_rn(e0, e1);
        }
        // V: vsT[d][pos-pair] = (V[pos][d], V[pos+1][d])
#pragma unroll
        for (int it = 0; it < 16; it++) {
            int slot = it * 128 + tid;            // 2048 (d, pos-pair) cells
            int d  = slot & 63;
            int pp = slot >> 6;                   // 0..31
            const float* p = qkv + (seq_base + kt * 64 + 2 * pp) * QKV3
                           + 2 * INNER + h * DH + d;
            float v0 = p[0];
            float v1 = p[QKV3];
            *(__half2*)&vsT[d * ASTH + 2 * pp] = __floats2half2_rn(v0, v1);
        }
    };

    stage_kv(0);
    __syncthreads();

    // ---- preload Q fragments (own warp's 16 rows), fp16 k16 ----
    uint32_t qa[4][4];
#pragma unroll
    for (int kk = 0; kk < 4; kk++) {
        const uint32_t* r0 = (const uint32_t*)&qs[(m0 + grp    ) * ASTH + kk * 16 + 2 * tig];
        const uint32_t* r1 = (const uint32_t*)&qs[(m0 + grp + 8) * ASTH + kk * 16 + 2 * tig];
        qa[kk][0] = r0[0];
        qa[kk][1] = r1[0];
        qa[kk][2] = r0[4];
        qa[kk][3] = r1[4];
    }

    float mrow[2] = {-1e30f, -1e30f};
    float lrow[2] = {0.f, 0.f};
    float oc[8][4];
#pragma unroll
    for (int nt = 0; nt < 8; nt++)
#pragma unroll
        for (int c = 0; c < 4; c++) oc[nt][c] = 0.f;

    int ntl = L >> 6;
    for (int kt = 0; kt < ntl; kt++) {
        if (kt > 0) {
            __syncthreads();          // all warps done with previous ks/vsT
            stage_kv(kt);
            __syncthreads();
        }

        // ---- S = Q @ K^T (fp16 k16) ----
        float sacc[8][4];
#pragma unroll
        for (int nt = 0; nt < 8; nt++)
#pragma unroll
            for (int c = 0; c < 4; c++) sacc[nt][c] = 0.f;
#pragma unroll
        for (int kk = 0; kk < 4; kk++) {
#pragma unroll
            for (int nt = 0; nt < 8; nt++) {
                const uint32_t* kr = (const uint32_t*)&ks[(nt * 8 + grp) * ASTH + kk * 16 + 2 * tig];
                mma_f16(sacc[nt], qa[kk][0], qa[kk][1], qa[kk][2], qa[kk][3],
                        kr[0], kr[4]);
            }
        }

        // ---- online softmax (rows m0+grp, m0+grp+8) ----
        float mx0 = -1e30f, mx1 = -1e30f;
#pragma unroll
        for (int nt = 0; nt < 8; nt++) {
            mx0 = fmaxf(mx0, fmaxf(sacc[nt][0], sacc[nt][1]));
            mx1 = fmaxf(mx1, fmaxf(sacc[nt][2], sacc[nt][3]));
        }
        mx0 = fmaxf(mx0, __shfl_xor_sync(0xffffffffu, mx0, 1));
        mx0 = fmaxf(mx0, __shfl_xor_sync(0xffffffffu, mx0, 2));
        mx1 = fmaxf(mx1, __shfl_xor_sync(0xffffffffu, mx1, 1));
        mx1 = fmaxf(mx1, __shfl_xor_sync(0xffffffffu, mx1, 2));
        float nm0 = fmaxf(mrow[0], mx0), nm1 = fmaxf(mrow[1], mx1);
        float al0 = fexp(mrow[0] - nm0),  al1 = fexp(mrow[1] - nm1);
        float s0 = 0.f, s1 = 0.f;
#pragma unroll
        for (int nt = 0; nt < 8; nt++) {
            float p0 = fexp(sacc[nt][0] - nm0);
            float p1 = fexp(sacc[nt][1] - nm0);
            float p2 = fexp(sacc[nt][2] - nm1);
            float p3 = fexp(sacc[nt][3] - nm1);
            s0 += p0 + p1;
            s1 += p2 + p3;
            *(__half2*)&ps[(m0 + grp    ) * ASTH + nt * 8 + 2 * tig] =
                __floats2half2_rn(p0, p1);
            *(__half2*)&ps[(m0 + grp + 8) * ASTH + nt * 8 + 2 * tig] =
                __floats2half2_rn(p2, p3);
        }
        s0 += __shfl_xor_sync(0xffffffffu, s0, 1);
        s0 += __shfl_xor_sync(0xffffffffu, s0, 2);
        s1 += __shfl_xor_sync(0xffffffffu, s1, 1);
        s1 += __shfl_xor_sync(0xffffffffu, s1, 2);
        lrow[0] = lrow[0] * al0 + s0;
        lrow[1] = lrow[1] * al1 + s1;
        mrow[0] = nm0; mrow[1] = nm1;
#pragma unroll
        for (int nt = 0; nt < 8; nt++) {
            oc[nt][0] *= al0; oc[nt][1] *= al0;
            oc[nt][2] *= al1; oc[nt][3] *= al1;
        }
        __syncwarp();

        // ---- O += P @ V (fp16 k16; B from vsT[d][pos]) ----
#pragma unroll
        for (int kk = 0; kk < 4; kk++) {
            const uint32_t* p0 = (const uint32_t*)&ps[(m0 + grp    ) * ASTH + kk * 16 + 2 * tig];
            const uint32_t* p1 = (const uint32_t*)&ps[(m0 + grp + 8) * ASTH + kk * 16 + 2 * tig];
            uint32_t pa0 = p0[0], pa1 = p1[0], pa2 = p0[4], pa3 = p1[4];
#pragma unroll
            for (int nt = 0; nt < 8; nt++) {
                const uint32_t* vr = (const uint32_t*)&vsT[(nt * 8 + grp) * ASTH + kk * 16 + 2 * tig];
                mma_f16(oc[nt], pa0, pa1, pa2, pa3, vr[0], vr[4]);
            }
        }
        __syncwarp();   // ps reads done before next tile's softmax overwrites
    }

    // ---- epilogue: fp16 ctx ----
    float i0 = 1.0f / lrow[0], i1 = 1.0f / lrow[1];
    size_t tok0 = seq_base + qbase + m0 + grp;
#pragma unroll
    for (int nt = 0; nt < 8; nt++) {
        int col = h * DH + nt * 8 + 2 * tig;
        *(__half2*)&ctx[tok0 * INNER + col] =
            __floats2half2_rn(oc[nt][0] * i0, oc[nt][1] * i0);
        *(__half2*)&ctx[(tok0 + 8) * INNER + col] =
            __floats2half2_rn(oc[nt][2] * i1, oc[nt][3] * i1);
    }
}

// ---------------------------------------------------------------------------
// Host launch
// ---------------------------------------------------------------------------
extern "C" void kernel_launch(void* const* d_in, const int* in_sizes, int n_in,
                              void* d_out, int out_size)
{
    const float* x_in    = (const float*)d_in[0];
    const float* ln_s_g  = (const float*)d_in[1];
    const float* ln_s_b  = (const float*)d_in[2];
    const float* w_qkv_s = (const float*)d_in[3];
    const float* w_out_s = (const float*)d_in[4];
    const float* b_out_s = (const float*)d_in[5];
    const float* ln_t_g  = (const float*)d_in[6];
    const float* ln_t_b  = (const float*)d_in[7];
    const float* w_qkv_t = (const float*)d_in[8];
    const float* w_out_t = (const float*)d_in[9];
    const float* b_out_t = (const float*)d_in[10];
    const float* ln_f_g  = (const float*)d_in[11];
    const float* ln_f_b  = (const float*)d_in[12];
    float* x = (float*)d_out;

    float *qkv_p, *xs_p, *xt_p;
    __half* ctx_p;
    uint32_t* wp_p;
    cudaGetSymbolAddress((void**)&qkv_p, g_qkv);
    cudaGetSymbolAddress((void**)&ctx_p, g_ctx);
    cudaGetSymbolAddress((void**)&xs_p,  g_xs);
    cudaGetSymbolAddress((void**)&xt_p,  g_xt);
    cudaGetSymbolAddress((void**)&wp_p,  g_wp);
    __half* ln_p = ctx_p;   // LN output aliases ctx (lifetimes disjoint)

    uint32_t* wp_qkv_s = wp_p;
    uint32_t* wp_out_s = wp_p + WQKV_SZ / 2;
    uint32_t* wp_qkv_t = wp_p + (WQKV_SZ + WOUT_SZ) / 2;
    uint32_t* wp_out_t = wp_p + WQKV_SZ + WOUT_SZ / 2;

    cudaMemcpyAsync(x, x_in, (size_t)NTOK * DD * sizeof(float),
                    cudaMemcpyDeviceToDevice);
    rope_table_kernel<<<(256 * 32 + 255) / 256, 256>>>();

    // pack all weights into fp16 k-pair words, once per launch
    {
        int nq = (DD / 2) * QKV3;
        int no = (INNER / 2) * DD;
        pack_half_kernel<<<dim3((nq + 255) / 256, DEPTH), 256>>>(w_qkv_s, wp_qkv_s, DD / 2, QKV3);
        pack_half_kernel<<<dim3((no + 255) / 256, DEPTH), 256>>>(w_out_s, wp_out_s, INNER / 2, DD);
        pack_half_kernel<<<dim3((nq + 255) / 256, DEPTH), 256>>>(w_qkv_t, wp_qkv_t, DD / 2, QKV3);
        pack_half_kernel<<<dim3((no + 255) / 256, DEPTH), 256>>>(w_out_t, wp_out_t, INNER / 2, DD);
    }

    dim3 ln_grid(NTOK / 8);
    dim3 gemm_qkv_grid(NTOK / 128, QKV3 / 128);
    dim3 gemm_out_grid(NTOK / 128, DD / 128);
    dim3 attn_s_grid(PP / 64, HH, BB * TT);
    dim3 attn_t_grid(TT / 64, HH, BB * PP);

    for (int i = 0; i < DEPTH; i++) {
        const uint32_t* wq_s = wp_qkv_s + (size_t)i * (DD / 2) * QKV3;
        const uint32_t* wo_s = wp_out_s + (size_t)i * (INNER / 2) * DD;
        const uint32_t* wq_t = wp_qkv_t + (size_t)i * (DD / 2) * QKV3;
        const uint32_t* wo_t = wp_out_t + (size_t)i * (INNER / 2) * DD;

        // ---- spatial branch ----
        ln_kernel<<<ln_grid, 256>>>(x, ln_s_g + i * DD, ln_s_b + i * DD, ln_p);
        hgemm_kernel<<<gemm_qkv_grid, 256>>>(ln_p, wq_s, nullptr, qkv_p,
                                             NTOK, QKV3, DD);
        attn_tc_kernel<<<attn_s_grid, 128>>>(qkv_p, ctx_p, PP);
        hgemm_kernel<<<gemm_out_grid, 256>>>(ctx_p, wo_s, b_out_s + i * DD, xs_p,
                                             NTOK, DD, INNER);

        // ---- temporal branch ----
        ln_add_transpose_kernel<<<ln_grid, 256>>>(x, xs_p, ln_t_g + i * DD,
                                                  ln_t_b + i * DD, ln_p);
        hgemm_kernel<<<gemm_qkv_grid, 256>>>(ln_p, wq_t, nullptr, qkv_p,
                                             NTOK, QKV3, DD);
        attn_tc_kernel<<<attn_t_grid, 128>>>(qkv_p, ctx_p, TT);
        hgemm_kernel<<<gemm_out_grid, 256>>>(ctx_p, wo_t, b_out_t + i * DD, xt_p,
                                             NTOK, DD, INNER);

        // ---- finish ----
        ln_final_kernel<<<ln_grid, 256>>>(xs_p, xt_p, ln_f_g + i * DD,
                                          ln_f_b + i * DD, x);
    }
}

// round 12
// speedup vs baseline: 4.6248x; 1.0230x over previous
#include <cuda_runtime.h>
#include <cuda_bf16.h>
#include <cuda_fp16.h>
#include <math.h>
#include <stdint.h>

// ---------------------------------------------------------------------------
// Problem constants
// ---------------------------------------------------------------------------
#define BB    2
#define TT    64
#define PP    256
#define DD    512
#define HH    8
#define DH    64
#define INNER 512          // HH*DH
#define QKV3  1536         // 3*INNER
#define NTOK  32768        // BB*TT*PP
#define DEPTH 4
#define LN_EPS 1e-5f

#define WQKV_SZ (DEPTH * DD * QKV3)
#define WOUT_SZ (DEPTH * INNER * DD)

// ---------------------------------------------------------------------------
// Static device scratch
// g_ctx (fp16) doubles as the LN-output buffer (lifetimes disjoint).
// g_qkv is now fp16 (halves GEMM-write + attention-read traffic).
// ---------------------------------------------------------------------------
__device__ __half   g_qkv[(size_t)NTOK * QKV3];
__device__ __half   g_ctx[(size_t)NTOK * INNER];
__device__ float    g_xs [(size_t)NTOK * DD];
__device__ float    g_xt [(size_t)NTOK * DD];
__device__ uint32_t g_wp [WQKV_SZ + WOUT_SZ];   // k-pair-packed fp16 weights
__device__ float    g_cos[256 * 32];
__device__ float    g_sin[256 * 32];

// ---------------------------------------------------------------------------
// RoPE table
// ---------------------------------------------------------------------------
__global__ void rope_table_kernel() {
    int i = blockIdx.x * blockDim.x + threadIdx.x;
    if (i >= 256 * 32) return;
    int pos = i >> 5;
    int j   = i & 31;
    float freq  = powf(10000.0f, -(float)(2 * j) / 64.0f);
    float theta = (float)pos * freq;
    float s, c;
    sincosf(theta, &s, &c);
    g_cos[i] = c;
    g_sin[i] = s;
}

// ---------------------------------------------------------------------------
// Fast exp on the FMA pipe
// ---------------------------------------------------------------------------
__device__ __forceinline__ float fexp(float x) {
    x = fmaxf(x, -80.0f);
    float y = x * 1.44269504088896340736f;
    float t = y + 12582912.0f;
    int   n = __float_as_int(t) - 0x4B400000;
    float f = y - (t - 12582912.0f);
    float p =             1.54035303933e-4f;
    p = fmaf(p, f, 1.33335581464e-3f);
    p = fmaf(p, f, 9.61812910763e-3f);
    p = fmaf(p, f, 5.55041086648e-2f);
    p = fmaf(p, f, 2.40226506959e-1f);
    p = fmaf(p, f, 6.93147180560e-1f);
    p = fmaf(p, f, 1.0f);
    return p * __int_as_float((n + 127) << 23);
}

__device__ __forceinline__ void mma_f16(float c[4],
                                        uint32_t a0, uint32_t a1, uint32_t a2, uint32_t a3,
                                        uint32_t b0, uint32_t b1)
{
    asm volatile(
        "mma.sync.aligned.m16n8k16.row.col.f32.f16.f16.f32 "
        "{%0,%1,%2,%3}, {%4,%5,%6,%7}, {%8,%9}, {%0,%1,%2,%3};"
        : "+f"(c[0]), "+f"(c[1]), "+f"(c[2]), "+f"(c[3])
        : "r"(a0), "r"(a1), "r"(a2), "r"(a3), "r"(b0), "r"(b1));
}

__device__ __forceinline__ void cp_async16(uint32_t dst, const void* src) {
    asm volatile("cp.async.cg.shared.global [%0], [%1], 16;\n" :: "r"(dst), "l"(src));
}

// ---------------------------------------------------------------------------
// Weight prep: dst word (k2, n) = half2(W[2k2][n], W[2k2+1][n])   per layer z
// ---------------------------------------------------------------------------
__global__ void pack_half_kernel(const float* __restrict__ src,
                                 uint32_t* __restrict__ dst, int K2, int N)
{
    int i = blockIdx.x * blockDim.x + threadIdx.x;
    if (i >= K2 * N) return;
    int z = blockIdx.y;
    const float* s = src + (size_t)z * 2 * K2 * N;
    int k2 = i / N, n = i - k2 * N;
    __half2 h = __floats2half2_rn(s[(size_t)(2 * k2) * N + n],
                                  s[(size_t)(2 * k2 + 1) * N + n]);
    dst[(size_t)z * K2 * N + i] = *(uint32_t*)&h;
}

// ---------------------------------------------------------------------------
// Warp-per-row LayerNorm over D=512
// ---------------------------------------------------------------------------
__device__ __forceinline__ void warp_ln_core(
    const float4 v[4], int lane,
    const float* __restrict__ g, const float* __restrict__ b,
    float4 o[4])
{
    float s = 0.f, s2 = 0.f;
#pragma unroll
    for (int i = 0; i < 4; i++) {
        s  += v[i].x + v[i].y + v[i].z + v[i].w;
        s2 += v[i].x * v[i].x + v[i].y * v[i].y + v[i].z * v[i].z + v[i].w * v[i].w;
    }
#pragma unroll
    for (int o_ = 16; o_ > 0; o_ >>= 1) {
        s  += __shfl_xor_sync(0xffffffffu, s,  o_);
        s2 += __shfl_xor_sync(0xffffffffu, s2, o_);
    }
    float mu   = s * (1.0f / 512.0f);
    float var  = s2 * (1.0f / 512.0f) - mu * mu;
    float rstd = rsqrtf(var + LN_EPS);
#pragma unroll
    for (int i = 0; i < 4; i++) {
        int c = (lane + 32 * i) * 4;
        float4 gg = *(const float4*)(g + c);
        float4 bb = *(const float4*)(b + c);
        o[i].x = (v[i].x - mu) * rstd * gg.x + bb.x;
        o[i].y = (v[i].y - mu) * rstd * gg.y + bb.y;
        o[i].z = (v[i].z - mu) * rstd * gg.z + bb.z;
        o[i].w = (v[i].w - mu) * rstd * gg.w + bb.w;
    }
}

__device__ __forceinline__ void store_half4(__half* p, float4 o) {
    __half2 ha = __floats2half2_rn(o.x, o.y);
    __half2 hb = __floats2half2_rn(o.z, o.w);
    uint2 pk = make_uint2(*(uint32_t*)&ha, *(uint32_t*)&hb);
    *(uint2*)p = pk;
}

// out = fp16(LN(x)) — feeds QKV GEMM only
__global__ void ln_kernel(const float* __restrict__ x,
                          const float* __restrict__ g, const float* __restrict__ b,
                          __half* __restrict__ out)
{
    int row  = blockIdx.x * 8 + (threadIdx.x >> 5);
    int lane = threadIdx.x & 31;
    const float* xr = x + (size_t)row * DD;
    float4 v[4];
#pragma unroll
    for (int i = 0; i < 4; i++) v[i] = *(const float4*)(xr + (lane + 32 * i) * 4);
    float4 o[4];
    warp_ln_core(v, lane, g, b, o);
    __half* orow = out + (size_t)row * DD;
#pragma unroll
    for (int i = 0; i < 4; i++) store_half4(orow + (lane + 32 * i) * 4, o[i]);
}

// out = fp16(LN(x[src] + xs[src])) in (b,p,t) order — feeds QKV GEMM only
__global__ void ln_add_transpose_kernel(const float* __restrict__ x,
                                        const float* __restrict__ xs,
                                        const float* __restrict__ g, const float* __restrict__ b,
                                        __half* __restrict__ out)
{
    int row  = blockIdx.x * 8 + (threadIdx.x >> 5);
    int lane = threadIdx.x & 31;
    int t_ = row & 63;
    int p_ = (row >> 6) & 255;
    int b_ = row >> 14;
    int src = (b_ * TT + t_) * PP + p_;
    const float* xr  = x  + (size_t)src * DD;
    const float* xsr = xs + (size_t)src * DD;
    float4 v[4];
#pragma unroll
    for (int i = 0; i < 4; i++) {
        float4 a = *(const float4*)(xr  + (lane + 32 * i) * 4);
        float4 c = *(const float4*)(xsr + (lane + 32 * i) * 4);
        v[i].x = a.x + c.x; v[i].y = a.y + c.y; v[i].z = a.z + c.z; v[i].w = a.w + c.w;
    }
    float4 o[4];
    warp_ln_core(v, lane, g, b, o);
    __half* orow = out + (size_t)row * DD;
#pragma unroll
    for (int i = 0; i < 4; i++) store_half4(orow + (lane + 32 * i) * 4, o[i]);
}

// x = LN(xs + xt[perm]) + x  (full fp32 — residual/output path)
__global__ void ln_final_kernel(const float* __restrict__ xs,
                                const float* __restrict__ xt,
                                const float* __restrict__ g, const float* __restrict__ b,
                                float* __restrict__ x)
{
    int row  = blockIdx.x * 8 + (threadIdx.x >> 5);
    int lane = threadIdx.x & 31;
    int p_ = row & 255;
    int t_ = (row >> 8) & 63;
    int b_ = row >> 14;
    int xtr = (b_ * PP + p_) * TT + t_;
    const float* xsr = xs + (size_t)row * DD;
    const float* xtr_p = xt + (size_t)xtr * DD;
    float* xr = x + (size_t)row * DD;
    float4 v[4], xv[4];
#pragma unroll
    for (int i = 0; i < 4; i++) {
        float4 a = *(const float4*)(xsr + (lane + 32 * i) * 4);
        float4 c = *(const float4*)(xtr_p + (lane + 32 * i) * 4);
        v[i].x = a.x + c.x; v[i].y = a.y + c.y; v[i].z = a.z + c.z; v[i].w = a.w + c.w;
        xv[i] = *(const float4*)(xr + (lane + 32 * i) * 4);
    }
    float4 o[4];
    warp_ln_core(v, lane, g, b, o);
#pragma unroll
    for (int i = 0; i < 4; i++) {
        o[i].x += xv[i].x; o[i].y += xv[i].y; o[i].z += xv[i].z; o[i].w += xv[i].w;
        *(float4*)(xr + (lane + 32 * i) * 4) = o[i];
    }
}

// ---------------------------------------------------------------------------
// fp16 tensor-core GEMM, templated output (fp16 for QKV, fp32 for out-proj).
// 128x128x32 tile, 8 warps, mma.m16n8k16, double-buffered cp.async,
// 2 CTAs/SM via launch bounds.
// ---------------------------------------------------------------------------
#define HA_STR 40
#define HB_STR 136
#define HA_BUF (128 * HA_STR)
#define HB_BUF (16 * HB_STR)

template <typename OutT>
__global__ void __launch_bounds__(256, 2) hgemm_kernel(
    const __half* __restrict__ A, const uint32_t* __restrict__ Bp,
    const float* __restrict__ bias, OutT* __restrict__ C,
    int M, int N, int K)
{
    __shared__ __half   As[2][HA_BUF];
    __shared__ uint32_t Bs[2][HB_BUF];

    int tid  = threadIdx.x;
    int lane = tid & 31;
    int wid  = tid >> 5;
    int wm   = wid >> 2;
    int wn   = wid & 3;
    int grp  = lane >> 2;
    int tig  = lane & 3;
    int bm = blockIdx.x, bn = blockIdx.y;

    const __half*   Ag = A  + (size_t)bm * 128 * K;
    const uint32_t* Bg = Bp + bn * 128;

    uint32_t as_base = (uint32_t)__cvta_generic_to_shared(&As[0][0]);
    uint32_t bs_base = (uint32_t)__cvta_generic_to_shared(&Bs[0][0]);

    float acc[4][4][4];
#pragma unroll
    for (int i = 0; i < 4; i++)
#pragma unroll
        for (int j = 0; j < 4; j++)
#pragma unroll
            for (int c = 0; c < 4; c++) acc[i][j][c] = 0.f;

    const int NK = K / 32;

    auto load_tiles = [&](int kt, int buf) {
#pragma unroll
        for (int it = 0; it < 2; it++) {
            int slot = tid + it * 256;
            int row  = slot >> 2;
            int seg  = slot & 3;
            uint32_t dst = as_base + buf * (HA_BUF * 2) + row * (HA_STR * 2) + seg * 16;
            cp_async16(dst, Ag + (size_t)row * K + kt * 32 + seg * 8);
        }
#pragma unroll
        for (int it = 0; it < 2; it++) {
            int slot = tid + it * 256;
            int row  = slot >> 5;
            int seg  = slot & 31;
            uint32_t dst = bs_base + buf * (HB_BUF * 4) + row * (HB_STR * 4) + seg * 16;
            cp_async16(dst, Bg + (size_t)(kt * 16 + row) * N + seg * 4);
        }
        asm volatile("cp.async.commit_group;\n");
    };

    load_tiles(0, 0);

    for (int kt = 0; kt < NK; kt++) {
        int buf = kt & 1;
        if (kt + 1 < NK) {
            load_tiles(kt + 1, buf ^ 1);
            asm volatile("cp.async.wait_group 1;\n");
        } else {
            asm volatile("cp.async.wait_group 0;\n");
        }
        __syncthreads();

#pragma unroll
        for (int ks = 0; ks < 2; ks++) {
            uint32_t af[4][4];
#pragma unroll
            for (int mt = 0; mt < 4; mt++) {
                int m = wm * 64 + mt * 16;
                const __half* ar0 = &As[buf][(m + grp    ) * HA_STR + ks * 16 + 2 * tig];
                const __half* ar1 = &As[buf][(m + grp + 8) * HA_STR + ks * 16 + 2 * tig];
                af[mt][0] = *(const uint32_t*)ar0;
                af[mt][1] = *(const uint32_t*)ar1;
                af[mt][2] = *(const uint32_t*)(ar0 + 8);
                af[mt][3] = *(const uint32_t*)(ar1 + 8);
            }
            uint32_t bf[4][2];
#pragma unroll
            for (int nt = 0; nt < 4; nt++) {
                int n = wn * 32 + nt * 8;
                bf[nt][0] = Bs[buf][(ks * 8 + tig    ) * HB_STR + n + grp];
                bf[nt][1] = Bs[buf][(ks * 8 + tig + 4) * HB_STR + n + grp];
            }
#pragma unroll
            for (int mt = 0; mt < 4; mt++)
#pragma unroll
                for (int nt = 0; nt < 4; nt++)
                    mma_f16(acc[mt][nt], af[mt][0], af[mt][1], af[mt][2], af[mt][3],
                            bf[nt][0], bf[nt][1]);
        }
        __syncthreads();
    }

#pragma unroll
    for (int nt = 0; nt < 4; nt++) {
        int colg = bn * 128 + wn * 32 + nt * 8 + 2 * tig;
        float2 bv = {0.f, 0.f};
        if (bias) bv = *(const float2*)(bias + colg);
#pragma unroll
        for (int mt = 0; mt < 4; mt++) {
            int row0 = bm * 128 + wm * 64 + mt * 16 + grp;
            float2 lo = {acc[mt][nt][0] + bv.x, acc[mt][nt][1] + bv.y};
            float2 hi = {acc[mt][nt][2] + bv.x, acc[mt][nt][3] + bv.y};
            if constexpr (sizeof(OutT) == 2) {
                *(__half2*)((__half*)C + (size_t)row0 * N + colg) =
                    __floats2half2_rn(lo.x, lo.y);
                *(__half2*)((__half*)C + (size_t)(row0 + 8) * N + colg) =
                    __floats2half2_rn(hi.x, hi.y);
            } else {
                *(float2*)((float*)C + (size_t)row0 * N + colg)       = lo;
                *(float2*)((float*)C + (size_t)(row0 + 8) * N + colg) = hi;
            }
        }
    }
}

// ---------------------------------------------------------------------------
// fp16 tensor-core flash attention (mma.m16n8k16 + FMA exp), fp16 qkv input.
// ---------------------------------------------------------------------------
#define ASTH 72                 // halves per tile row

__global__ void __launch_bounds__(128, 4) attn_tc_kernel(
    const __half* __restrict__ qkv, __half* __restrict__ ctx, int L)
{
    __shared__ __half qs [64 * ASTH];
    __shared__ __half ks [64 * ASTH];
    __shared__ __half vsT[64 * ASTH];
    __half* ps = qs;

    int tid  = threadIdx.x;
    int lane = tid & 31;
    int w    = tid >> 5;
    int grp  = lane >> 2;
    int tig  = lane & 3;
    int qt = blockIdx.x, h = blockIdx.y;
    size_t seq_base = (size_t)blockIdx.z * L;
    int qbase = qt * 64;
    int m0 = w * 16;

    // ---- stage Q (rotary + scale -> fp16) ----
#pragma unroll
    for (int it = 0; it < 16; it++) {
        int slot = it * 128 + tid;            // 2048 rotary pairs
        int row = slot >> 5, pr = slot & 31;
        int pos = qbase + row;
        const __half* p = qkv + (seq_base + pos) * QKV3 + h * DH + 2 * pr;
        __half2 qh = *(const __half2*)p;
        float qx = __half2float(__low2half(qh)), qy = __half2float(__high2half(qh));
        float c = g_cos[pos * 32 + pr], sn = g_sin[pos * 32 + pr];
        float e0 = (qx * c - qy * sn) * 0.125f;
        float e1 = (qy * c + qx * sn) * 0.125f;
        *(__half2*)&qs[row * ASTH + 2 * pr] = __floats2half2_rn(e0, e1);
    }

    // ---- KV staging: K rotary->fp16, V transposed fp16 ----
    auto stage_kv = [&](int kt) {
#pragma unroll
        for (int it = 0; it < 16; it++) {
            int slot = it * 128 + tid;
            int row = slot >> 5, pr = slot & 31;
            int pos = kt * 64 + row;
            const __half* p = qkv + (seq_base + pos) * QKV3 + INNER + h * DH + 2 * pr;
            __half2 kh = *(const __half2*)p;
            float kx = __half2float(__low2half(kh)), ky = __half2float(__high2half(kh));
            float c = g_cos[pos * 32 + pr], sn = g_sin[pos * 32 + pr];
            float e0 = kx * c - ky * sn;
            float e1 = ky * c + kx * sn;
            *(__half2*)&ks[row * ASTH + 2 * pr] = __floats2half2_rn(e0, e1);
        }
        // V: vsT[d][pos-pair] = (V[pos][d], V[pos+1][d])
#pragma unroll
        for (int it = 0; it < 16; it++) {
            int slot = it * 128 + tid;            // 2048 (d, pos-pair) cells
            int d  = slot & 63;
            int pp = slot >> 6;                   // 0..31
            const __half* p = qkv + (seq_base + kt * 64 + 2 * pp) * QKV3
                            + 2 * INNER + h * DH + d;
            __half v0 = p[0];
            __half v1 = p[QKV3];
            *(__half2*)&vsT[d * ASTH + 2 * pp] = __halves2half2(v0, v1);
        }
    };

    stage_kv(0);
    __syncthreads();

    // ---- preload Q fragments (own warp's 16 rows), fp16 k16 ----
    uint32_t qa[4][4];
#pragma unroll
    for (int kk = 0; kk < 4; kk++) {
        const uint32_t* r0 = (const uint32_t*)&qs[(m0 + grp    ) * ASTH + kk * 16 + 2 * tig];
        const uint32_t* r1 = (const uint32_t*)&qs[(m0 + grp + 8) * ASTH + kk * 16 + 2 * tig];
        qa[kk][0] = r0[0];
        qa[kk][1] = r1[0];
        qa[kk][2] = r0[4];
        qa[kk][3] = r1[4];
    }

    float mrow[2] = {-1e30f, -1e30f};
    float lrow[2] = {0.f, 0.f};
    float oc[8][4];
#pragma unroll
    for (int nt = 0; nt < 8; nt++)
#pragma unroll
        for (int c = 0; c < 4; c++) oc[nt][c] = 0.f;

    int ntl = L >> 6;
    for (int kt = 0; kt < ntl; kt++) {
        if (kt > 0) {
            __syncthreads();
            stage_kv(kt);
            __syncthreads();
        }

        // ---- S = Q @ K^T ----
        float sacc[8][4];
#pragma unroll
        for (int nt = 0; nt < 8; nt++)
#pragma unroll
            for (int c = 0; c < 4; c++) sacc[nt][c] = 0.f;
#pragma unroll
        for (int kk = 0; kk < 4; kk++) {
#pragma unroll
            for (int nt = 0; nt < 8; nt++) {
                const uint32_t* kr = (const uint32_t*)&ks[(nt * 8 + grp) * ASTH + kk * 16 + 2 * tig];
                mma_f16(sacc[nt], qa[kk][0], qa[kk][1], qa[kk][2], qa[kk][3],
                        kr[0], kr[4]);
            }
        }

        // ---- online softmax ----
        float mx0 = -1e30f, mx1 = -1e30f;
#pragma unroll
        for (int nt = 0; nt < 8; nt++) {
            mx0 = fmaxf(mx0, fmaxf(sacc[nt][0], sacc[nt][1]));
            mx1 = fmaxf(mx1, fmaxf(sacc[nt][2], sacc[nt][3]));
        }
        mx0 = fmaxf(mx0, __shfl_xor_sync(0xffffffffu, mx0, 1));
        mx0 = fmaxf(mx0, __shfl_xor_sync(0xffffffffu, mx0, 2));
        mx1 = fmaxf(mx1, __shfl_xor_sync(0xffffffffu, mx1, 1));
        mx1 = fmaxf(mx1, __shfl_xor_sync(0xffffffffu, mx1, 2));
        float nm0 = fmaxf(mrow[0], mx0), nm1 = fmaxf(mrow[1], mx1);
        float al0 = fexp(mrow[0] - nm0),  al1 = fexp(mrow[1] - nm1);
        float s0 = 0.f, s1 = 0.f;
#pragma unroll
        for (int nt = 0; nt < 8; nt++) {
            float p0 = fexp(sacc[nt][0] - nm0);
            float p1 = fexp(sacc[nt][1] - nm0);
            float p2 = fexp(sacc[nt][2] - nm1);
            float p3 = fexp(sacc[nt][3] - nm1);
            s0 += p0 + p1;
            s1 += p2 + p3;
            *(__half2*)&ps[(m0 + grp    ) * ASTH + nt * 8 + 2 * tig] =
                __floats2half2_rn(p0, p1);
            *(__half2*)&ps[(m0 + grp + 8) * ASTH + nt * 8 + 2 * tig] =
                __floats2half2_rn(p2, p3);
        }
        s0 += __shfl_xor_sync(0xffffffffu, s0, 1);
        s0 += __shfl_xor_sync(0xffffffffu, s0, 2);
        s1 += __shfl_xor_sync(0xffffffffu, s1, 1);
        s1 += __shfl_xor_sync(0xffffffffu, s1, 2);
        lrow[0] = lrow[0] * al0 + s0;
        lrow[1] = lrow[1] * al1 + s1;
        mrow[0] = nm0; mrow[1] = nm1;
#pragma unroll
        for (int nt = 0; nt < 8; nt++) {
            oc[nt][0] *= al0; oc[nt][1] *= al0;
            oc[nt][2] *= al1; oc[nt][3] *= al1;
        }
        __syncwarp();

        // ---- O += P @ V ----
#pragma unroll
        for (int kk = 0; kk < 4; kk++) {
            const uint32_t* p0 = (const uint32_t*)&ps[(m0 + grp    ) * ASTH + kk * 16 + 2 * tig];
            const uint32_t* p1 = (const uint32_t*)&ps[(m0 + grp + 8) * ASTH + kk * 16 + 2 * tig];
            uint32_t pa0 = p0[0], pa1 = p1[0], pa2 = p0[4], pa3 = p1[4];
#pragma unroll
            for (int nt = 0; nt < 8; nt++) {
                const uint32_t* vr = (const uint32_t*)&vsT[(nt * 8 + grp) * ASTH + kk * 16 + 2 * tig];
                mma_f16(oc[nt], pa0, pa1, pa2, pa3, vr[0], vr[4]);
            }
        }
        __syncwarp();
    }

    // ---- epilogue: fp16 ctx ----
    float i0 = 1.0f / lrow[0], i1 = 1.0f / lrow[1];
    size_t tok0 = seq_base + qbase + m0 + grp;
#pragma unroll
    for (int nt = 0; nt < 8; nt++) {
        int col = h * DH + nt * 8 + 2 * tig;
        *(__half2*)&ctx[tok0 * INNER + col] =
            __floats2half2_rn(oc[nt][0] * i0, oc[nt][1] * i0);
        *(__half2*)&ctx[(tok0 + 8) * INNER + col] =
            __floats2half2_rn(oc[nt][2] * i1, oc[nt][3] * i1);
    }
}

// ---------------------------------------------------------------------------
// Host launch
// ---------------------------------------------------------------------------
extern "C" void kernel_launch(void* const* d_in, const int* in_sizes, int n_in,
                              void* d_out, int out_size)
{
    const float* x_in    = (const float*)d_in[0];
    const float* ln_s_g  = (const float*)d_in[1];
    const float* ln_s_b  = (const float*)d_in[2];
    const float* w_qkv_s = (const float*)d_in[3];
    const float* w_out_s = (const float*)d_in[4];
    const float* b_out_s = (const float*)d_in[5];
    const float* ln_t_g  = (const float*)d_in[6];
    const float* ln_t_b  = (const float*)d_in[7];
    const float* w_qkv_t = (const float*)d_in[8];
    const float* w_out_t = (const float*)d_in[9];
    const float* b_out_t = (const float*)d_in[10];
    const float* ln_f_g  = (const float*)d_in[11];
    const float* ln_f_b  = (const float*)d_in[12];
    float* x = (float*)d_out;

    __half *qkv_p, *ctx_p;
    float *xs_p, *xt_p;
    uint32_t* wp_p;
    cudaGetSymbolAddress((void**)&qkv_p, g_qkv);
    cudaGetSymbolAddress((void**)&ctx_p, g_ctx);
    cudaGetSymbolAddress((void**)&xs_p,  g_xs);
    cudaGetSymbolAddress((void**)&xt_p,  g_xt);
    cudaGetSymbolAddress((void**)&wp_p,  g_wp);
    __half* ln_p = ctx_p;   // LN output aliases ctx (lifetimes disjoint)

    uint32_t* wp_qkv_s = wp_p;
    uint32_t* wp_out_s = wp_p + WQKV_SZ / 2;
    uint32_t* wp_qkv_t = wp_p + (WQKV_SZ + WOUT_SZ) / 2;
    uint32_t* wp_out_t = wp_p + WQKV_SZ + WOUT_SZ / 2;

    cudaMemcpyAsync(x, x_in, (size_t)NTOK * DD * sizeof(float),
                    cudaMemcpyDeviceToDevice);
    rope_table_kernel<<<(256 * 32 + 255) / 256, 256>>>();

    // pack all weights into fp16 k-pair words, once per launch
    {
        int nq = (DD / 2) * QKV3;
        int no = (INNER / 2) * DD;
        pack_half_kernel<<<dim3((nq + 255) / 256, DEPTH), 256>>>(w_qkv_s, wp_qkv_s, DD / 2, QKV3);
        pack_half_kernel<<<dim3((no + 255) / 256, DEPTH), 256>>>(w_out_s, wp_out_s, INNER / 2, DD);
        pack_half_kernel<<<dim3((nq + 255) / 256, DEPTH), 256>>>(w_qkv_t, wp_qkv_t, DD / 2, QKV3);
        pack_half_kernel<<<dim3((no + 255) / 256, DEPTH), 256>>>(w_out_t, wp_out_t, INNER / 2, DD);
    }

    dim3 ln_grid(NTOK / 8);
    dim3 gemm_qkv_grid(NTOK / 128, QKV3 / 128);
    dim3 gemm_out_grid(NTOK / 128, DD / 128);
    dim3 attn_s_grid(PP / 64, HH, BB * TT);
    dim3 attn_t_grid(TT / 64, HH, BB * PP);

    for (int i = 0; i < DEPTH; i++) {
        const uint32_t* wq_s = wp_qkv_s + (size_t)i * (DD / 2) * QKV3;
        const uint32_t* wo_s = wp_out_s + (size_t)i * (INNER / 2) * DD;
        const uint32_t* wq_t = wp_qkv_t + (size_t)i * (DD / 2) * QKV3;
        const uint32_t* wo_t = wp_out_t + (size_t)i * (INNER / 2) * DD;

        // ---- spatial branch ----
        ln_kernel<<<ln_grid, 256>>>(x, ln_s_g + i * DD, ln_s_b + i * DD, ln_p);
        hgemm_kernel<__half><<<gemm_qkv_grid, 256>>>(ln_p, wq_s, nullptr, qkv_p,
                                                     NTOK, QKV3, DD);
        attn_tc_kernel<<<attn_s_grid, 128>>>(qkv_p, ctx_p, PP);
        hgemm_kernel<float><<<gemm_out_grid, 256>>>(ctx_p, wo_s, b_out_s + i * DD, xs_p,
                                                    NTOK, DD, INNER);

        // ---- temporal branch ----
        ln_add_transpose_kernel<<<ln_grid, 256>>>(x, xs_p, ln_t_g + i * DD,
                                                  ln_t_b + i * DD, ln_p);
        hgemm_kernel<__half><<<gemm_qkv_grid, 256>>>(ln_p, wq_t, nullptr, qkv_p,
                                                     NTOK, QKV3, DD);
        attn_tc_kernel<<<attn_t_grid, 128>>>(qkv_p, ctx_p, TT);
        hgemm_kernel<float><<<gemm_out_grid, 256>>>(ctx_p, wo_t, b_out_t + i * DD, xt_p,
                                                    NTOK, DD, INNER);

        // ---- finish ----
        ln_final_kernel<<<ln_grid, 256>>>(xs_p, xt_p, ln_f_g + i * DD,
                                          ln_f_b + i * DD, x);
    }
}

// round 13
// speedup vs baseline: 5.0306x; 1.0877x over previous
#include <cuda_runtime.h>
#include <cuda_bf16.h>
#include <cuda_fp16.h>
#include <math.h>
#include <stdint.h>

// ---------------------------------------------------------------------------
// Problem constants
// ---------------------------------------------------------------------------
#define BB    2
#define TT    64
#define PP    256
#define DD    512
#define HH    8
#define DH    64
#define INNER 512          // HH*DH
#define QKV3  1536         // 3*INNER
#define NTOK  32768        // BB*TT*PP
#define DEPTH 4
#define LN_EPS 1e-5f

#define WQKV_SZ (DEPTH * DD * QKV3)
#define WOUT_SZ (DEPTH * INNER * DD)

// ---------------------------------------------------------------------------
// Static device scratch (qkv/ctx/xs/xt all fp16 now; x residual stays fp32)
// g_ctx doubles as the LN-output buffer (lifetimes disjoint).
// ---------------------------------------------------------------------------
__device__ __half   g_qkv[(size_t)NTOK * QKV3];
__device__ __half   g_ctx[(size_t)NTOK * INNER];
__device__ __half   g_xs [(size_t)NTOK * DD];
__device__ __half   g_xt [(size_t)NTOK * DD];
__device__ uint32_t g_wp [WQKV_SZ + WOUT_SZ];   // k-pair-packed fp16 weights
__device__ float    g_cos[256 * 32];
__device__ float    g_sin[256 * 32];

// ---------------------------------------------------------------------------
// RoPE table
// ---------------------------------------------------------------------------
__global__ void rope_table_kernel() {
    int i = blockIdx.x * blockDim.x + threadIdx.x;
    if (i >= 256 * 32) return;
    int pos = i >> 5;
    int j   = i & 31;
    float freq  = powf(10000.0f, -(float)(2 * j) / 64.0f);
    float theta = (float)pos * freq;
    float s, c;
    sincosf(theta, &s, &c);
    g_cos[i] = c;
    g_sin[i] = s;
}

// ---------------------------------------------------------------------------
// Fast exp on the FMA pipe
// ---------------------------------------------------------------------------
__device__ __forceinline__ float fexp(float x) {
    x = fmaxf(x, -80.0f);
    float y = x * 1.44269504088896340736f;
    float t = y + 12582912.0f;
    int   n = __float_as_int(t) - 0x4B400000;
    float f = y - (t - 12582912.0f);
    float p =             1.54035303933e-4f;
    p = fmaf(p, f, 1.33335581464e-3f);
    p = fmaf(p, f, 9.61812910763e-3f);
    p = fmaf(p, f, 5.55041086648e-2f);
    p = fmaf(p, f, 2.40226506959e-1f);
    p = fmaf(p, f, 6.93147180560e-1f);
    p = fmaf(p, f, 1.0f);
    return p * __int_as_float((n + 127) << 23);
}

__device__ __forceinline__ void mma_f16(float c[4],
                                        uint32_t a0, uint32_t a1, uint32_t a2, uint32_t a3,
                                        uint32_t b0, uint32_t b1)
{
    asm volatile(
        "mma.sync.aligned.m16n8k16.row.col.f32.f16.f16.f32 "
        "{%0,%1,%2,%3}, {%4,%5,%6,%7}, {%8,%9}, {%0,%1,%2,%3};"
        : "+f"(c[0]), "+f"(c[1]), "+f"(c[2]), "+f"(c[3])
        : "r"(a0), "r"(a1), "r"(a2), "r"(a3), "r"(b0), "r"(b1));
}

__device__ __forceinline__ void cp_async16(uint32_t dst, const void* src) {
    asm volatile("cp.async.cg.shared.global [%0], [%1], 16;\n" :: "r"(dst), "l"(src));
}

// ---------------------------------------------------------------------------
// Weight prep: dst word (k2, n) = half2(W[2k2][n], W[2k2+1][n])   per layer z
// ---------------------------------------------------------------------------
__global__ void pack_half_kernel(const float* __restrict__ src,
                                 uint32_t* __restrict__ dst, int K2, int N)
{
    int i = blockIdx.x * blockDim.x + threadIdx.x;
    if (i >= K2 * N) return;
    int z = blockIdx.y;
    const float* s = src + (size_t)z * 2 * K2 * N;
    int k2 = i / N, n = i - k2 * N;
    __half2 h = __floats2half2_rn(s[(size_t)(2 * k2) * N + n],
                                  s[(size_t)(2 * k2 + 1) * N + n]);
    dst[(size_t)z * K2 * N + i] = *(uint32_t*)&h;
}

// ---------------------------------------------------------------------------
// Warp-per-row LayerNorm over D=512
// ---------------------------------------------------------------------------
__device__ __forceinline__ void warp_ln_core(
    const float4 v[4], int lane,
    const float* __restrict__ g, const float* __restrict__ b,
    float4 o[4])
{
    float s = 0.f, s2 = 0.f;
#pragma unroll
    for (int i = 0; i < 4; i++) {
        s  += v[i].x + v[i].y + v[i].z + v[i].w;
        s2 += v[i].x * v[i].x + v[i].y * v[i].y + v[i].z * v[i].z + v[i].w * v[i].w;
    }
#pragma unroll
    for (int o_ = 16; o_ > 0; o_ >>= 1) {
        s  += __shfl_xor_sync(0xffffffffu, s,  o_);
        s2 += __shfl_xor_sync(0xffffffffu, s2, o_);
    }
    float mu   = s * (1.0f / 512.0f);
    float var  = s2 * (1.0f / 512.0f) - mu * mu;
    float rstd = rsqrtf(var + LN_EPS);
#pragma unroll
    for (int i = 0; i < 4; i++) {
        int c = (lane + 32 * i) * 4;
        float4 gg = *(const float4*)(g + c);
        float4 bb = *(const float4*)(b + c);
        o[i].x = (v[i].x - mu) * rstd * gg.x + bb.x;
        o[i].y = (v[i].y - mu) * rstd * gg.y + bb.y;
        o[i].z = (v[i].z - mu) * rstd * gg.z + bb.z;
        o[i].w = (v[i].w - mu) * rstd * gg.w + bb.w;
    }
}

__device__ __forceinline__ void store_half4(__half* p, float4 o) {
    __half2 ha = __floats2half2_rn(o.x, o.y);
    __half2 hb = __floats2half2_rn(o.z, o.w);
    uint2 pk = make_uint2(*(uint32_t*)&ha, *(uint32_t*)&hb);
    *(uint2*)p = pk;
}

__device__ __forceinline__ float4 load_half4(const __half* p) {
    uint2 pk = *(const uint2*)p;
    __half2 ha = *(__half2*)&pk.x;
    __half2 hb = *(__half2*)&pk.y;
    return make_float4(__half2float(__low2half(ha)), __half2float(__high2half(ha)),
                       __half2float(__low2half(hb)), __half2float(__high2half(hb)));
}

// out = fp16(LN(x)) — feeds QKV GEMM only
__global__ void ln_kernel(const float* __restrict__ x,
                          const float* __restrict__ g, const float* __restrict__ b,
                          __half* __restrict__ out)
{
    int row  = blockIdx.x * 8 + (threadIdx.x >> 5);
    int lane = threadIdx.x & 31;
    const float* xr = x + (size_t)row * DD;
    float4 v[4];
#pragma unroll
    for (int i = 0; i < 4; i++) v[i] = *(const float4*)(xr + (lane + 32 * i) * 4);
    float4 o[4];
    warp_ln_core(v, lane, g, b, o);
    __half* orow = out + (size_t)row * DD;
#pragma unroll
    for (int i = 0; i < 4; i++) store_half4(orow + (lane + 32 * i) * 4, o[i]);
}

// out = fp16(LN(x[src] + xs[src])) in (b,p,t) order — feeds QKV GEMM only
__global__ void ln_add_transpose_kernel(const float* __restrict__ x,
                                        const __half* __restrict__ xs,
                                        const float* __restrict__ g, const float* __restrict__ b,
                                        __half* __restrict__ out)
{
    int row  = blockIdx.x * 8 + (threadIdx.x >> 5);
    int lane = threadIdx.x & 31;
    int t_ = row & 63;
    int p_ = (row >> 6) & 255;
    int b_ = row >> 14;
    int src = (b_ * TT + t_) * PP + p_;
    const float* xr   = x  + (size_t)src * DD;
    const __half* xsr = xs + (size_t)src * DD;
    float4 v[4];
#pragma unroll
    for (int i = 0; i < 4; i++) {
        float4 a = *(const float4*)(xr + (lane + 32 * i) * 4);
        float4 c = load_half4(xsr + (lane + 32 * i) * 4);
        v[i].x = a.x + c.x; v[i].y = a.y + c.y; v[i].z = a.z + c.z; v[i].w = a.w + c.w;
    }
    float4 o[4];
    warp_ln_core(v, lane, g, b, o);
    __half* orow = out + (size_t)row * DD;
#pragma unroll
    for (int i = 0; i < 4; i++) store_half4(orow + (lane + 32 * i) * 4, o[i]);
}

// x = LN(xs + xt[perm]) + x  (residual path; x stays fp32)
__global__ void ln_final_kernel(const __half* __restrict__ xs,
                                const __half* __restrict__ xt,
                                const float* __restrict__ g, const float* __restrict__ b,
                                float* __restrict__ x)
{
    int row  = blockIdx.x * 8 + (threadIdx.x >> 5);
    int lane = threadIdx.x & 31;
    int p_ = row & 255;
    int t_ = (row >> 8) & 63;
    int b_ = row >> 14;
    int xtr = (b_ * PP + p_) * TT + t_;
    const __half* xsr   = xs + (size_t)row * DD;
    const __half* xtr_p = xt + (size_t)xtr * DD;
    float* xr = x + (size_t)row * DD;
    float4 v[4], xv[4];
#pragma unroll
    for (int i = 0; i < 4; i++) {
        float4 a = load_half4(xsr   + (lane + 32 * i) * 4);
        float4 c = load_half4(xtr_p + (lane + 32 * i) * 4);
        v[i].x = a.x + c.x; v[i].y = a.y + c.y; v[i].z = a.z + c.z; v[i].w = a.w + c.w;
        xv[i] = *(const float4*)(xr + (lane + 32 * i) * 4);
    }
    float4 o[4];
    warp_ln_core(v, lane, g, b, o);
#pragma unroll
    for (int i = 0; i < 4; i++) {
        o[i].x += xv[i].x; o[i].y += xv[i].y; o[i].z += xv[i].z; o[i].w += xv[i].w;
        *(float4*)(xr + (lane + 32 * i) * 4) = o[i];
    }
}

// ---------------------------------------------------------------------------
// fp16 tensor-core GEMM, fp16 output. 128x128x64 tile (TBK=64 -> half the
// sync cadence), 8 warps, mma.m16n8k16, double-buffered cp.async, dynamic
// smem (71.7 KB), 2 CTAs/SM.
// ---------------------------------------------------------------------------
#define HA_STR 72              // halves per A smem row (64 + 8 pad)
#define HB_STR 136             // words per B smem row
#define HA_BUF (128 * HA_STR)  // halves per A buffer
#define HB_BUF (32 * HB_STR)   // words per B buffer
#define HGEMM_SMEM (2 * HA_BUF * 2 + 2 * HB_BUF * 4)   // 71680 B

__global__ void __launch_bounds__(256, 2) hgemm_kernel(
    const __half* __restrict__ A, const uint32_t* __restrict__ Bp,
    const float* __restrict__ bias, __half* __restrict__ C,
    int M, int N, int K)
{
    extern __shared__ char smem[];
    __half*   As = (__half*)smem;
    uint32_t* Bs = (uint32_t*)(smem + 2 * HA_BUF * 2);

    int tid  = threadIdx.x;
    int lane = tid & 31;
    int wid  = tid >> 5;
    int wm   = wid >> 2;
    int wn   = wid & 3;
    int grp  = lane >> 2;
    int tig  = lane & 3;
    int bm = blockIdx.x, bn = blockIdx.y;

    const __half*   Ag = A  + (size_t)bm * 128 * K;
    const uint32_t* Bg = Bp + bn * 128;

    uint32_t as_base = (uint32_t)__cvta_generic_to_shared(As);
    uint32_t bs_base = (uint32_t)__cvta_generic_to_shared(Bs);

    float acc[4][4][4];
#pragma unroll
    for (int i = 0; i < 4; i++)
#pragma unroll
        for (int j = 0; j < 4; j++)
#pragma unroll
            for (int c = 0; c < 4; c++) acc[i][j][c] = 0.f;

    const int NK = K / 64;

    auto load_tiles = [&](int kt, int buf) {
        // A: 128 rows x 64 halves = 1024 chunks of 16B
#pragma unroll
        for (int it = 0; it < 4; it++) {
            int slot = tid + it * 256;
            int row  = slot >> 3;
            int seg  = slot & 7;
            uint32_t dst = as_base + buf * (HA_BUF * 2) + row * (HA_STR * 2) + seg * 16;
            cp_async16(dst, Ag + (size_t)row * K + kt * 64 + seg * 8);
        }
        // B: 32 k2-rows x 128 words = 1024 chunks of 16B
#pragma unroll
        for (int it = 0; it < 4; it++) {
            int slot = tid + it * 256;
            int row  = slot >> 5;
            int seg  = slot & 31;
            uint32_t dst = bs_base + buf * (HB_BUF * 4) + row * (HB_STR * 4) + seg * 16;
            cp_async16(dst, Bg + (size_t)(kt * 32 + row) * N + seg * 4);
        }
        asm volatile("cp.async.commit_group;\n");
    };

    load_tiles(0, 0);

    for (int kt = 0; kt < NK; kt++) {
        int buf = kt & 1;
        if (kt + 1 < NK) {
            load_tiles(kt + 1, buf ^ 1);
            asm volatile("cp.async.wait_group 1;\n");
        } else {
            asm volatile("cp.async.wait_group 0;\n");
        }
        __syncthreads();

        const __half*   as = As + buf * HA_BUF;
        const uint32_t* bs = Bs + buf * HB_BUF;

#pragma unroll
        for (int ks = 0; ks < 4; ks++) {           // four m16n8k16 k-steps
            uint32_t af[4][4];
#pragma unroll
            for (int mt = 0; mt < 4; mt++) {
                int m = wm * 64 + mt * 16;
                const __half* ar0 = &as[(m + grp    ) * HA_STR + ks * 16 + 2 * tig];
                const __half* ar1 = &as[(m + grp + 8) * HA_STR + ks * 16 + 2 * tig];
                af[mt][0] = *(const uint32_t*)ar0;
                af[mt][1] = *(const uint32_t*)ar1;
                af[mt][2] = *(const uint32_t*)(ar0 + 8);
                af[mt][3] = *(const uint32_t*)(ar1 + 8);
            }
            uint32_t bf[4][2];
#pragma unroll
            for (int nt = 0; nt < 4; nt++) {
                int n = wn * 32 + nt * 8;
                bf[nt][0] = bs[(ks * 8 + tig    ) * HB_STR + n + grp];
                bf[nt][1] = bs[(ks * 8 + tig + 4) * HB_STR + n + grp];
            }
#pragma unroll
            for (int mt = 0; mt < 4; mt++)
#pragma unroll
                for (int nt = 0; nt < 4; nt++)
                    mma_f16(acc[mt][nt], af[mt][0], af[mt][1], af[mt][2], af[mt][3],
                            bf[nt][0], bf[nt][1]);
        }
        __syncthreads();
    }

#pragma unroll
    for (int nt = 0; nt < 4; nt++) {
        int colg = bn * 128 + wn * 32 + nt * 8 + 2 * tig;
        float2 bv = {0.f, 0.f};
        if (bias) bv = *(const float2*)(bias + colg);
#pragma unroll
        for (int mt = 0; mt < 4; mt++) {
            int row0 = bm * 128 + wm * 64 + mt * 16 + grp;
            *(__half2*)(C + (size_t)row0 * N + colg) =
                __floats2half2_rn(acc[mt][nt][0] + bv.x, acc[mt][nt][1] + bv.y);
            *(__half2*)(C + (size_t)(row0 + 8) * N + colg) =
                __floats2half2_rn(acc[mt][nt][2] + bv.x, acc[mt][nt][3] + bv.y);
        }
    }
}

// ---------------------------------------------------------------------------
// fp16 tensor-core flash attention (mma.m16n8k16 + FMA exp), fp16 qkv input.
// ---------------------------------------------------------------------------
#define ASTH 72                 // halves per tile row

__global__ void __launch_bounds__(128, 4) attn_tc_kernel(
    const __half* __restrict__ qkv, __half* __restrict__ ctx, int L)
{
    __shared__ __half qs [64 * ASTH];
    __shared__ __half ks [64 * ASTH];
    __shared__ __half vsT[64 * ASTH];
    __half* ps = qs;

    int tid  = threadIdx.x;
    int lane = tid & 31;
    int w    = tid >> 5;
    int grp  = lane >> 2;
    int tig  = lane & 3;
    int qt = blockIdx.x, h = blockIdx.y;
    size_t seq_base = (size_t)blockIdx.z * L;
    int qbase = qt * 64;
    int m0 = w * 16;

    // ---- stage Q (rotary + scale -> fp16) ----
#pragma unroll
    for (int it = 0; it < 16; it++) {
        int slot = it * 128 + tid;
        int row = slot >> 5, pr = slot & 31;
        int pos = qbase + row;
        const __half* p = qkv + (seq_base + pos) * QKV3 + h * DH + 2 * pr;
        __half2 qh = *(const __half2*)p;
        float qx = __half2float(__low2half(qh)), qy = __half2float(__high2half(qh));
        float c = g_cos[pos * 32 + pr], sn = g_sin[pos * 32 + pr];
        float e0 = (qx * c - qy * sn) * 0.125f;
        float e1 = (qy * c + qx * sn) * 0.125f;
        *(__half2*)&qs[row * ASTH + 2 * pr] = __floats2half2_rn(e0, e1);
    }

    auto stage_kv = [&](int kt) {
#pragma unroll
        for (int it = 0; it < 16; it++) {
            int slot = it * 128 + tid;
            int row = slot >> 5, pr = slot & 31;
            int pos = kt * 64 + row;
            const __half* p = qkv + (seq_base + pos) * QKV3 + INNER + h * DH + 2 * pr;
            __half2 kh = *(const __half2*)p;
            float kx = __half2float(__low2half(kh)), ky = __half2float(__high2half(kh));
            float c = g_cos[pos * 32 + pr], sn = g_sin[pos * 32 + pr];
            float e0 = kx * c - ky * sn;
            float e1 = ky * c + kx * sn;
            *(__half2*)&ks[row * ASTH + 2 * pr] = __floats2half2_rn(e0, e1);
        }
        // V: vsT[d][pos-pair] = (V[pos][d], V[pos+1][d])
#pragma unroll
        for (int it = 0; it < 16; it++) {
            int slot = it * 128 + tid;
            int d  = slot & 63;
            int pp = slot >> 6;
            const __half* p = qkv + (seq_base + kt * 64 + 2 * pp) * QKV3
                            + 2 * INNER + h * DH + d;
            __half v0 = p[0];
            __half v1 = p[QKV3];
            *(__half2*)&vsT[d * ASTH + 2 * pp] = __halves2half2(v0, v1);
        }
    };

    stage_kv(0);
    __syncthreads();

    uint32_t qa[4][4];
#pragma unroll
    for (int kk = 0; kk < 4; kk++) {
        const uint32_t* r0 = (const uint32_t*)&qs[(m0 + grp    ) * ASTH + kk * 16 + 2 * tig];
        const uint32_t* r1 = (const uint32_t*)&qs[(m0 + grp + 8) * ASTH + kk * 16 + 2 * tig];
        qa[kk][0] = r0[0];
        qa[kk][1] = r1[0];
        qa[kk][2] = r0[4];
        qa[kk][3] = r1[4];
    }

    float mrow[2] = {-1e30f, -1e30f};
    float lrow[2] = {0.f, 0.f};
    float oc[8][4];
#pragma unroll
    for (int nt = 0; nt < 8; nt++)
#pragma unroll
        for (int c = 0; c < 4; c++) oc[nt][c] = 0.f;

    int ntl = L >> 6;
    for (int kt = 0; kt < ntl; kt++) {
        if (kt > 0) {
            __syncthreads();
            stage_kv(kt);
            __syncthreads();
        }

        float sacc[8][4];
#pragma unroll
        for (int nt = 0; nt < 8; nt++)
#pragma unroll
            for (int c = 0; c < 4; c++) sacc[nt][c] = 0.f;
#pragma unroll
        for (int kk = 0; kk < 4; kk++) {
#pragma unroll
            for (int nt = 0; nt < 8; nt++) {
                const uint32_t* kr = (const uint32_t*)&ks[(nt * 8 + grp) * ASTH + kk * 16 + 2 * tig];
                mma_f16(sacc[nt], qa[kk][0], qa[kk][1], qa[kk][2], qa[kk][3],
                        kr[0], kr[4]);
            }
        }

        float mx0 = -1e30f, mx1 = -1e30f;
#pragma unroll
        for (int nt = 0; nt < 8; nt++) {
            mx0 = fmaxf(mx0, fmaxf(sacc[nt][0], sacc[nt][1]));
            mx1 = fmaxf(mx1, fmaxf(sacc[nt][2], sacc[nt][3]));
        }
        mx0 = fmaxf(mx0, __shfl_xor_sync(0xffffffffu, mx0, 1));
        mx0 = fmaxf(mx0, __shfl_xor_sync(0xffffffffu, mx0, 2));
        mx1 = fmaxf(mx1, __shfl_xor_sync(0xffffffffu, mx1, 1));
        mx1 = fmaxf(mx1, __shfl_xor_sync(0xffffffffu, mx1, 2));
        float nm0 = fmaxf(mrow[0], mx0), nm1 = fmaxf(mrow[1], mx1);
        float al0 = fexp(mrow[0] - nm0),  al1 = fexp(mrow[1] - nm1);
        float s0 = 0.f, s1 = 0.f;
#pragma unroll
        for (int nt = 0; nt < 8; nt++) {
            float p0 = fexp(sacc[nt][0] - nm0);
            float p1 = fexp(sacc[nt][1] - nm0);
            float p2 = fexp(sacc[nt][2] - nm1);
            float p3 = fexp(sacc[nt][3] - nm1);
            s0 += p0 + p1;
            s1 += p2 + p3;
            *(__half2*)&ps[(m0 + grp    ) * ASTH + nt * 8 + 2 * tig] =
                __floats2half2_rn(p0, p1);
            *(__half2*)&ps[(m0 + grp + 8) * ASTH + nt * 8 + 2 * tig] =
                __floats2half2_rn(p2, p3);
        }
        s0 += __shfl_xor_sync(0xffffffffu, s0, 1);
        s0 += __shfl_xor_sync(0xffffffffu, s0, 2);
        s1 += __shfl_xor_sync(0xffffffffu, s1, 1);
        s1 += __shfl_xor_sync(0xffffffffu, s1, 2);
        lrow[0] = lrow[0] * al0 + s0;
        lrow[1] = lrow[1] * al1 + s1;
        mrow[0] = nm0; mrow[1] = nm1;
#pragma unroll
        for (int nt = 0; nt < 8; nt++) {
            oc[nt][0] *= al0; oc[nt][1] *= al0;
            oc[nt][2] *= al1; oc[nt][3] *= al1;
        }
        __syncwarp();

#pragma unroll
        for (int kk = 0; kk < 4; kk++) {
            const uint32_t* p0 = (const uint32_t*)&ps[(m0 + grp    ) * ASTH + kk * 16 + 2 * tig];
            const uint32_t* p1 = (const uint32_t*)&ps[(m0 + grp + 8) * ASTH + kk * 16 + 2 * tig];
            uint32_t pa0 = p0[0], pa1 = p1[0], pa2 = p0[4], pa3 = p1[4];
#pragma unroll
            for (int nt = 0; nt < 8; nt++) {
                const uint32_t* vr = (const uint32_t*)&vsT[(nt * 8 + grp) * ASTH + kk * 16 + 2 * tig];
                mma_f16(oc[nt], pa0, pa1, pa2, pa3, vr[0], vr[4]);
            }
        }
        __syncwarp();
    }

    float i0 = 1.0f / lrow[0], i1 = 1.0f / lrow[1];
    size_t tok0 = seq_base + qbase + m0 + grp;
#pragma unroll
    for (int nt = 0; nt < 8; nt++) {
        int col = h * DH + nt * 8 + 2 * tig;
        *(__half2*)&ctx[tok0 * INNER + col] =
            __floats2half2_rn(oc[nt][0] * i0, oc[nt][1] * i0);
        *(__half2*)&ctx[(tok0 + 8) * INNER + col] =
            __floats2half2_rn(oc[nt][2] * i1, oc[nt][3] * i1);
    }
}

// ---------------------------------------------------------------------------
// Host launch
// ---------------------------------------------------------------------------
extern "C" void kernel_launch(void* const* d_in, const int* in_sizes, int n_in,
                              void* d_out, int out_size)
{
    const float* x_in    = (const float*)d_in[0];
    const float* ln_s_g  = (const float*)d_in[1];
    const float* ln_s_b  = (const float*)d_in[2];
    const float* w_qkv_s = (const float*)d_in[3];
    const float* w_out_s = (const float*)d_in[4];
    const float* b_out_s = (const float*)d_in[5];
    const float* ln_t_g  = (const float*)d_in[6];
    const float* ln_t_b  = (const float*)d_in[7];
    const float* w_qkv_t = (const float*)d_in[8];
    const float* w_out_t = (const float*)d_in[9];
    const float* b_out_t = (const float*)d_in[10];
    const float* ln_f_g  = (const float*)d_in[11];
    const float* ln_f_b  = (const float*)d_in[12];
    float* x = (float*)d_out;

    cudaFuncSetAttribute(hgemm_kernel, cudaFuncAttributeMaxDynamicSharedMemorySize,
                         HGEMM_SMEM);

    __half *qkv_p, *ctx_p, *xs_p, *xt_p;
    uint32_t* wp_p;
    cudaGetSymbolAddress((void**)&qkv_p, g_qkv);
    cudaGetSymbolAddress((void**)&ctx_p, g_ctx);
    cudaGetSymbolAddress((void**)&xs_p,  g_xs);
    cudaGetSymbolAddress((void**)&xt_p,  g_xt);
    cudaGetSymbolAddress((void**)&wp_p,  g_wp);
    __half* ln_p = ctx_p;   // LN output aliases ctx (lifetimes disjoint)

    uint32_t* wp_qkv_s = wp_p;
    uint32_t* wp_out_s = wp_p + WQKV_SZ / 2;
    uint32_t* wp_qkv_t = wp_p + (WQKV_SZ + WOUT_SZ) / 2;
    uint32_t* wp_out_t = wp_p + WQKV_SZ + WOUT_SZ / 2;

    cudaMemcpyAsync(x, x_in, (size_t)NTOK * DD * sizeof(float),
                    cudaMemcpyDeviceToDevice);
    rope_table_kernel<<<(256 * 32 + 255) / 256, 256>>>();

    {
        int nq = (DD / 2) * QKV3;
        int no = (INNER / 2) * DD;
        pack_half_kernel<<<dim3((nq + 255) / 256, DEPTH), 256>>>(w_qkv_s, wp_qkv_s, DD / 2, QKV3);
        pack_half_kernel<<<dim3((no + 255) / 256, DEPTH), 256>>>(w_out_s, wp_out_s, INNER / 2, DD);
        pack_half_kernel<<<dim3((nq + 255) / 256, DEPTH), 256>>>(w_qkv_t, wp_qkv_t, DD / 2, QKV3);
        pack_half_kernel<<<dim3((no + 255) / 256, DEPTH), 256>>>(w_out_t, wp_out_t, INNER / 2, DD);
    }

    dim3 ln_grid(NTOK / 8);
    dim3 gemm_qkv_grid(NTOK / 128, QKV3 / 128);
    dim3 gemm_out_grid(NTOK / 128, DD / 128);
    dim3 attn_s_grid(PP / 64, HH, BB * TT);
    dim3 attn_t_grid(TT / 64, HH, BB * PP);

    for (int i = 0; i < DEPTH; i++) {
        const uint32_t* wq_s = wp_qkv_s + (size_t)i * (DD / 2) * QKV3;
        const uint32_t* wo_s = wp_out_s + (size_t)i * (INNER / 2) * DD;
        const uint32_t* wq_t = wp_qkv_t + (size_t)i * (DD / 2) * QKV3;
        const uint32_t* wo_t = wp_out_t + (size_t)i * (INNER / 2) * DD;

        // ---- spatial branch ----
        ln_kernel<<<ln_grid, 256>>>(x, ln_s_g + i * DD, ln_s_b + i * DD, ln_p);
        hgemm_kernel<<<gemm_qkv_grid, 256, HGEMM_SMEM>>>(ln_p, wq_s, nullptr, qkv_p,
                                                         NTOK, QKV3, DD);
        attn_tc_kernel<<<attn_s_grid, 128>>>(qkv_p, ctx_p, PP);
        hgemm_kernel<<<gemm_out_grid, 256, HGEMM_SMEM>>>(ctx_p, wo_s, b_out_s + i * DD, xs_p,
                                                         NTOK, DD, INNER);

        // ---- temporal branch ----
        ln_add_transpose_kernel<<<ln_grid, 256>>>(x, xs_p, ln_t_g + i * DD,
                                                  ln_t_b + i * DD, ln_p);
        hgemm_kernel<<<gemm_qkv_grid, 256, HGEMM_SMEM>>>(ln_p, wq_t, nullptr, qkv_p,
                                                         NTOK, QKV3, DD);
        attn_tc_kernel<<<attn_t_grid, 128>>>(qkv_p, ctx_p, TT);
        hgemm_kernel<<<gemm_out_grid, 256, HGEMM_SMEM>>>(ctx_p, wo_t, b_out_t + i * DD, xt_p,
                                                         NTOK, DD, INNER);

        // ---- finish ----
        ln_final_kernel<<<ln_grid, 256>>>(xs_p, xt_p, ln_f_g + i * DD,
                                          ln_f_b + i * DD, x);
    }
}